// round 3
// baseline (speedup 1.0000x reference)
#include <cuda_runtime.h>
#include <math.h>

// ---------------------------------------------------------------------------
// StructureLayer (Invariant Point Attention) — B=1, N=512, H=12, C_S=384,
// C_P=128, C_H=16, P_QK=4, P_V=8.
// Output layout: [ s2 (512*384) | rot_new (512*9) | trans_new (512*3) ]
// ---------------------------------------------------------------------------

#define NN 512
#define CS 384
#define CP 128
#define CH 16
#define HDS 12
#define PQK 4
#define PV 8

// ---- scratch (device globals; no allocation allowed) ----------------------
__device__ float g_q[NN * 192];          // (N, H*CH)
__device__ float g_kv[NN * 384];         // (N, H*2CH)
__device__ float g_qp[NN * 144];         // (N, H*PQK*3) rotated
__device__ float g_kvp[NN * 432];        // (N, H*12*3) rotated
__device__ float g_kpack[HDS * NN * 16];
__device__ float g_kppack[HDS * NN * 12];
__device__ float g_vpack[HDS * NN * 40]; // [h][j][ v(16) | vp(24) ]
__device__ float g_biasb[NN * NN * HDS]; // (i*N+j, h)
__device__ float g_att[HDS * NN * NN];   // [h][i][j]
__device__ float g_ov[HDS * NN * 40];    // [h][i][ o(16) | op_raw(24) ]
__device__ float g_cat[NN * 2112];
__device__ float g_x1[NN * CS];
__device__ float g_x2[NN * CS];
__device__ float g_x3[NN * CS];
__device__ float g_upd[NN * 6];

// ---------------------------------------------------------------------------
// Generic register-tiled SGEMM: C = A(MxK) @ B(KxN) [+bias][+res][relu]
// BM=BN=64, BK=16, 256 threads, 4x4 per thread. K must be a multiple of 16.
// ---------------------------------------------------------------------------
__global__ void sgemm_kernel(const float* __restrict__ A,
                             const float* __restrict__ B,
                             const float* __restrict__ bias,
                             const float* __restrict__ res,
                             float* __restrict__ C,
                             int M, int Nn, int K, int relu)
{
    __shared__ float As[64][17];
    __shared__ float Bs[16][64];
    const int bm = blockIdx.y * 64, bn = blockIdx.x * 64;
    const int tid = threadIdx.x;
    const int tx = tid & 15, ty = tid >> 4;
    float acc[4][4];
    #pragma unroll
    for (int i = 0; i < 4; i++)
        #pragma unroll
        for (int j = 0; j < 4; j++) acc[i][j] = 0.f;

    for (int k0 = 0; k0 < K; k0 += 16) {
        #pragma unroll
        for (int l = 0; l < 4; l++) {
            int idx = tid + l * 256;
            int r = idx >> 4, c = idx & 15;
            int gr = bm + r;
            As[r][c] = (gr < M) ? A[(size_t)gr * K + (k0 + c)] : 0.f;
        }
        #pragma unroll
        for (int l = 0; l < 4; l++) {
            int idx = tid + l * 256;
            int r = idx >> 6, c = idx & 63;
            int gc = bn + c;
            Bs[r][c] = (gc < Nn) ? B[(size_t)(k0 + r) * Nn + gc] : 0.f;
        }
        __syncthreads();
        #pragma unroll
        for (int kk = 0; kk < 16; kk++) {
            float av[4];
            #pragma unroll
            for (int i = 0; i < 4; i++) av[i] = As[ty * 4 + i][kk];
            float4 bv = ((const float4*)&Bs[kk][0])[tx];
            #pragma unroll
            for (int i = 0; i < 4; i++) {
                acc[i][0] += av[i] * bv.x;
                acc[i][1] += av[i] * bv.y;
                acc[i][2] += av[i] * bv.z;
                acc[i][3] += av[i] * bv.w;
            }
        }
        __syncthreads();
    }
    #pragma unroll
    for (int i = 0; i < 4; i++) {
        int gr = bm + ty * 4 + i;
        if (gr >= M) continue;
        #pragma unroll
        for (int j = 0; j < 4; j++) {
            int gc = bn + tx * 4 + j;
            if (gc >= Nn) continue;
            float v = acc[i][j];
            if (bias) v += bias[gc];
            if (res)  v += res[(size_t)gr * Nn + gc];
            if (relu) v = fmaxf(v, 0.f);
            C[(size_t)gr * Nn + gc] = v;
        }
    }
}

// ---------------------------------------------------------------------------
// Apply frame: v <- rot[n] @ v + trans[n]  (in place, 3-vectors)
// ---------------------------------------------------------------------------
__global__ void rot_apply_kernel(float* __restrict__ v,
                                 const float* __restrict__ rot,
                                 const float* __restrict__ trans, int npts)
{
    int idx = blockIdx.x * blockDim.x + threadIdx.x;
    if (idx >= NN * npts) return;
    int n = idx / npts;
    float* pv = v + (size_t)idx * 3;
    float x = pv[0], y = pv[1], z = pv[2];
    const float* R = rot + n * 9;
    const float* t = trans + n * 3;
    pv[0] = R[0]*x + R[1]*y + R[2]*z + t[0];
    pv[1] = R[3]*x + R[4]*y + R[5]*z + t[1];
    pv[2] = R[6]*x + R[7]*y + R[8]*z + t[2];
}

// ---------------------------------------------------------------------------
// Repack k / kp / v|vp into head-major contiguous layouts for coalescing.
// ---------------------------------------------------------------------------
__global__ void pack_kernel(const float* __restrict__ kv,
                            const float* __restrict__ kvp,
                            float* __restrict__ kpack,
                            float* __restrict__ kppack,
                            float* __restrict__ vpack)
{
    const int T1 = HDS * NN * 16, T2 = HDS * NN * 12, T3 = HDS * NN * 40;
    int idx = blockIdx.x * blockDim.x + threadIdx.x;
    if (idx < T1) {
        int c = idx & 15, j = (idx >> 4) & 511, h = idx >> 13;
        kpack[idx] = kv[j * 384 + h * 32 + c];
    } else if (idx < T1 + T2) {
        int t = idx - T1;
        int d = t % 12, j = (t / 12) & 511, h = t / (12 * 512);
        kppack[t] = kvp[j * 432 + h * 36 + d];
    } else if (idx < T1 + T2 + T3) {
        int t = idx - T1 - T2;
        int c = t % 40, j = (t / 40) & 511, h = t / (40 * 512);
        float v;
        if (c < 16) v = kv[j * 384 + h * 32 + 16 + c];
        else        v = kvp[j * 432 + h * 36 + 12 + (c - 16)];
        vpack[t] = v;
    }
}

// ---------------------------------------------------------------------------
// Attention logits: a[h,i,j] = qk*s1 + s2*bias + pt_att + mask_bias
// One block per (i, h); 256 threads, 2 j each.
// ---------------------------------------------------------------------------
__global__ void logits_kernel(const float* __restrict__ q,
                              const float* __restrict__ qp,
                              const float* __restrict__ kpack,
                              const float* __restrict__ kppack,
                              const float* __restrict__ biasb,
                              const float* __restrict__ mask,
                              const float* __restrict__ head_w,
                              float* __restrict__ att)
{
    const int i = blockIdx.x, h = blockIdx.y;
    __shared__ float qs[16], qps[12], sh_hw, sh_mi;
    int tid = threadIdx.x;
    if (tid < 16)      qs[tid] = q[i * 192 + h * 16 + tid];
    else if (tid < 28) qps[tid - 16] = qp[i * 144 + h * 12 + (tid - 16)];
    else if (tid == 28) {
        float w = head_w[h];
        float sp = fmaxf(w, 0.f) + log1pf(expf(-fabsf(w)));   // softplus
        sh_hw = sp * 0.13608276348795434f;                    // sqrt(1/54)
    } else if (tid == 29) sh_mi = mask[i];
    __syncthreads();

    const float hw = sh_hw, mi = sh_mi;
    const float* kb  = kpack  + (size_t)(h * NN) * 16;
    const float* kpb = kppack + (size_t)(h * NN) * 12;
    const float sqk = 0.14433756729740643f;   // sqrt(1/48)
    const float sb  = 0.5773502691896258f;    // sqrt(1/3)

    for (int j = tid; j < NN; j += 256) {
        float qk = 0.f;
        const float4* kv4 = (const float4*)(kb + j * 16);
        #pragma unroll
        for (int c4 = 0; c4 < 4; c4++) {
            float4 kk = kv4[c4];
            qk += qs[c4*4+0]*kk.x + qs[c4*4+1]*kk.y
                + qs[c4*4+2]*kk.z + qs[c4*4+3]*kk.w;
        }
        float d2 = 0.f;
        const float4* kp4 = (const float4*)(kpb + j * 12);
        #pragma unroll
        for (int c4 = 0; c4 < 3; c4++) {
            float4 kk = kp4[c4];
            float d0 = qps[c4*4+0]-kk.x, d1 = qps[c4*4+1]-kk.y;
            float d2_ = qps[c4*4+2]-kk.z, d3 = qps[c4*4+3]-kk.w;
            d2 += d0*d0 + d1*d1 + d2_*d2_ + d3*d3;
        }
        float val = qk * sqk
                  + sb * biasb[((size_t)i * NN + j) * HDS + h]
                  - 0.5f * hw * d2
                  + (mi * mask[j] - 1.0f) * 100000.0f;
        att[((size_t)(h * NN + i)) * NN + j] = val;
    }
}

// ---------------------------------------------------------------------------
// Row softmax over j (rows = h*N+i), 512 elements per row.
// ---------------------------------------------------------------------------
__global__ void softmax_kernel(float* __restrict__ att)
{
    __shared__ float red[256];
    const int row = blockIdx.x;
    float* ar = att + (size_t)row * NN;
    int tid = threadIdx.x;
    float v0 = ar[tid], v1 = ar[tid + 256];
    red[tid] = fmaxf(v0, v1);
    __syncthreads();
    for (int s = 128; s > 0; s >>= 1) {
        if (tid < s) red[tid] = fmaxf(red[tid], red[tid + s]);
        __syncthreads();
    }
    float m = red[0];
    __syncthreads();
    float e0 = expf(v0 - m), e1 = expf(v1 - m);
    red[tid] = e0 + e1;
    __syncthreads();
    for (int s = 128; s > 0; s >>= 1) {
        if (tid < s) red[tid] += red[tid + s];
        __syncthreads();
    }
    float inv = 1.0f / red[0];
    ar[tid] = e0 * inv;
    ar[tid + 256] = e1 * inv;
}

// ---------------------------------------------------------------------------
// o_pair[i,h,c] = sum_j a[h,i,j] * p[i,j,c]   -> cat[i][576 + h*128 + c]
// One block per i, 192 threads: (c4 in 0..31) x (2 heads per thread).
// ---------------------------------------------------------------------------
__global__ void opair_kernel(const float* __restrict__ att,
                             const float* __restrict__ p,
                             float* __restrict__ cat)
{
    const int i = blockIdx.x;
    __shared__ float as[HDS][NN];    // 24 KB
    __shared__ float ps[32][128];    // 16 KB
    const int tid = threadIdx.x;     // 192

    for (int idx = tid; idx < HDS * NN; idx += 192) {
        int h = idx >> 9, j = idx & 511;
        as[h][j] = att[((size_t)(h * NN + i)) * NN + j];
    }

    const int c4 = tid & 31;
    const int hh = tid >> 5;         // 0..5 -> heads 2hh, 2hh+1
    float acc0[4] = {0,0,0,0}, acc1[4] = {0,0,0,0};
    const float* pi = p + (size_t)i * NN * CP;

    for (int j0 = 0; j0 < NN; j0 += 32) {
        for (int idx = tid; idx < 32 * 32; idx += 192) {
            int jj = idx >> 5, cc = idx & 31;
            ((float4*)&ps[jj][0])[cc] =
                ((const float4*)(pi + (size_t)(j0 + jj) * CP))[cc];
        }
        __syncthreads();
        #pragma unroll 8
        for (int jj = 0; jj < 32; jj++) {
            float a0 = as[2 * hh][j0 + jj];
            float a1 = as[2 * hh + 1][j0 + jj];
            float4 pv = ((const float4*)&ps[jj][0])[c4];
            acc0[0] += a0 * pv.x; acc0[1] += a0 * pv.y;
            acc0[2] += a0 * pv.z; acc0[3] += a0 * pv.w;
            acc1[0] += a1 * pv.x; acc1[1] += a1 * pv.y;
            acc1[2] += a1 * pv.z; acc1[3] += a1 * pv.w;
        }
        __syncthreads();
    }
    float* dst = cat + (size_t)i * 2112 + 576;
    #pragma unroll
    for (int d = 0; d < 4; d++) {
        dst[(2 * hh) * 128 + c4 * 4 + d]     = acc0[d];
        dst[(2 * hh + 1) * 128 + c4 * 4 + d] = acc1[d];
    }
}

// ---------------------------------------------------------------------------
// Epilogue: copy o, rotate op back to local frame, norms -> cat sections.
// ---------------------------------------------------------------------------
__global__ void postproc_kernel(const float* __restrict__ ov,
                                const float* __restrict__ rot,
                                const float* __restrict__ trans,
                                float* __restrict__ cat)
{
    const int i = blockIdx.x;
    const int tid = threadIdx.x;   // 192
    float* ci = cat + (size_t)i * 2112;
    {
        int h = tid >> 4, c = tid & 15;
        ci[tid] = ov[((size_t)(h * NN) + i) * 40 + c];
    }
    if (tid < 96) {
        int h = tid >> 3, pp = tid & 7;
        const float* base = ov + ((size_t)(h * NN) + i) * 40 + 16 + pp * 3;
        float vx = base[0] - trans[i*3+0];
        float vy = base[1] - trans[i*3+1];
        float vz = base[2] - trans[i*3+2];
        const float* R = rot + i * 9;
        float ox = R[0]*vx + R[3]*vy + R[6]*vz;   // rot^T @ v
        float oy = R[1]*vx + R[4]*vy + R[7]*vz;
        float oz = R[2]*vx + R[5]*vy + R[8]*vz;
        ci[192 + h*24 + pp*3 + 0] = ox;
        ci[192 + h*24 + pp*3 + 1] = oy;
        ci[192 + h*24 + pp*3 + 2] = oz;
        ci[480 + h*8 + pp] = sqrtf(ox*ox + oy*oy + oz*oz + 1e-8f);
    }
}

// ---------------------------------------------------------------------------
// LayerNorm over 384 features. One block per row, 128 threads.
// ---------------------------------------------------------------------------
__global__ void layernorm_kernel(const float* __restrict__ x,
                                 const float* __restrict__ g,
                                 const float* __restrict__ b,
                                 float* __restrict__ y)
{
    __shared__ float rs[128], rs2[128];
    const int i = blockIdx.x, tid = threadIdx.x;
    const float* xr = x + (size_t)i * CS;
    float v0 = xr[tid], v1 = xr[tid + 128], v2 = xr[tid + 256];
    rs[tid]  = v0 + v1 + v2;
    rs2[tid] = v0*v0 + v1*v1 + v2*v2;
    __syncthreads();
    for (int s = 64; s > 0; s >>= 1) {
        if (tid < s) { rs[tid] += rs[tid + s]; rs2[tid] += rs2[tid + s]; }
        __syncthreads();
    }
    float mean = rs[0] * (1.0f / CS);
    float var  = rs2[0] * (1.0f / CS) - mean * mean;
    float inv  = rsqrtf(var + 1e-5f);
    float* yr = y + (size_t)i * CS;
    yr[tid]       = (v0 - mean) * inv * g[tid]       + b[tid];
    yr[tid + 128] = (v1 - mean) * inv * g[tid + 128] + b[tid + 128];
    yr[tid + 256] = (v2 - mean) * inv * g[tid + 256] + b[tid + 256];
}

// ---------------------------------------------------------------------------
// Frame update: quat -> rot update, compose, translate. One thread per i.
// ---------------------------------------------------------------------------
__global__ void finalize_kernel(const float* __restrict__ upd,
                                const float* __restrict__ rot,
                                const float* __restrict__ trans,
                                float* __restrict__ out)
{
    int i = blockIdx.x * blockDim.x + threadIdx.x;
    if (i >= NN) return;
    const float* u = upd + i * 6;
    float bx = u[0], by = u[1], bz = u[2];
    float inv = rsqrtf(1.f + bx*bx + by*by + bz*bz);
    float w = inv, x = bx * inv, y = by * inv, z = bz * inv;
    float Ru[9] = {
        1 - 2*(y*y + z*z), 2*(x*y - w*z),     2*(x*z + w*y),
        2*(x*y + w*z),     1 - 2*(x*x + z*z), 2*(y*z - w*x),
        2*(x*z - w*y),     2*(y*z + w*x),     1 - 2*(x*x + y*y)};
    const float* R = rot + i * 9;
    float* ro = out + NN * CS + i * 9;
    #pragma unroll
    for (int r = 0; r < 3; r++)
        #pragma unroll
        for (int c = 0; c < 3; c++)
            ro[r*3+c] = R[r*3+0]*Ru[0*3+c] + R[r*3+1]*Ru[1*3+c] + R[r*3+2]*Ru[2*3+c];
    float tx = u[3], ty = u[4], tz = u[5];
    float* to = out + NN * CS + NN * 9 + i * 3;
    #pragma unroll
    for (int r = 0; r < 3; r++)
        to[r] = R[r*3+0]*tx + R[r*3+1]*ty + R[r*3+2]*tz + trans[i*3+r];
}

// ---------------------------------------------------------------------------
extern "C" void kernel_launch(void* const* d_in, const int* in_sizes, int n_in,
                              void* d_out, int out_size)
{
    const float* s      = (const float*)d_in[0];
    const float* p      = (const float*)d_in[1];
    const float* rot    = (const float*)d_in[2];
    const float* trans  = (const float*)d_in[3];
    const float* mask   = (const float*)d_in[4];
    const float* w_q    = (const float*)d_in[5];
    const float* b_q    = (const float*)d_in[6];
    const float* w_kv   = (const float*)d_in[7];
    const float* b_kv   = (const float*)d_in[8];
    const float* w_qp   = (const float*)d_in[9];
    const float* b_qp   = (const float*)d_in[10];
    const float* w_kvp  = (const float*)d_in[11];
    const float* b_kvp  = (const float*)d_in[12];
    const float* w_b    = (const float*)d_in[13];
    const float* b_b    = (const float*)d_in[14];
    const float* head_w = (const float*)d_in[15];
    const float* w_o    = (const float*)d_in[16];
    const float* b_o    = (const float*)d_in[17];
    const float* ln1_g  = (const float*)d_in[18];
    const float* ln1_b  = (const float*)d_in[19];
    const float* tw1    = (const float*)d_in[20];
    const float* tb1    = (const float*)d_in[21];
    const float* tw2    = (const float*)d_in[22];
    const float* tb2    = (const float*)d_in[23];
    const float* tw3    = (const float*)d_in[24];
    const float* tb3    = (const float*)d_in[25];
    const float* ln2_g  = (const float*)d_in[26];
    const float* ln2_b  = (const float*)d_in[27];
    const float* bb_w   = (const float*)d_in[28];
    const float* bb_b   = (const float*)d_in[29];
    float* out = (float*)d_out;

    float *q_, *kv_, *qp_, *kvp_, *kpk, *kppk, *vpk, *bias_, *a_, *ov_,
          *cat_, *x1, *x2, *x3, *upd_;
    cudaGetSymbolAddress((void**)&q_,   g_q);
    cudaGetSymbolAddress((void**)&kv_,  g_kv);
    cudaGetSymbolAddress((void**)&qp_,  g_qp);
    cudaGetSymbolAddress((void**)&kvp_, g_kvp);
    cudaGetSymbolAddress((void**)&kpk,  g_kpack);
    cudaGetSymbolAddress((void**)&kppk, g_kppack);
    cudaGetSymbolAddress((void**)&vpk,  g_vpack);
    cudaGetSymbolAddress((void**)&bias_, g_biasb);
    cudaGetSymbolAddress((void**)&a_,   g_att);
    cudaGetSymbolAddress((void**)&ov_,  g_ov);
    cudaGetSymbolAddress((void**)&cat_, g_cat);
    cudaGetSymbolAddress((void**)&x1,   g_x1);
    cudaGetSymbolAddress((void**)&x2,   g_x2);
    cudaGetSymbolAddress((void**)&x3,   g_x3);
    cudaGetSymbolAddress((void**)&upd_, g_upd);

    // projections
    sgemm_kernel<<<dim3(3, 8), 256>>>(s, w_q,   b_q,   nullptr, q_,   NN, 192, CS, 0);
    sgemm_kernel<<<dim3(6, 8), 256>>>(s, w_kv,  b_kv,  nullptr, kv_,  NN, 384, CS, 0);
    sgemm_kernel<<<dim3(3, 8), 256>>>(s, w_qp,  b_qp,  nullptr, qp_,  NN, 144, CS, 0);
    sgemm_kernel<<<dim3(7, 8), 256>>>(s, w_kvp, b_kvp, nullptr, kvp_, NN, 432, CS, 0);

    // rotate points to global frame
    rot_apply_kernel<<<(NN * 48  + 255) / 256, 256>>>(qp_,  rot, trans, 48);
    rot_apply_kernel<<<(NN * 144 + 255) / 256, 256>>>(kvp_, rot, trans, 144);

    // repack head-major
    pack_kernel<<<(HDS * NN * (16 + 12 + 40) + 255) / 256, 256>>>(kv_, kvp_, kpk, kppk, vpk);

    // bias = p @ w_b + b_b    (262144 x 128 x 12)
    sgemm_kernel<<<dim3(1, 4096), 256>>>(p, w_b, b_b, nullptr, bias_, NN * NN, HDS, CP, 0);

    // logits + softmax
    logits_kernel<<<dim3(NN, HDS), 256>>>(q_, qp_, kpk, kppk, bias_, mask, head_w, a_);
    softmax_kernel<<<HDS * NN, 256>>>(a_);

    // o / op_raw : per-head (512x512)@(512x40)
    for (int h = 0; h < HDS; h++)
        sgemm_kernel<<<dim3(1, 8), 256>>>(a_ + (size_t)h * NN * NN,
                                          vpk + (size_t)h * NN * 40,
                                          nullptr, nullptr,
                                          ov_ + (size_t)h * NN * 40,
                                          NN, 40, NN, 0);

    // o_pair (second pass over p)
    opair_kernel<<<NN, 192>>>(a_, p, cat_);

    // epilogue rotate/norm/concat
    postproc_kernel<<<NN, 192>>>(ov_, rot, trans, cat_);

    // output projection + residual, LN1
    sgemm_kernel<<<dim3(6, 8), 256>>>(cat_, w_o, b_o, s, x1, NN, CS, 2112, 0);
    layernorm_kernel<<<NN, 128>>>(x1, ln1_g, ln1_b, x2);

    // transition MLP + residual, LN2 -> out (s2)
    sgemm_kernel<<<dim3(6, 8), 256>>>(x2, tw1, tb1, nullptr, x3, NN, CS, CS, 1);
    sgemm_kernel<<<dim3(6, 8), 256>>>(x3, tw2, tb2, nullptr, x1, NN, CS, CS, 1);
    sgemm_kernel<<<dim3(6, 8), 256>>>(x1, tw3, tb3, x2,      x3, NN, CS, CS, 0);
    layernorm_kernel<<<NN, 128>>>(x3, ln2_g, ln2_b, out);

    // backbone update
    sgemm_kernel<<<dim3(1, 8), 256>>>(out, bb_w, bb_b, nullptr, upd_, NN, 6, CS, 0);
    finalize_kernel<<<4, 128>>>(upd_, rot, trans, out);
}

// round 4
// speedup vs baseline: 2.8360x; 2.8360x over previous
#include <cuda_runtime.h>
#include <math.h>

// ---------------------------------------------------------------------------
// StructureLayer (IPA) — B=1, N=512, H=12, C_S=384, C_P=128, C_H=16,
// P_QK=4, P_V=8.  Output: [ s2 (512*384) | rot_new (512*9) | trans_new (512*3) ]
// ---------------------------------------------------------------------------

#define NN 512
#define CS 384
#define CP 128
#define HDS 12

// proj row layout: [ q(192) | kv(384) | qp(144) | kvp(432) ]  = 1152
#define LDP 1152
#define OFF_Q   0
#define OFF_KV  192
#define OFF_QP  576
#define OFF_KVP 720

#define SQK 0.14433756729740643f    // sqrt(1/48)
#define SB  0.5773502691896258f     // sqrt(1/3)
#define SHW 0.13608276348795434f    // sqrt(1/54)

// ---- scratch (device globals) ----------------------------------------------
__device__ float g_wcat[CS * LDP];
__device__ float g_bcat[LDP];
__device__ float g_proj[NN * LDP];
__device__ float g_kpack[HDS * NN * 16];
__device__ float g_kppack[HDS * NN * 12];
__device__ float g_vpack[HDS * NN * 40];  // [h][j][ v(16) | vp(24) ]
__device__ float g_att[HDS * NN * NN];    // bias planes, then probs [h][i][j]
__device__ float g_ov[HDS * NN * 40];     // [h][i][ o(16) | op_raw(24) ]
__device__ float g_cat[NN * 2112];
__device__ float g_part[4 * NN * CS];     // split-K partials for w_o
__device__ float g_x2[NN * CS];
__device__ float g_x3[NN * CS];
__device__ float g_x1[NN * CS];

// ---------------------------------------------------------------------------
// Pack projection weights/biases into one (384 x 1152) matrix.
// ---------------------------------------------------------------------------
__global__ void pack_w_kernel(const float* __restrict__ w_q,  const float* __restrict__ b_q,
                              const float* __restrict__ w_kv, const float* __restrict__ b_kv,
                              const float* __restrict__ w_qp, const float* __restrict__ b_qp,
                              const float* __restrict__ w_kvp,const float* __restrict__ b_kvp,
                              float* __restrict__ wcat, float* __restrict__ bcat)
{
    int idx = blockIdx.x * blockDim.x + threadIdx.x;
    if (idx < CS * LDP) {
        int r = idx / LDP, c = idx % LDP;
        float v;
        if      (c < 192) v = w_q  [r * 192 + c];
        else if (c < 576) v = w_kv [r * 384 + (c - 192)];
        else if (c < 720) v = w_qp [r * 144 + (c - 576)];
        else              v = w_kvp[r * 432 + (c - 720)];
        wcat[idx] = v;
    } else if (idx < CS * LDP + LDP) {
        int c = idx - CS * LDP;
        float v;
        if      (c < 192) v = b_q  [c];
        else if (c < 576) v = b_kv [c - 192];
        else if (c < 720) v = b_qp [c - 576];
        else              v = b_kvp[c - 720];
        bcat[c] = v;
    }
}

// ---------------------------------------------------------------------------
// Register-tiled pipelined SGEMM: C = A(MxK)@B(KxN) [+bias][+res][relu]
// BM=BN=64, BK=16, 256 thr, 4x4/thread. blockIdx.z batch via strides.
// K must be a multiple of 16.
// ---------------------------------------------------------------------------
__global__ void sgemm_kernel(const float* __restrict__ A, int lda, long long sA,
                             const float* __restrict__ B, int ldb, long long sB,
                             const float* __restrict__ bias,
                             const float* __restrict__ res,
                             float* __restrict__ C, int ldc, long long sC,
                             int M, int Nn, int K, int relu)
{
    A += (size_t)blockIdx.z * (size_t)sA;
    B += (size_t)blockIdx.z * (size_t)sB;
    C += (size_t)blockIdx.z * (size_t)sC;

    __shared__ float As[64][17];
    __shared__ float Bs[16][64];
    const int bm = blockIdx.y * 64, bn = blockIdx.x * 64;
    const int tid = threadIdx.x;
    const int tx = tid & 15, ty = tid >> 4;

    float acc[4][4];
    #pragma unroll
    for (int i = 0; i < 4; i++)
        #pragma unroll
        for (int j = 0; j < 4; j++) acc[i][j] = 0.f;

    float ra[4], rb[4];
    // prologue: load tile k0=0 into regs
    #pragma unroll
    for (int l = 0; l < 4; l++) {
        int idx = tid + l * 256;
        int r = idx >> 4, c = idx & 15;
        int gr = bm + r;
        ra[l] = (gr < M) ? A[(size_t)gr * lda + c] : 0.f;
    }
    #pragma unroll
    for (int l = 0; l < 4; l++) {
        int idx = tid + l * 256;
        int r = idx >> 6, c = idx & 63;
        int gc = bn + c;
        rb[l] = (gc < Nn) ? B[(size_t)r * ldb + gc] : 0.f;
    }
    #pragma unroll
    for (int l = 0; l < 4; l++) {
        int idx = tid + l * 256;
        As[idx >> 4][idx & 15] = ra[l];
        Bs[idx >> 6][idx & 63] = rb[l];
    }
    __syncthreads();

    for (int k0 = 0; k0 < K; k0 += 16) {
        const bool more = (k0 + 16) < K;
        if (more) {
            #pragma unroll
            for (int l = 0; l < 4; l++) {
                int idx = tid + l * 256;
                int r = idx >> 4, c = idx & 15;
                int gr = bm + r;
                ra[l] = (gr < M) ? A[(size_t)gr * lda + (k0 + 16) + c] : 0.f;
            }
            #pragma unroll
            for (int l = 0; l < 4; l++) {
                int idx = tid + l * 256;
                int r = idx >> 6, c = idx & 63;
                int gc = bn + c;
                rb[l] = (gc < Nn) ? B[(size_t)(k0 + 16 + r) * ldb + gc] : 0.f;
            }
        }
        #pragma unroll
        for (int kk = 0; kk < 16; kk++) {
            float av[4];
            #pragma unroll
            for (int i = 0; i < 4; i++) av[i] = As[ty * 4 + i][kk];
            float4 bv = ((const float4*)&Bs[kk][0])[tx];
            #pragma unroll
            for (int i = 0; i < 4; i++) {
                acc[i][0] += av[i] * bv.x;
                acc[i][1] += av[i] * bv.y;
                acc[i][2] += av[i] * bv.z;
                acc[i][3] += av[i] * bv.w;
            }
        }
        __syncthreads();
        if (more) {
            #pragma unroll
            for (int l = 0; l < 4; l++) {
                int idx = tid + l * 256;
                As[idx >> 4][idx & 15] = ra[l];
                Bs[idx >> 6][idx & 63] = rb[l];
            }
            __syncthreads();
        }
    }

    #pragma unroll
    for (int i = 0; i < 4; i++) {
        int gr = bm + ty * 4 + i;
        if (gr >= M) continue;
        #pragma unroll
        for (int j = 0; j < 4; j++) {
            int gc = bn + tx * 4 + j;
            if (gc >= Nn) continue;
            float v = acc[i][j];
            if (bias) v += bias[gc];
            if (res)  v += res[(size_t)gr * ldc + gc];
            if (relu) v = fmaxf(v, 0.f);
            C[(size_t)gr * ldc + gc] = v;
        }
    }
}

// ---------------------------------------------------------------------------
// Apply frame to point triples inside g_proj rows (stride LDP).
// ---------------------------------------------------------------------------
__global__ void rot_apply_kernel(float* __restrict__ proj,
                                 const float* __restrict__ rot,
                                 const float* __restrict__ trans,
                                 int off, int npts)
{
    int idx = blockIdx.x * blockDim.x + threadIdx.x;
    if (idx >= NN * npts) return;
    int n = idx / npts, pp = idx % npts;
    float* pv = proj + (size_t)n * LDP + off + pp * 3;
    float x = pv[0], y = pv[1], z = pv[2];
    const float* R = rot + n * 9;
    const float* t = trans + n * 3;
    pv[0] = R[0]*x + R[1]*y + R[2]*z + t[0];
    pv[1] = R[3]*x + R[4]*y + R[5]*z + t[1];
    pv[2] = R[6]*x + R[7]*y + R[8]*z + t[2];
}

// ---------------------------------------------------------------------------
// Repack k / kp / v|vp head-major.
// ---------------------------------------------------------------------------
__global__ void pack_kernel(const float* __restrict__ proj,
                            float* __restrict__ kpack,
                            float* __restrict__ kppack,
                            float* __restrict__ vpack)
{
    const int T1 = HDS * NN * 16, T2 = HDS * NN * 12, T3 = HDS * NN * 40;
    int idx = blockIdx.x * blockDim.x + threadIdx.x;
    if (idx < T1) {
        int c = idx & 15, j = (idx >> 4) & 511, h = idx >> 13;
        kpack[idx] = proj[(size_t)j * LDP + OFF_KV + h * 32 + c];
    } else if (idx < T1 + T2) {
        int t = idx - T1;
        int d = t % 12, j = (t / 12) & 511, h = t / (12 * 512);
        kppack[t] = proj[(size_t)j * LDP + OFF_KVP + h * 36 + d];
    } else if (idx < T1 + T2 + T3) {
        int t = idx - T1 - T2;
        int c = t % 40, j = (t / 40) & 511, h = t / (40 * 512);
        float v;
        if (c < 16) v = proj[(size_t)j * LDP + OFF_KV + h * 32 + 16 + c];
        else        v = proj[(size_t)j * LDP + OFF_KVP + h * 36 + 12 + (c - 16)];
        vpack[t] = v;
    }
}

// ---------------------------------------------------------------------------
// bias planes: att[h][i][j] = (p[i,j,:]·w_b[:,h] + b_b[h]) * sqrt(1/3)
// One warp per 32 consecutive j of a row i. Fully coalesced reads/writes.
// ---------------------------------------------------------------------------
__global__ void bias_kernel(const float* __restrict__ p,
                            const float* __restrict__ w_b,
                            const float* __restrict__ b_b,
                            float* __restrict__ att)
{
    __shared__ float wbt[HDS][CP];   // transposed w_b
    __shared__ float bbs[HDS];
    const int tid = threadIdx.x;
    #pragma unroll
    for (int k = 0; k < 6; k++) {
        int e = tid + k * 256;
        int h = e / CP, c = e % CP;
        wbt[h][c] = w_b[c * HDS + h];
    }
    if (tid < HDS) bbs[tid] = b_b[tid];
    __syncthreads();

    const int gw = blockIdx.x * 8 + (tid >> 5);
    const int lane = tid & 31;
    const int i = gw >> 4;
    const int j = ((gw & 15) << 5) + lane;

    float acc[HDS];
    #pragma unroll
    for (int h = 0; h < HDS; h++) acc[h] = 0.f;

    const float4* prow = (const float4*)(p + ((size_t)i * NN + j) * CP);
    #pragma unroll 4
    for (int c4 = 0; c4 < 32; c4++) {
        float4 pv = prow[c4];
        #pragma unroll
        for (int h = 0; h < HDS; h++) {
            float4 wv = ((const float4*)&wbt[h][0])[c4];
            acc[h] = fmaf(pv.x, wv.x,
                     fmaf(pv.y, wv.y,
                     fmaf(pv.z, wv.z,
                     fmaf(pv.w, wv.w, acc[h]))));
        }
    }
    #pragma unroll
    for (int h = 0; h < HDS; h++)
        att[((size_t)(h * NN) + i) * NN + j] = (acc[h] + bbs[h]) * SB;
}

// ---------------------------------------------------------------------------
// Fused logits + softmax.  Block = (i-tile of 8, head h).  256 threads.
// Reads bias plane from att, writes probs back to att.
// ---------------------------------------------------------------------------
__global__ void logits_softmax_kernel(const float* __restrict__ proj,
                                      const float* __restrict__ kpack,
                                      const float* __restrict__ kppack,
                                      const float* __restrict__ mask,
                                      const float* __restrict__ head_w,
                                      float* __restrict__ att)
{
    const int i0 = blockIdx.x * 8, h = blockIdx.y;
    const int tid = threadIdx.x;

    __shared__ float att_s[8][NN];    // 16 KB
    __shared__ float kt[64][20];
    __shared__ float kpt[64][13];
    __shared__ float q_s[8][17];
    __shared__ float qp_s[8][13];
    __shared__ float m_i[8];
    __shared__ float sh_hw;

    if (tid < 128) {
        int il = tid >> 4, c = tid & 15;
        q_s[il][c] = proj[(size_t)(i0 + il) * LDP + OFF_Q + h * 16 + c];
    } else if (tid < 224) {
        int e = tid - 128;
        int il = e / 12, c = e % 12;
        qp_s[il][c] = proj[(size_t)(i0 + il) * LDP + OFF_QP + h * 12 + c];
    } else if (tid < 232) {
        m_i[tid - 224] = mask[i0 + (tid - 224)];
    } else if (tid == 232) {
        float w = head_w[h];
        float sp = fmaxf(w, 0.f) + log1pf(expf(-fabsf(w)));
        sh_hw = sp * SHW;
    }

    const float* kb  = kpack  + (size_t)(h * NN) * 16;
    const float* kpb = kppack + (size_t)(h * NN) * 12;

    const int jl = tid >> 2, ig = tid & 3;

    for (int j0 = 0; j0 < NN; j0 += 64) {
        // stage k tiles
        #pragma unroll
        for (int k = 0; k < 4; k++) {
            int e = tid + k * 256;
            int r = e >> 4, c = e & 15;
            kt[r][c] = kb[(size_t)(j0 + r) * 16 + c];
        }
        #pragma unroll
        for (int k = 0; k < 3; k++) {
            int e = tid + k * 256;
            if (e < 768) {
                int r = e / 12, c = e % 12;
                kpt[r][c] = kpb[(size_t)(j0 + r) * 12 + c];
            }
        }
        __syncthreads();

        float mj = mask[j0 + jl];
        float hw = sh_hw;
        #pragma unroll
        for (int ii = 0; ii < 2; ii++) {
            int il = ig * 2 + ii;
            float qk = 0.f;
            #pragma unroll
            for (int c = 0; c < 16; c++) qk = fmaf(q_s[il][c], kt[jl][c], qk);
            float d2 = 0.f;
            #pragma unroll
            for (int d = 0; d < 12; d++) {
                float dd = qp_s[il][d] - kpt[jl][d];
                d2 = fmaf(dd, dd, d2);
            }
            float bias = att[((size_t)(h * NN) + i0 + il) * NN + j0 + jl];
            att_s[il][j0 + jl] = qk * SQK + bias - 0.5f * hw * d2
                               + (m_i[il] * mj - 1.0f) * 100000.0f;
        }
        __syncthreads();
    }

    // softmax: warp w owns row w
    const int w = tid >> 5, lane = tid & 31;
    float vals[16];
    float vmax = -1e30f;
    #pragma unroll
    for (int k = 0; k < 16; k++) {
        vals[k] = att_s[w][lane + 32 * k];
        vmax = fmaxf(vmax, vals[k]);
    }
    #pragma unroll
    for (int o = 16; o > 0; o >>= 1)
        vmax = fmaxf(vmax, __shfl_xor_sync(0xffffffffu, vmax, o));
    float sum = 0.f;
    #pragma unroll
    for (int k = 0; k < 16; k++) { vals[k] = expf(vals[k] - vmax); sum += vals[k]; }
    #pragma unroll
    for (int o = 16; o > 0; o >>= 1)
        sum += __shfl_xor_sync(0xffffffffu, sum, o);
    float inv = 1.0f / sum;
    float* arow = att + ((size_t)(h * NN) + i0 + w) * NN;
    #pragma unroll
    for (int k = 0; k < 16; k++)
        arow[lane + 32 * k] = vals[k] * inv;
}

// ---------------------------------------------------------------------------
// o_pair[i,h,c] = sum_j a[h,i,j]*p[i,j,c]  -> cat[i][576 + h*128 + c]
// ---------------------------------------------------------------------------
__global__ void opair_kernel(const float* __restrict__ att,
                             const float* __restrict__ p,
                             float* __restrict__ cat)
{
    const int i = blockIdx.x;
    __shared__ float as[HDS][NN];    // 24 KB
    __shared__ float ps[32][128];    // 16 KB
    const int tid = threadIdx.x;     // 192

    for (int idx = tid; idx < HDS * NN; idx += 192) {
        int h = idx >> 9, j = idx & 511;
        as[h][j] = att[((size_t)(h * NN + i)) * NN + j];
    }

    const int c4 = tid & 31;
    const int hh = tid >> 5;
    float acc0[4] = {0,0,0,0}, acc1[4] = {0,0,0,0};
    const float* pi = p + (size_t)i * NN * CP;

    for (int j0 = 0; j0 < NN; j0 += 32) {
        for (int idx = tid; idx < 32 * 32; idx += 192) {
            int jj = idx >> 5, cc = idx & 31;
            ((float4*)&ps[jj][0])[cc] =
                ((const float4*)(pi + (size_t)(j0 + jj) * CP))[cc];
        }
        __syncthreads();
        #pragma unroll 8
        for (int jj = 0; jj < 32; jj++) {
            float a0 = as[2 * hh][j0 + jj];
            float a1 = as[2 * hh + 1][j0 + jj];
            float4 pv = ((const float4*)&ps[jj][0])[c4];
            acc0[0] += a0 * pv.x; acc0[1] += a0 * pv.y;
            acc0[2] += a0 * pv.z; acc0[3] += a0 * pv.w;
            acc1[0] += a1 * pv.x; acc1[1] += a1 * pv.y;
            acc1[2] += a1 * pv.z; acc1[3] += a1 * pv.w;
        }
        __syncthreads();
    }
    float* dst = cat + (size_t)i * 2112 + 576;
    #pragma unroll
    for (int d = 0; d < 4; d++) {
        dst[(2 * hh) * 128 + c4 * 4 + d]     = acc0[d];
        dst[(2 * hh + 1) * 128 + c4 * 4 + d] = acc1[d];
    }
}

// ---------------------------------------------------------------------------
// Epilogue: copy o, rotate op back, norms.
// ---------------------------------------------------------------------------
__global__ void postproc_kernel(const float* __restrict__ ov,
                                const float* __restrict__ rot,
                                const float* __restrict__ trans,
                                float* __restrict__ cat)
{
    const int i = blockIdx.x;
    const int tid = threadIdx.x;   // 192
    float* ci = cat + (size_t)i * 2112;
    {
        int h = tid >> 4, c = tid & 15;
        ci[tid] = ov[((size_t)(h * NN) + i) * 40 + c];
    }
    if (tid < 96) {
        int h = tid >> 3, pp = tid & 7;
        const float* base = ov + ((size_t)(h * NN) + i) * 40 + 16 + pp * 3;
        float vx = base[0] - trans[i*3+0];
        float vy = base[1] - trans[i*3+1];
        float vz = base[2] - trans[i*3+2];
        const float* R = rot + i * 9;
        float ox = R[0]*vx + R[3]*vy + R[6]*vz;
        float oy = R[1]*vx + R[4]*vy + R[7]*vz;
        float oz = R[2]*vx + R[5]*vy + R[8]*vz;
        ci[192 + h*24 + pp*3 + 0] = ox;
        ci[192 + h*24 + pp*3 + 1] = oy;
        ci[192 + h*24 + pp*3 + 2] = oz;
        ci[480 + h*8 + pp] = sqrtf(ox*ox + oy*oy + oz*oz + 1e-8f);
    }
}

// ---------------------------------------------------------------------------
// Split-K reduce + b_o + residual s + LayerNorm1.  Block per row, 128 thr.
// ---------------------------------------------------------------------------
__global__ void reduce_ln1_kernel(const float* __restrict__ part,
                                  const float* __restrict__ b_o,
                                  const float* __restrict__ s,
                                  const float* __restrict__ g,
                                  const float* __restrict__ b,
                                  float* __restrict__ y)
{
    __shared__ float rs[128], rs2[128];
    const int i = blockIdx.x, tid = threadIdx.x;
    const size_t SP = (size_t)NN * CS;
    float v[3];
    float sm = 0.f, sm2 = 0.f;
    #pragma unroll
    for (int k = 0; k < 3; k++) {
        int c = tid + k * 128;
        size_t o = (size_t)i * CS + c;
        float x = part[o] + part[SP + o] + part[2*SP + o] + part[3*SP + o]
                + b_o[c] + s[o];
        v[k] = x;
        sm += x; sm2 += x * x;
    }
    rs[tid] = sm; rs2[tid] = sm2;
    __syncthreads();
    for (int st = 64; st > 0; st >>= 1) {
        if (tid < st) { rs[tid] += rs[tid + st]; rs2[tid] += rs2[tid + st]; }
        __syncthreads();
    }
    float mean = rs[0] * (1.0f / CS);
    float var  = rs2[0] * (1.0f / CS) - mean * mean;
    float inv  = rsqrtf(var + 1e-5f);
    #pragma unroll
    for (int k = 0; k < 3; k++) {
        int c = tid + k * 128;
        y[(size_t)i * CS + c] = (v[k] - mean) * inv * g[c] + b[c];
    }
}

// ---------------------------------------------------------------------------
// LayerNorm over 384 features.
// ---------------------------------------------------------------------------
__global__ void layernorm_kernel(const float* __restrict__ x,
                                 const float* __restrict__ g,
                                 const float* __restrict__ b,
                                 float* __restrict__ y)
{
    __shared__ float rs[128], rs2[128];
    const int i = blockIdx.x, tid = threadIdx.x;
    const float* xr = x + (size_t)i * CS;
    float v0 = xr[tid], v1 = xr[tid + 128], v2 = xr[tid + 256];
    rs[tid]  = v0 + v1 + v2;
    rs2[tid] = v0*v0 + v1*v1 + v2*v2;
    __syncthreads();
    for (int st = 64; st > 0; st >>= 1) {
        if (tid < st) { rs[tid] += rs[tid + st]; rs2[tid] += rs2[tid + st]; }
        __syncthreads();
    }
    float mean = rs[0] * (1.0f / CS);
    float var  = rs2[0] * (1.0f / CS) - mean * mean;
    float inv  = rsqrtf(var + 1e-5f);
    float* yr = y + (size_t)i * CS;
    yr[tid]       = (v0 - mean) * inv * g[tid]       + b[tid];
    yr[tid + 128] = (v1 - mean) * inv * g[tid + 128] + b[tid + 128];
    yr[tid + 256] = (v2 - mean) * inv * g[tid + 256] + b[tid + 256];
}

// ---------------------------------------------------------------------------
// Fused backbone projection (s2 @ bb_w + bb_b) + quaternion frame update.
// Block per residue i, 192 threads (6 warps: warp w computes column w).
// ---------------------------------------------------------------------------
__global__ void bb_finalize_kernel(const float* __restrict__ s2,
                                   const float* __restrict__ bb_w,
                                   const float* __restrict__ bb_b,
                                   const float* __restrict__ rot,
                                   const float* __restrict__ trans,
                                   float* __restrict__ out)
{
    const int i = blockIdx.x;
    const int tid = threadIdx.x;
    const int w = tid >> 5, lane = tid & 31;
    __shared__ float u[6];
    const float* row = s2 + (size_t)i * CS;
    float sum = 0.f;
    for (int c = lane; c < CS; c += 32)
        sum = fmaf(row[c], bb_w[c * 6 + w], sum);
    #pragma unroll
    for (int o = 16; o > 0; o >>= 1)
        sum += __shfl_xor_sync(0xffffffffu, sum, o);
    if (lane == 0) u[w] = sum + bb_b[w];
    __syncthreads();
    if (tid == 0) {
        float bx = u[0], by = u[1], bz = u[2];
        float inv = rsqrtf(1.f + bx*bx + by*by + bz*bz);
        float qw = inv, x = bx * inv, y = by * inv, z = bz * inv;
        float Ru[9] = {
            1 - 2*(y*y + z*z), 2*(x*y - qw*z),    2*(x*z + qw*y),
            2*(x*y + qw*z),    1 - 2*(x*x + z*z), 2*(y*z - qw*x),
            2*(x*z - qw*y),    2*(y*z + qw*x),    1 - 2*(x*x + y*y)};
        const float* R = rot + i * 9;
        float* ro = out + NN * CS + i * 9;
        #pragma unroll
        for (int r = 0; r < 3; r++)
            #pragma unroll
            for (int c = 0; c < 3; c++)
                ro[r*3+c] = R[r*3+0]*Ru[0*3+c] + R[r*3+1]*Ru[1*3+c]
                          + R[r*3+2]*Ru[2*3+c];
        float tx = u[3], ty = u[4], tz = u[5];
        float* to = out + NN * CS + NN * 9 + i * 3;
        #pragma unroll
        for (int r = 0; r < 3; r++)
            to[r] = R[r*3+0]*tx + R[r*3+1]*ty + R[r*3+2]*tz + trans[i*3+r];
    }
}

// ---------------------------------------------------------------------------
extern "C" void kernel_launch(void* const* d_in, const int* in_sizes, int n_in,
                              void* d_out, int out_size)
{
    const float* s      = (const float*)d_in[0];
    const float* p      = (const float*)d_in[1];
    const float* rot    = (const float*)d_in[2];
    const float* trans  = (const float*)d_in[3];
    const float* mask   = (const float*)d_in[4];
    const float* w_q    = (const float*)d_in[5];
    const float* b_q    = (const float*)d_in[6];
    const float* w_kv   = (const float*)d_in[7];
    const float* b_kv   = (const float*)d_in[8];
    const float* w_qp   = (const float*)d_in[9];
    const float* b_qp   = (const float*)d_in[10];
    const float* w_kvp  = (const float*)d_in[11];
    const float* b_kvp  = (const float*)d_in[12];
    const float* w_b    = (const float*)d_in[13];
    const float* b_b    = (const float*)d_in[14];
    const float* head_w = (const float*)d_in[15];
    const float* w_o    = (const float*)d_in[16];
    const float* b_o    = (const float*)d_in[17];
    const float* ln1_g  = (const float*)d_in[18];
    const float* ln1_b  = (const float*)d_in[19];
    const float* tw1    = (const float*)d_in[20];
    const float* tb1    = (const float*)d_in[21];
    const float* tw2    = (const float*)d_in[22];
    const float* tb2    = (const float*)d_in[23];
    const float* tw3    = (const float*)d_in[24];
    const float* tb3    = (const float*)d_in[25];
    const float* ln2_g  = (const float*)d_in[26];
    const float* ln2_b  = (const float*)d_in[27];
    const float* bb_w   = (const float*)d_in[28];
    const float* bb_b   = (const float*)d_in[29];
    float* out = (float*)d_out;

    float *wcat, *bcat, *proj, *kpk, *kppk, *vpk, *a_, *ov_, *cat_,
          *part, *x2, *x3, *x1;
    cudaGetSymbolAddress((void**)&wcat, g_wcat);
    cudaGetSymbolAddress((void**)&bcat, g_bcat);
    cudaGetSymbolAddress((void**)&proj, g_proj);
    cudaGetSymbolAddress((void**)&kpk,  g_kpack);
    cudaGetSymbolAddress((void**)&kppk, g_kppack);
    cudaGetSymbolAddress((void**)&vpk,  g_vpack);
    cudaGetSymbolAddress((void**)&a_,   g_att);
    cudaGetSymbolAddress((void**)&ov_,  g_ov);
    cudaGetSymbolAddress((void**)&cat_, g_cat);
    cudaGetSymbolAddress((void**)&part, g_part);
    cudaGetSymbolAddress((void**)&x2,   g_x2);
    cudaGetSymbolAddress((void**)&x3,   g_x3);
    cudaGetSymbolAddress((void**)&x1,   g_x1);

    // bias planes (only needs p) — first, overlaps nothing but is independent
    bias_kernel<<<1024, 256>>>(p, w_b, b_b, a_);

    // pack weights, fused projection GEMM
    pack_w_kernel<<<(CS * LDP + LDP + 255) / 256, 256>>>(
        w_q, b_q, w_kv, b_kv, w_qp, b_qp, w_kvp, b_kvp, wcat, bcat);
    sgemm_kernel<<<dim3(18, 8, 1), 256>>>(s, CS, 0, wcat, LDP, 0,
                                          bcat, nullptr, proj, LDP, 0,
                                          NN, LDP, CS, 0);

    // rotate points to global frame (in place inside proj)
    rot_apply_kernel<<<(NN * 48  + 255) / 256, 256>>>(proj, rot, trans, OFF_QP, 48);
    rot_apply_kernel<<<(NN * 144 + 255) / 256, 256>>>(proj, rot, trans, OFF_KVP, 144);

    // repack head-major
    pack_kernel<<<(HDS * NN * 68 + 255) / 256, 256>>>(proj, kpk, kppk, vpk);

    // fused logits + softmax
    logits_softmax_kernel<<<dim3(64, HDS), 256>>>(proj, kpk, kppk, mask, head_w, a_);

    // batched o / op_raw: 12 x (512x512)@(512x40)
    sgemm_kernel<<<dim3(1, 8, HDS), 256>>>(a_, NN, (long long)NN * NN,
                                           vpk, 40, (long long)NN * 40,
                                           nullptr, nullptr,
                                           ov_, 40, (long long)NN * 40,
                                           NN, 40, NN, 0);

    // o_pair (second pass over p)
    opair_kernel<<<NN, 192>>>(a_, p, cat_);

    // epilogue rotate/norm/concat
    postproc_kernel<<<NN, 192>>>(ov_, rot, trans, cat_);

    // output projection split-K (4 x 528) + fused reduce/residual/LN1
    sgemm_kernel<<<dim3(6, 8, 4), 256>>>(cat_, 2112, 528,
                                         w_o, CS, (long long)528 * CS,
                                         nullptr, nullptr,
                                         part, CS, (long long)NN * CS,
                                         NN, CS, 528, 0);
    reduce_ln1_kernel<<<NN, 128>>>(part, b_o, s, ln1_g, ln1_b, x2);

    // transition MLP + residual, LN2 -> out (s2)
    sgemm_kernel<<<dim3(6, 8, 1), 256>>>(x2, CS, 0, tw1, CS, 0, tb1, nullptr,
                                         x3, CS, 0, NN, CS, CS, 1);
    sgemm_kernel<<<dim3(6, 8, 1), 256>>>(x3, CS, 0, tw2, CS, 0, tb2, nullptr,
                                         x1, CS, 0, NN, CS, CS, 1);
    sgemm_kernel<<<dim3(6, 8, 1), 256>>>(x1, CS, 0, tw3, CS, 0, tb3, x2,
                                         x3, CS, 0, NN, CS, CS, 0);
    layernorm_kernel<<<NN, 128>>>(x3, ln2_g, ln2_b, out);

    // backbone update (fused projection + quat compose)
    bb_finalize_kernel<<<NN, 192>>>(out, bb_w, bb_b, rot, trans, out);
}

// round 5
// speedup vs baseline: 3.0788x; 1.0856x over previous
#include <cuda_runtime.h>
#include <math.h>

// ---------------------------------------------------------------------------
// StructureLayer (IPA) — B=1, N=512, H=12, C_S=384, C_P=128, C_H=16,
// P_QK=4, P_V=8.  Output: [ s2 (512*384) | rot_new (512*9) | trans_new (512*3) ]
// ---------------------------------------------------------------------------

#define NN 512
#define CS 384
#define CP 128
#define HDS 12

// proj row layout: [ q(192) | kv(384) | qp(144) | kvp(432) ]  = 1152
#define LDP 1152
#define OFF_Q   0
#define OFF_KV  192
#define OFF_QP  576
#define OFF_KVP 720

#define SQK 0.14433756729740643f    // sqrt(1/48)
#define SB  0.5773502691896258f     // sqrt(1/3)
#define SHW 0.13608276348795434f    // sqrt(1/54)

// ---- scratch (device globals) ----------------------------------------------
__device__ float g_wcat[CS * LDP];
__device__ float g_bcat[LDP];
__device__ float g_proj[NN * LDP];
__device__ float g_kpack[HDS * NN * 16];
__device__ float g_kppack[HDS * NN * 12];
__device__ float g_vpack[HDS * NN * 40];  // [h][j][ v(16) | vp(24) ]
__device__ float g_att[HDS * NN * NN];    // bias planes, then probs [h][i][j]
__device__ float g_ov[HDS * NN * 40];     // [h][i][ o(16) | op_raw(24) ]
__device__ float g_cat[NN * 2112];
__device__ float g_part[3 * NN * CS];     // split-K partials
__device__ float g_x2[NN * CS];
__device__ float g_x3[NN * CS];
__device__ float g_x1[NN * CS];

// ---------------------------------------------------------------------------
// Pack projection weights/biases into one (384 x 1152) matrix.
// ---------------------------------------------------------------------------
__global__ void pack_w_kernel(const float* __restrict__ w_q,  const float* __restrict__ b_q,
                              const float* __restrict__ w_kv, const float* __restrict__ b_kv,
                              const float* __restrict__ w_qp, const float* __restrict__ b_qp,
                              const float* __restrict__ w_kvp,const float* __restrict__ b_kvp,
                              float* __restrict__ wcat, float* __restrict__ bcat)
{
    int idx = blockIdx.x * blockDim.x + threadIdx.x;
    if (idx < CS * LDP) {
        int r = idx / LDP, c = idx % LDP;
        float v;
        if      (c < 192) v = w_q  [r * 192 + c];
        else if (c < 576) v = w_kv [r * 384 + (c - 192)];
        else if (c < 720) v = w_qp [r * 144 + (c - 576)];
        else              v = w_kvp[r * 432 + (c - 720)];
        wcat[idx] = v;
    } else if (idx < CS * LDP + LDP) {
        int c = idx - CS * LDP;
        float v;
        if      (c < 192) v = b_q  [c];
        else if (c < 576) v = b_kv [c - 192];
        else if (c < 720) v = b_qp [c - 576];
        else              v = b_kvp[c - 720];
        bcat[c] = v;
    }
}

// ---------------------------------------------------------------------------
// Fast SGEMM: 64x64 tile, 128 threads, 8x4 per thread, double-buffered smem.
// Requires: M,N multiples of 64; K multiple of 16; all pointers float4-aligned
// per the launch configs used below. grid = (N/64, M/64, z).
// ---------------------------------------------------------------------------
__global__ void __launch_bounds__(128)
gemm64_kernel(const float* __restrict__ A, int lda, long long sA,
              const float* __restrict__ B, int ldb, long long sB,
              const float* __restrict__ bias,
              float* __restrict__ C, int ldc, long long sC,
              int K)
{
    A += (size_t)blockIdx.z * (size_t)sA;
    B += (size_t)blockIdx.z * (size_t)sB;
    C += (size_t)blockIdx.z * (size_t)sC;

    __shared__ __align__(16) float As[2][16][68];
    __shared__ __align__(16) float Bs[2][16][64];

    const int bm = blockIdx.y * 64, bn = blockIdx.x * 64;
    const int tid = threadIdx.x;
    const int tx = tid & 15, ty = tid >> 4;      // tx: n (16x4), ty: m (8x8)
    const int m0 = ty * 8, n0 = tx * 4;

    const int ar = tid >> 2, ak = (tid & 3) * 4; // A loads: 2 float4 per thread
    const int br = tid >> 4, bc = (tid & 15) * 4;// B loads: 2 float4 per thread

    const float* Ab = A + (size_t)bm * lda;

    float4 ra0, ra1, rb0, rb1;
    ra0 = *(const float4*)(Ab + (size_t)ar * lda + ak);
    ra1 = *(const float4*)(Ab + (size_t)(ar + 32) * lda + ak);
    rb0 = *(const float4*)(B + (size_t)br * ldb + bn + bc);
    rb1 = *(const float4*)(B + (size_t)(br + 8) * ldb + bn + bc);
    As[0][ak+0][ar] = ra0.x; As[0][ak+1][ar] = ra0.y;
    As[0][ak+2][ar] = ra0.z; As[0][ak+3][ar] = ra0.w;
    As[0][ak+0][ar+32] = ra1.x; As[0][ak+1][ar+32] = ra1.y;
    As[0][ak+2][ar+32] = ra1.z; As[0][ak+3][ar+32] = ra1.w;
    *(float4*)&Bs[0][br][bc]     = rb0;
    *(float4*)&Bs[0][br + 8][bc] = rb1;
    __syncthreads();

    float acc[8][4];
    #pragma unroll
    for (int i = 0; i < 8; i++)
        #pragma unroll
        for (int j = 0; j < 4; j++) acc[i][j] = 0.f;

    int buf = 0;
    for (int k0 = 0; k0 < K; k0 += 16) {
        const bool more = (k0 + 16) < K;
        if (more) {
            ra0 = *(const float4*)(Ab + (size_t)ar * lda + k0 + 16 + ak);
            ra1 = *(const float4*)(Ab + (size_t)(ar + 32) * lda + k0 + 16 + ak);
            rb0 = *(const float4*)(B + (size_t)(k0 + 16 + br) * ldb + bn + bc);
            rb1 = *(const float4*)(B + (size_t)(k0 + 16 + br + 8) * ldb + bn + bc);
        }
        #pragma unroll
        for (int kk = 0; kk < 16; kk++) {
            float4 a0 = *(const float4*)&As[buf][kk][m0];
            float4 a1 = *(const float4*)&As[buf][kk][m0 + 4];
            float4 b  = *(const float4*)&Bs[buf][kk][n0];
            float am[8] = {a0.x, a0.y, a0.z, a0.w, a1.x, a1.y, a1.z, a1.w};
            #pragma unroll
            for (int i = 0; i < 8; i++) {
                acc[i][0] = fmaf(am[i], b.x, acc[i][0]);
                acc[i][1] = fmaf(am[i], b.y, acc[i][1]);
                acc[i][2] = fmaf(am[i], b.z, acc[i][2]);
                acc[i][3] = fmaf(am[i], b.w, acc[i][3]);
            }
        }
        if (more) {
            buf ^= 1;
            __syncthreads();
            As[buf][ak+0][ar] = ra0.x; As[buf][ak+1][ar] = ra0.y;
            As[buf][ak+2][ar] = ra0.z; As[buf][ak+3][ar] = ra0.w;
            As[buf][ak+0][ar+32] = ra1.x; As[buf][ak+1][ar+32] = ra1.y;
            As[buf][ak+2][ar+32] = ra1.z; As[buf][ak+3][ar+32] = ra1.w;
            *(float4*)&Bs[buf][br][bc]     = rb0;
            *(float4*)&Bs[buf][br + 8][bc] = rb1;
            __syncthreads();
        }
    }

    #pragma unroll
    for (int i = 0; i < 8; i++) {
        float4 o = make_float4(acc[i][0], acc[i][1], acc[i][2], acc[i][3]);
        if (bias) {
            o.x += bias[bn + n0 + 0];
            o.y += bias[bn + n0 + 1];
            o.z += bias[bn + n0 + 2];
            o.w += bias[bn + n0 + 3];
        }
        *(float4*)(C + (size_t)(bm + m0 + i) * ldc + bn + n0) = o;
    }
}

// ---------------------------------------------------------------------------
// Old bounds-checked 64x64 SGEMM (kept for the N=40 ov GEMM, batched via z).
// ---------------------------------------------------------------------------
__global__ void sgemm_kernel(const float* __restrict__ A, int lda, long long sA,
                             const float* __restrict__ B, int ldb, long long sB,
                             float* __restrict__ C, int ldc, long long sC,
                             int M, int Nn, int K)
{
    A += (size_t)blockIdx.z * (size_t)sA;
    B += (size_t)blockIdx.z * (size_t)sB;
    C += (size_t)blockIdx.z * (size_t)sC;

    __shared__ float As[64][17];
    __shared__ float Bs[16][64];
    const int bm = blockIdx.y * 64, bn = blockIdx.x * 64;
    const int tid = threadIdx.x;
    const int tx = tid & 15, ty = tid >> 4;
    float acc[4][4];
    #pragma unroll
    for (int i = 0; i < 4; i++)
        #pragma unroll
        for (int j = 0; j < 4; j++) acc[i][j] = 0.f;

    for (int k0 = 0; k0 < K; k0 += 16) {
        #pragma unroll
        for (int l = 0; l < 4; l++) {
            int idx = tid + l * 256;
            int r = idx >> 4, c = idx & 15;
            int gr = bm + r;
            As[r][c] = (gr < M) ? A[(size_t)gr * lda + (k0 + c)] : 0.f;
        }
        #pragma unroll
        for (int l = 0; l < 4; l++) {
            int idx = tid + l * 256;
            int r = idx >> 6, c = idx & 63;
            int gc = bn + c;
            Bs[r][c] = (gc < Nn) ? B[(size_t)(k0 + r) * ldb + gc] : 0.f;
        }
        __syncthreads();
        #pragma unroll
        for (int kk = 0; kk < 16; kk++) {
            float av[4];
            #pragma unroll
            for (int i = 0; i < 4; i++) av[i] = As[ty * 4 + i][kk];
            float4 bv = ((const float4*)&Bs[kk][0])[tx];
            #pragma unroll
            for (int i = 0; i < 4; i++) {
                acc[i][0] += av[i] * bv.x;
                acc[i][1] += av[i] * bv.y;
                acc[i][2] += av[i] * bv.z;
                acc[i][3] += av[i] * bv.w;
            }
        }
        __syncthreads();
    }
    #pragma unroll
    for (int i = 0; i < 4; i++) {
        int gr = bm + ty * 4 + i;
        if (gr >= M) continue;
        #pragma unroll
        for (int j = 0; j < 4; j++) {
            int gc = bn + tx * 4 + j;
            if (gc >= Nn) continue;
            C[(size_t)gr * ldc + gc] = acc[i][j];
        }
    }
}

// ---------------------------------------------------------------------------
// Fused rotate + repack:
//  - rotate kp/vp points (inside kvp) into global frame while packing
//    head-major kpack / kppack / vpack (v from kv, no rotation).
//  - rotate qp points in place inside proj.
// ---------------------------------------------------------------------------
__global__ void rotpack_kernel(float* __restrict__ proj,
                               const float* __restrict__ rot,
                               const float* __restrict__ trans,
                               float* __restrict__ kpack,
                               float* __restrict__ kppack,
                               float* __restrict__ vpack)
{
    int idx = blockIdx.x * blockDim.x + threadIdx.x;
    if (idx < NN * HDS) {
        int h = idx % HDS, j = idx / HDS;
        const float* R = rot + j * 9;
        const float* t = trans + j * 3;
        float R0=R[0],R1=R[1],R2=R[2],R3=R[3],R4=R[4],R5=R[5],R6=R[6],R7=R[7],R8=R[8];
        float t0=t[0],t1=t[1],t2=t[2];
        const float* kvr = proj + (size_t)j * LDP + OFF_KV + h * 32;
        float* kp = kpack + ((size_t)h * NN + j) * 16;
        float* vp = vpack + ((size_t)h * NN + j) * 40;
        #pragma unroll
        for (int c = 0; c < 16; c++) kp[c] = kvr[c];
        #pragma unroll
        for (int c = 0; c < 16; c++) vp[c] = kvr[16 + c];
        const float* kvpr = proj + (size_t)j * LDP + OFF_KVP + h * 36;
        float* kpp = kppack + ((size_t)h * NN + j) * 12;
        #pragma unroll
        for (int pp = 0; pp < 12; pp++) {
            float x = kvpr[pp*3], y = kvpr[pp*3+1], z = kvpr[pp*3+2];
            float rx = R0*x + R1*y + R2*z + t0;
            float ry = R3*x + R4*y + R5*z + t1;
            float rz = R6*x + R7*y + R8*z + t2;
            if (pp < 4) {
                kpp[pp*3+0] = rx; kpp[pp*3+1] = ry; kpp[pp*3+2] = rz;
            } else {
                vp[16 + (pp-4)*3 + 0] = rx;
                vp[16 + (pp-4)*3 + 1] = ry;
                vp[16 + (pp-4)*3 + 2] = rz;
            }
        }
    } else if (idx < NN * HDS + NN * 48) {
        int e = idx - NN * HDS;
        int j = e / 48, pt = e % 48;
        float* pv = proj + (size_t)j * LDP + OFF_QP + pt * 3;
        const float* R = rot + j * 9;
        const float* t = trans + j * 3;
        float x = pv[0], y = pv[1], z = pv[2];
        pv[0] = R[0]*x + R[1]*y + R[2]*z + t[0];
        pv[1] = R[3]*x + R[4]*y + R[5]*z + t[1];
        pv[2] = R[6]*x + R[7]*y + R[8]*z + t[2];
    }
}

// ---------------------------------------------------------------------------
// bias planes: att[h][i][j] = (p[i,j,:]·w_b[:,h] + b_b[h]) * sqrt(1/3)
// ---------------------------------------------------------------------------
__global__ void bias_kernel(const float* __restrict__ p,
                            const float* __restrict__ w_b,
                            const float* __restrict__ b_b,
                            float* __restrict__ att)
{
    __shared__ float wbt[HDS][CP];
    __shared__ float bbs[HDS];
    const int tid = threadIdx.x;
    #pragma unroll
    for (int k = 0; k < 6; k++) {
        int e = tid + k * 256;
        int h = e / CP, c = e % CP;
        wbt[h][c] = w_b[c * HDS + h];
    }
    if (tid < HDS) bbs[tid] = b_b[tid];
    __syncthreads();

    const int gw = blockIdx.x * 8 + (tid >> 5);
    const int lane = tid & 31;
    const int i = gw >> 4;
    const int j = ((gw & 15) << 5) + lane;

    float acc[HDS];
    #pragma unroll
    for (int h = 0; h < HDS; h++) acc[h] = 0.f;

    const float4* prow = (const float4*)(p + ((size_t)i * NN + j) * CP);
    #pragma unroll 4
    for (int c4 = 0; c4 < 32; c4++) {
        float4 pv = prow[c4];
        #pragma unroll
        for (int h = 0; h < HDS; h++) {
            float4 wv = ((const float4*)&wbt[h][0])[c4];
            acc[h] = fmaf(pv.x, wv.x,
                     fmaf(pv.y, wv.y,
                     fmaf(pv.z, wv.z,
                     fmaf(pv.w, wv.w, acc[h]))));
        }
    }
    #pragma unroll
    for (int h = 0; h < HDS; h++)
        att[((size_t)(h * NN) + i) * NN + j] = (acc[h] + bbs[h]) * SB;
}

// ---------------------------------------------------------------------------
// Fused logits + softmax.  Block = (i-tile of 8, head h).  256 threads.
// ---------------------------------------------------------------------------
__global__ void logits_softmax_kernel(const float* __restrict__ proj,
                                      const float* __restrict__ kpack,
                                      const float* __restrict__ kppack,
                                      const float* __restrict__ mask,
                                      const float* __restrict__ head_w,
                                      float* __restrict__ att)
{
    const int i0 = blockIdx.x * 8, h = blockIdx.y;
    const int tid = threadIdx.x;

    __shared__ float att_s[8][NN];
    __shared__ float kt[64][20];
    __shared__ float kpt[64][13];
    __shared__ float q_s[8][17];
    __shared__ float qp_s[8][13];
    __shared__ float m_i[8];
    __shared__ float sh_hw;

    if (tid < 128) {
        int il = tid >> 4, c = tid & 15;
        q_s[il][c] = proj[(size_t)(i0 + il) * LDP + OFF_Q + h * 16 + c];
    } else if (tid < 224) {
        int e = tid - 128;
        int il = e / 12, c = e % 12;
        qp_s[il][c] = proj[(size_t)(i0 + il) * LDP + OFF_QP + h * 12 + c];
    } else if (tid < 232) {
        m_i[tid - 224] = mask[i0 + (tid - 224)];
    } else if (tid == 232) {
        float w = head_w[h];
        float sp = fmaxf(w, 0.f) + log1pf(expf(-fabsf(w)));
        sh_hw = sp * SHW;
    }

    const float* kb  = kpack  + (size_t)(h * NN) * 16;
    const float* kpb = kppack + (size_t)(h * NN) * 12;

    const int jl = tid >> 2, ig = tid & 3;

    for (int j0 = 0; j0 < NN; j0 += 64) {
        #pragma unroll
        for (int k = 0; k < 4; k++) {
            int e = tid + k * 256;
            int r = e >> 4, c = e & 15;
            kt[r][c] = kb[(size_t)(j0 + r) * 16 + c];
        }
        #pragma unroll
        for (int k = 0; k < 3; k++) {
            int e = tid + k * 256;
            if (e < 768) {
                int r = e / 12, c = e % 12;
                kpt[r][c] = kpb[(size_t)(j0 + r) * 12 + c];
            }
        }
        __syncthreads();

        float mj = mask[j0 + jl];
        float hw = sh_hw;
        #pragma unroll
        for (int ii = 0; ii < 2; ii++) {
            int il = ig * 2 + ii;
            float qk = 0.f;
            #pragma unroll
            for (int c = 0; c < 16; c++) qk = fmaf(q_s[il][c], kt[jl][c], qk);
            float d2 = 0.f;
            #pragma unroll
            for (int d = 0; d < 12; d++) {
                float dd = qp_s[il][d] - kpt[jl][d];
                d2 = fmaf(dd, dd, d2);
            }
            float bias = att[((size_t)(h * NN) + i0 + il) * NN + j0 + jl];
            att_s[il][j0 + jl] = qk * SQK + bias - 0.5f * hw * d2
                               + (m_i[il] * mj - 1.0f) * 100000.0f;
        }
        __syncthreads();
    }

    const int w = tid >> 5, lane = tid & 31;
    float vals[16];
    float vmax = -1e30f;
    #pragma unroll
    for (int k = 0; k < 16; k++) {
        vals[k] = att_s[w][lane + 32 * k];
        vmax = fmaxf(vmax, vals[k]);
    }
    #pragma unroll
    for (int o = 16; o > 0; o >>= 1)
        vmax = fmaxf(vmax, __shfl_xor_sync(0xffffffffu, vmax, o));
    float sum = 0.f;
    #pragma unroll
    for (int k = 0; k < 16; k++) { vals[k] = expf(vals[k] - vmax); sum += vals[k]; }
    #pragma unroll
    for (int o = 16; o > 0; o >>= 1)
        sum += __shfl_xor_sync(0xffffffffu, sum, o);
    float inv = 1.0f / sum;
    float* arow = att + ((size_t)(h * NN) + i0 + w) * NN;
    #pragma unroll
    for (int k = 0; k < 16; k++)
        arow[lane + 32 * k] = vals[k] * inv;
}

// ---------------------------------------------------------------------------
// o_pair[i,h,c] = sum_j a[h,i,j]*p[i,j,c]  -> cat[i][576 + h*128 + c]
// ---------------------------------------------------------------------------
__global__ void opair_kernel(const float* __restrict__ att,
                             const float* __restrict__ p,
                             float* __restrict__ cat)
{
    const int i = blockIdx.x;
    __shared__ float as[HDS][NN];
    __shared__ float ps[32][128];
    const int tid = threadIdx.x;     // 192

    for (int idx = tid; idx < HDS * NN; idx += 192) {
        int h = idx >> 9, j = idx & 511;
        as[h][j] = att[((size_t)(h * NN + i)) * NN + j];
    }

    const int c4 = tid & 31;
    const int hh = tid >> 5;
    float acc0[4] = {0,0,0,0}, acc1[4] = {0,0,0,0};
    const float* pi = p + (size_t)i * NN * CP;

    for (int j0 = 0; j0 < NN; j0 += 32) {
        for (int idx = tid; idx < 32 * 32; idx += 192) {
            int jj = idx >> 5, cc = idx & 31;
            ((float4*)&ps[jj][0])[cc] =
                ((const float4*)(pi + (size_t)(j0 + jj) * CP))[cc];
        }
        __syncthreads();
        #pragma unroll 8
        for (int jj = 0; jj < 32; jj++) {
            float a0 = as[2 * hh][j0 + jj];
            float a1 = as[2 * hh + 1][j0 + jj];
            float4 pv = ((const float4*)&ps[jj][0])[c4];
            acc0[0] += a0 * pv.x; acc0[1] += a0 * pv.y;
            acc0[2] += a0 * pv.z; acc0[3] += a0 * pv.w;
            acc1[0] += a1 * pv.x; acc1[1] += a1 * pv.y;
            acc1[2] += a1 * pv.z; acc1[3] += a1 * pv.w;
        }
        __syncthreads();
    }
    float* dst = cat + (size_t)i * 2112 + 576;
    #pragma unroll
    for (int d = 0; d < 4; d++) {
        dst[(2 * hh) * 128 + c4 * 4 + d]     = acc0[d];
        dst[(2 * hh + 1) * 128 + c4 * 4 + d] = acc1[d];
    }
}

// ---------------------------------------------------------------------------
// Epilogue: copy o, rotate op back, norms.
// ---------------------------------------------------------------------------
__global__ void postproc_kernel(const float* __restrict__ ov,
                                const float* __restrict__ rot,
                                const float* __restrict__ trans,
                                float* __restrict__ cat)
{
    const int i = blockIdx.x;
    const int tid = threadIdx.x;   // 192
    float* ci = cat + (size_t)i * 2112;
    {
        int h = tid >> 4, c = tid & 15;
        ci[tid] = ov[((size_t)(h * NN) + i) * 40 + c];
    }
    if (tid < 96) {
        int h = tid >> 3, pp = tid & 7;
        const float* base = ov + ((size_t)(h * NN) + i) * 40 + 16 + pp * 3;
        float vx = base[0] - trans[i*3+0];
        float vy = base[1] - trans[i*3+1];
        float vz = base[2] - trans[i*3+2];
        const float* R = rot + i * 9;
        float ox = R[0]*vx + R[3]*vy + R[6]*vz;
        float oy = R[1]*vx + R[4]*vy + R[7]*vz;
        float oz = R[2]*vx + R[5]*vy + R[8]*vz;
        ci[192 + h*24 + pp*3 + 0] = ox;
        ci[192 + h*24 + pp*3 + 1] = oy;
        ci[192 + h*24 + pp*3 + 2] = oz;
        ci[480 + h*8 + pp] = sqrtf(ox*ox + oy*oy + oz*oz + 1e-8f);
    }
}

// ---------------------------------------------------------------------------
// 3-way split-K reduce + bias + optional relu (elementwise).
// ---------------------------------------------------------------------------
__global__ void reduce_act_kernel(const float* __restrict__ part,
                                  const float* __restrict__ bias,
                                  float* __restrict__ y, int relu)
{
    int idx = blockIdx.x * blockDim.x + threadIdx.x;
    const size_t SP = (size_t)NN * CS;
    int c = idx % CS;
    float v = part[idx] + part[SP + idx] + part[2*SP + idx] + bias[c];
    y[idx] = relu ? fmaxf(v, 0.f) : v;
}

// ---------------------------------------------------------------------------
// 3-way split-K reduce + bias + residual + LayerNorm.  Block/row, 128 thr.
// ---------------------------------------------------------------------------
__global__ void reduce_ln_kernel(const float* __restrict__ part,
                                 const float* __restrict__ bias,
                                 const float* __restrict__ res,
                                 const float* __restrict__ g,
                                 const float* __restrict__ b,
                                 float* __restrict__ y)
{
    __shared__ float rs[128], rs2[128];
    const int i = blockIdx.x, tid = threadIdx.x;
    const size_t SP = (size_t)NN * CS;
    float v[3];
    float sm = 0.f, sm2 = 0.f;
    #pragma unroll
    for (int k = 0; k < 3; k++) {
        int c = tid + k * 128;
        size_t o = (size_t)i * CS + c;
        float x = part[o] + part[SP + o] + part[2*SP + o] + bias[c] + res[o];
        v[k] = x;
        sm += x; sm2 += x * x;
    }
    rs[tid] = sm; rs2[tid] = sm2;
    __syncthreads();
    for (int st = 64; st > 0; st >>= 1) {
        if (tid < st) { rs[tid] += rs[tid + st]; rs2[tid] += rs2[tid + st]; }
        __syncthreads();
    }
    float mean = rs[0] * (1.0f / CS);
    float var  = rs2[0] * (1.0f / CS) - mean * mean;
    float inv  = rsqrtf(var + 1e-5f);
    #pragma unroll
    for (int k = 0; k < 3; k++) {
        int c = tid + k * 128;
        y[(size_t)i * CS + c] = (v[k] - mean) * inv * g[c] + b[c];
    }
}

// ---------------------------------------------------------------------------
// Fused backbone projection + quaternion frame update.
// ---------------------------------------------------------------------------
__global__ void bb_finalize_kernel(const float* __restrict__ s2,
                                   const float* __restrict__ bb_w,
                                   const float* __restrict__ bb_b,
                                   const float* __restrict__ rot,
                                   const float* __restrict__ trans,
                                   float* __restrict__ out)
{
    const int i = blockIdx.x;
    const int tid = threadIdx.x;
    const int w = tid >> 5, lane = tid & 31;
    __shared__ float u[6];
    const float* row = s2 + (size_t)i * CS;
    float sum = 0.f;
    for (int c = lane; c < CS; c += 32)
        sum = fmaf(row[c], bb_w[c * 6 + w], sum);
    #pragma unroll
    for (int o = 16; o > 0; o >>= 1)
        sum += __shfl_xor_sync(0xffffffffu, sum, o);
    if (lane == 0) u[w] = sum + bb_b[w];
    __syncthreads();
    if (tid == 0) {
        float bx = u[0], by = u[1], bz = u[2];
        float inv = rsqrtf(1.f + bx*bx + by*by + bz*bz);
        float qw = inv, x = bx * inv, y = by * inv, z = bz * inv;
        float Ru[9] = {
            1 - 2*(y*y + z*z), 2*(x*y - qw*z),    2*(x*z + qw*y),
            2*(x*y + qw*z),    1 - 2*(x*x + z*z), 2*(y*z - qw*x),
            2*(x*z - qw*y),    2*(y*z + qw*x),    1 - 2*(x*x + y*y)};
        const float* R = rot + i * 9;
        float* ro = out + NN * CS + i * 9;
        #pragma unroll
        for (int r = 0; r < 3; r++)
            #pragma unroll
            for (int c = 0; c < 3; c++)
                ro[r*3+c] = R[r*3+0]*Ru[0*3+c] + R[r*3+1]*Ru[1*3+c]
                          + R[r*3+2]*Ru[2*3+c];
        float tx = u[3], ty = u[4], tz = u[5];
        float* to = out + NN * CS + NN * 9 + i * 3;
        #pragma unroll
        for (int r = 0; r < 3; r++)
            to[r] = R[r*3+0]*tx + R[r*3+1]*ty + R[r*3+2]*tz + trans[i*3+r];
    }
}

// ---------------------------------------------------------------------------
static cudaStream_t g_s1 = nullptr;
static cudaEvent_t  g_ev0, g_ev1, g_ev2, g_ev3;

extern "C" void kernel_launch(void* const* d_in, const int* in_sizes, int n_in,
                              void* d_out, int out_size)
{
    if (!g_s1) {
        cudaStreamCreateWithFlags(&g_s1, cudaStreamNonBlocking);
        cudaEventCreateWithFlags(&g_ev0, cudaEventDisableTiming);
        cudaEventCreateWithFlags(&g_ev1, cudaEventDisableTiming);
        cudaEventCreateWithFlags(&g_ev2, cudaEventDisableTiming);
        cudaEventCreateWithFlags(&g_ev3, cudaEventDisableTiming);
    }

    const float* s      = (const float*)d_in[0];
    const float* p      = (const float*)d_in[1];
    const float* rot    = (const float*)d_in[2];
    const float* trans  = (const float*)d_in[3];
    const float* mask   = (const float*)d_in[4];
    const float* w_q    = (const float*)d_in[5];
    const float* b_q    = (const float*)d_in[6];
    const float* w_kv   = (const float*)d_in[7];
    const float* b_kv   = (const float*)d_in[8];
    const float* w_qp   = (const float*)d_in[9];
    const float* b_qp   = (const float*)d_in[10];
    const float* w_kvp  = (const float*)d_in[11];
    const float* b_kvp  = (const float*)d_in[12];
    const float* w_b    = (const float*)d_in[13];
    const float* b_b    = (const float*)d_in[14];
    const float* head_w = (const float*)d_in[15];
    const float* w_o    = (const float*)d_in[16];
    const float* b_o    = (const float*)d_in[17];
    const float* ln1_g  = (const float*)d_in[18];
    const float* ln1_b  = (const float*)d_in[19];
    const float* tw1    = (const float*)d_in[20];
    const float* tb1    = (const float*)d_in[21];
    const float* tw2    = (const float*)d_in[22];
    const float* tb2    = (const float*)d_in[23];
    const float* tw3    = (const float*)d_in[24];
    const float* tb3    = (const float*)d_in[25];
    const float* ln2_g  = (const float*)d_in[26];
    const float* ln2_b  = (const float*)d_in[27];
    const float* bb_w   = (const float*)d_in[28];
    const float* bb_b   = (const float*)d_in[29];
    float* out = (float*)d_out;

    float *wcat, *bcat, *proj, *kpk, *kppk, *vpk, *a_, *ov_, *cat_,
          *part, *x2, *x3, *x1;
    cudaGetSymbolAddress((void**)&wcat, g_wcat);
    cudaGetSymbolAddress((void**)&bcat, g_bcat);
    cudaGetSymbolAddress((void**)&proj, g_proj);
    cudaGetSymbolAddress((void**)&kpk,  g_kpack);
    cudaGetSymbolAddress((void**)&kppk, g_kppack);
    cudaGetSymbolAddress((void**)&vpk,  g_vpack);
    cudaGetSymbolAddress((void**)&a_,   g_att);
    cudaGetSymbolAddress((void**)&ov_,  g_ov);
    cudaGetSymbolAddress((void**)&cat_, g_cat);
    cudaGetSymbolAddress((void**)&part, g_part);
    cudaGetSymbolAddress((void**)&x2,   g_x2);
    cudaGetSymbolAddress((void**)&x3,   g_x3);
    cudaGetSymbolAddress((void**)&x1,   g_x1);

    // ---- fork: bias planes on side stream (independent of proj chain) -----
    cudaEventRecord(g_ev0, 0);
    cudaStreamWaitEvent(g_s1, g_ev0, 0);
    bias_kernel<<<1024, 256, 0, g_s1>>>(p, w_b, b_b, a_);
    cudaEventRecord(g_ev1, g_s1);

    // ---- main stream: projections ------------------------------------------
    pack_w_kernel<<<(CS * LDP + LDP + 255) / 256, 256>>>(
        w_q, b_q, w_kv, b_kv, w_qp, b_qp, w_kvp, b_kvp, wcat, bcat);
    gemm64_kernel<<<dim3(LDP / 64, 8, 1), 128>>>(s, CS, 0, wcat, LDP, 0,
                                                 bcat, proj, LDP, 0, CS);
    rotpack_kernel<<<(NN * HDS + NN * 48 + 255) / 256, 256>>>(
        proj, rot, trans, kpk, kppk, vpk);

    // join bias, then fused logits+softmax
    cudaStreamWaitEvent(0, g_ev1, 0);
    logits_softmax_kernel<<<dim3(64, HDS), 256>>>(proj, kpk, kppk, mask,
                                                  head_w, a_);

    // ---- fork: o_pair on side stream; ov gemm + postproc on main ----------
    cudaEventRecord(g_ev2, 0);
    cudaStreamWaitEvent(g_s1, g_ev2, 0);
    opair_kernel<<<NN, 192, 0, g_s1>>>(a_, p, cat_);
    cudaEventRecord(g_ev3, g_s1);

    sgemm_kernel<<<dim3(1, 8, HDS), 256>>>(a_, NN, (long long)NN * NN,
                                           vpk, 40, (long long)NN * 40,
                                           ov_, 40, (long long)NN * 40,
                                           NN, 40, NN);
    postproc_kernel<<<NN, 192>>>(ov_, rot, trans, cat_);
    cudaStreamWaitEvent(0, g_ev3, 0);

    // ---- output projection (split-K 3) + fused reduce/residual/LN1 --------
    gemm64_kernel<<<dim3(6, 8, 3), 128>>>(cat_, 2112, 704,
                                          w_o, CS, (long long)704 * CS,
                                          nullptr, part, CS, (long long)NN * CS,
                                          704);
    reduce_ln_kernel<<<NN, 128>>>(part, b_o, s, ln1_g, ln1_b, x2);

    // ---- transition MLP (each GEMM split-K 3) ------------------------------
    gemm64_kernel<<<dim3(6, 8, 3), 128>>>(x2, CS, 128,
                                          tw1, CS, (long long)128 * CS,
                                          nullptr, part, CS, (long long)NN * CS,
                                          128);
    reduce_act_kernel<<<(NN * CS) / 256, 256>>>(part, tb1, x3, 1);
    gemm64_kernel<<<dim3(6, 8, 3), 128>>>(x3, CS, 128,
                                          tw2, CS, (long long)128 * CS,
                                          nullptr, part, CS, (long long)NN * CS,
                                          128);
    reduce_act_kernel<<<(NN * CS) / 256, 256>>>(part, tb2, x1, 1);
    gemm64_kernel<<<dim3(6, 8, 3), 128>>>(x1, CS, 128,
                                          tw3, CS, (long long)128 * CS,
                                          nullptr, part, CS, (long long)NN * CS,
                                          128);
    reduce_ln_kernel<<<NN, 128>>>(part, tb3, x2, ln2_g, ln2_b, out);

    // ---- backbone update ----------------------------------------------------
    bb_finalize_kernel<<<NN, 192>>>(out, bb_w, bb_b, rot, trans, out);
}

// round 6
// speedup vs baseline: 3.3061x; 1.0738x over previous
#include <cuda_runtime.h>
#include <math.h>

// ---------------------------------------------------------------------------
// StructureLayer (IPA) — B=1, N=512, H=12, C_S=384, C_P=128, C_H=16,
// P_QK=4, P_V=8.  Output: [ s2 (512*384) | rot_new (512*9) | trans_new (512*3) ]
// ---------------------------------------------------------------------------

#define NN 512
#define CS 384
#define CP 128
#define HDS 12

// proj row layout: [ q(192) | kv(384) | qp(144) | kvp(432) ]  = 1152
#define LDP 1152
#define OFF_Q   0
#define OFF_KV  192
#define OFF_QP  576
#define OFF_KVP 720

#define SQK 0.14433756729740643f    // sqrt(1/48)
#define SB  0.5773502691896258f     // sqrt(1/3)
#define SHW 0.13608276348795434f    // sqrt(1/54)

// ---- scratch (device globals) ----------------------------------------------
__device__ float g_wcat[CS * LDP];
__device__ float g_bcat[LDP];
__device__ float g_proj[NN * LDP];
__device__ float g_kpack[HDS * NN * 16];
__device__ float g_kppack[HDS * NN * 12];
__device__ float g_vpack[HDS * NN * 64];  // [h][j][ v(16) | vp(24) | pad(24)=0 ]
__device__ float g_att[HDS * NN * NN];    // bias planes, then probs [h][i][j]
__device__ float g_ov[HDS * NN * 64];     // [h][i][ o(16) | op_raw(24) | pad ]
__device__ float g_cat[NN * 2112];
__device__ float g_part[3 * NN * CS];     // split-K partials
__device__ float g_x2[NN * CS];
__device__ float g_x3[NN * CS];
__device__ float g_x1[NN * CS];

// ---------------------------------------------------------------------------
// Pack projection weights/biases into one (384 x 1152) matrix. float4 copies.
// ---------------------------------------------------------------------------
__global__ void pack_w_kernel(const float* __restrict__ w_q,  const float* __restrict__ b_q,
                              const float* __restrict__ w_kv, const float* __restrict__ b_kv,
                              const float* __restrict__ w_qp, const float* __restrict__ b_qp,
                              const float* __restrict__ w_kvp,const float* __restrict__ b_kvp,
                              float* __restrict__ wcat, float* __restrict__ bcat)
{
    const int NW4 = CS * LDP / 4;              // 110592 float4s
    int idx = blockIdx.x * blockDim.x + threadIdx.x;
    if (idx < NW4) {
        int r = idx / (LDP / 4), c = (idx % (LDP / 4)) * 4;
        float4 v;
        if      (c < 192) v = *(const float4*)(w_q  + r * 192 + c);
        else if (c < 576) v = *(const float4*)(w_kv + r * 384 + (c - 192));
        else if (c < 720) v = *(const float4*)(w_qp + r * 144 + (c - 576));
        else              v = *(const float4*)(w_kvp + r * 432 + (c - 720));
        *(float4*)(wcat + r * LDP + c) = v;
    } else if (idx < NW4 + LDP / 4) {
        int c = (idx - NW4) * 4;
        float4 v;
        if      (c < 192) v = *(const float4*)(b_q  + c);
        else if (c < 576) v = *(const float4*)(b_kv + (c - 192));
        else if (c < 720) v = *(const float4*)(b_qp + (c - 576));
        else              v = *(const float4*)(b_kvp + (c - 720));
        *(float4*)(bcat + c) = v;
    }
}

// ---------------------------------------------------------------------------
// Fast SGEMM: 64x64 tile, 128 threads, 8x4 per thread, double-buffered smem.
// Requires: M,N multiples of 64; K multiple of 16; float4-aligned pointers.
// grid = (N/64, M/64, z).
// ---------------------------------------------------------------------------
__global__ void __launch_bounds__(128)
gemm64_kernel(const float* __restrict__ A, int lda, long long sA,
              const float* __restrict__ B, int ldb, long long sB,
              const float* __restrict__ bias,
              float* __restrict__ C, int ldc, long long sC,
              int K)
{
    A += (size_t)blockIdx.z * (size_t)sA;
    B += (size_t)blockIdx.z * (size_t)sB;
    C += (size_t)blockIdx.z * (size_t)sC;

    __shared__ __align__(16) float As[2][16][68];
    __shared__ __align__(16) float Bs[2][16][64];

    const int bm = blockIdx.y * 64, bn = blockIdx.x * 64;
    const int tid = threadIdx.x;
    const int tx = tid & 15, ty = tid >> 4;
    const int m0 = ty * 8, n0 = tx * 4;

    const int ar = tid >> 2, ak = (tid & 3) * 4;
    const int br = tid >> 4, bc = (tid & 15) * 4;

    const float* Ab = A + (size_t)bm * lda;

    float4 ra0, ra1, rb0, rb1;
    ra0 = *(const float4*)(Ab + (size_t)ar * lda + ak);
    ra1 = *(const float4*)(Ab + (size_t)(ar + 32) * lda + ak);
    rb0 = *(const float4*)(B + (size_t)br * ldb + bn + bc);
    rb1 = *(const float4*)(B + (size_t)(br + 8) * ldb + bn + bc);
    As[0][ak+0][ar] = ra0.x; As[0][ak+1][ar] = ra0.y;
    As[0][ak+2][ar] = ra0.z; As[0][ak+3][ar] = ra0.w;
    As[0][ak+0][ar+32] = ra1.x; As[0][ak+1][ar+32] = ra1.y;
    As[0][ak+2][ar+32] = ra1.z; As[0][ak+3][ar+32] = ra1.w;
    *(float4*)&Bs[0][br][bc]     = rb0;
    *(float4*)&Bs[0][br + 8][bc] = rb1;
    __syncthreads();

    float acc[8][4];
    #pragma unroll
    for (int i = 0; i < 8; i++)
        #pragma unroll
        for (int j = 0; j < 4; j++) acc[i][j] = 0.f;

    int buf = 0;
    for (int k0 = 0; k0 < K; k0 += 16) {
        const bool more = (k0 + 16) < K;
        if (more) {
            ra0 = *(const float4*)(Ab + (size_t)ar * lda + k0 + 16 + ak);
            ra1 = *(const float4*)(Ab + (size_t)(ar + 32) * lda + k0 + 16 + ak);
            rb0 = *(const float4*)(B + (size_t)(k0 + 16 + br) * ldb + bn + bc);
            rb1 = *(const float4*)(B + (size_t)(k0 + 16 + br + 8) * ldb + bn + bc);
        }
        #pragma unroll
        for (int kk = 0; kk < 16; kk++) {
            float4 a0 = *(const float4*)&As[buf][kk][m0];
            float4 a1 = *(const float4*)&As[buf][kk][m0 + 4];
            float4 b  = *(const float4*)&Bs[buf][kk][n0];
            float am[8] = {a0.x, a0.y, a0.z, a0.w, a1.x, a1.y, a1.z, a1.w};
            #pragma unroll
            for (int i = 0; i < 8; i++) {
                acc[i][0] = fmaf(am[i], b.x, acc[i][0]);
                acc[i][1] = fmaf(am[i], b.y, acc[i][1]);
                acc[i][2] = fmaf(am[i], b.z, acc[i][2]);
                acc[i][3] = fmaf(am[i], b.w, acc[i][3]);
            }
        }
        if (more) {
            buf ^= 1;
            __syncthreads();
            As[buf][ak+0][ar] = ra0.x; As[buf][ak+1][ar] = ra0.y;
            As[buf][ak+2][ar] = ra0.z; As[buf][ak+3][ar] = ra0.w;
            As[buf][ak+0][ar+32] = ra1.x; As[buf][ak+1][ar+32] = ra1.y;
            As[buf][ak+2][ar+32] = ra1.z; As[buf][ak+3][ar+32] = ra1.w;
            *(float4*)&Bs[buf][br][bc]     = rb0;
            *(float4*)&Bs[buf][br + 8][bc] = rb1;
            __syncthreads();
        }
    }

    #pragma unroll
    for (int i = 0; i < 8; i++) {
        float4 o = make_float4(acc[i][0], acc[i][1], acc[i][2], acc[i][3]);
        if (bias) {
            o.x += bias[bn + n0 + 0];
            o.y += bias[bn + n0 + 1];
            o.z += bias[bn + n0 + 2];
            o.w += bias[bn + n0 + 3];
        }
        *(float4*)(C + (size_t)(bm + m0 + i) * ldc + bn + n0) = o;
    }
}

// ---------------------------------------------------------------------------
// Coalesced rotate + repack.  Output-indexed copies, triple-indexed rotations.
//   seg1: kpack[h][j][c]   <- proj kv  (copy)            HDS*NN*16 threads
//   seg2: vpack[h][j][c]   <- proj kv+16 (copy)          HDS*NN*16 threads
//   seg3: kppack triples   <- rotate proj kvp[0..3]      HDS*NN*4 threads
//   seg4: vpack vp triples <- rotate proj kvp[4..11]     HDS*NN*8 threads
//   seg5: qp triples       <- rotate in place            NN*48 threads
// ---------------------------------------------------------------------------
__global__ void rotpack_kernel(float* __restrict__ proj,
                               const float* __restrict__ rot,
                               const float* __restrict__ trans,
                               float* __restrict__ kpack,
                               float* __restrict__ kppack,
                               float* __restrict__ vpack)
{
    const int S1 = HDS * NN * 16;
    const int S2 = S1 + HDS * NN * 16;
    const int S3 = S2 + HDS * NN * 4;
    const int S4 = S3 + HDS * NN * 8;
    const int S5 = S4 + NN * 48;
    int idx = blockIdx.x * blockDim.x + threadIdx.x;

    if (idx < S1) {
        int c = idx & 15, j = (idx >> 4) & 511, h = idx >> 13;
        kpack[idx] = proj[(size_t)j * LDP + OFF_KV + h * 32 + c];
    } else if (idx < S2) {
        int t = idx - S1;
        int c = t & 15, j = (t >> 4) & 511, h = t >> 13;
        vpack[(((size_t)h * NN) + j) * 64 + c] =
            proj[(size_t)j * LDP + OFF_KV + h * 32 + 16 + c];
    } else if (idx < S3) {
        int t = idx - S2;
        int pp = t & 3, j = (t >> 2) & 511, h = t >> 11;
        const float* src = proj + (size_t)j * LDP + OFF_KVP + h * 36 + pp * 3;
        const float* R = rot + j * 9;
        const float* tr = trans + j * 3;
        float x = src[0], y = src[1], z = src[2];
        float* dst = kppack + (((size_t)h * NN) + j) * 12 + pp * 3;
        dst[0] = R[0]*x + R[1]*y + R[2]*z + tr[0];
        dst[1] = R[3]*x + R[4]*y + R[5]*z + tr[1];
        dst[2] = R[6]*x + R[7]*y + R[8]*z + tr[2];
    } else if (idx < S4) {
        int t = idx - S3;
        int pp = t & 7, j = (t >> 3) & 511, h = t >> 12;
        const float* src = proj + (size_t)j * LDP + OFF_KVP + h * 36 + (4 + pp) * 3;
        const float* R = rot + j * 9;
        const float* tr = trans + j * 3;
        float x = src[0], y = src[1], z = src[2];
        float* dst = vpack + (((size_t)h * NN) + j) * 64 + 16 + pp * 3;
        dst[0] = R[0]*x + R[1]*y + R[2]*z + tr[0];
        dst[1] = R[3]*x + R[4]*y + R[5]*z + tr[1];
        dst[2] = R[6]*x + R[7]*y + R[8]*z + tr[2];
    } else if (idx < S5) {
        int t = idx - S4;
        int pt = t % 48, j = t / 48;
        float* pv = proj + (size_t)j * LDP + OFF_QP + pt * 3;
        const float* R = rot + j * 9;
        const float* tr = trans + j * 3;
        float x = pv[0], y = pv[1], z = pv[2];
        pv[0] = R[0]*x + R[1]*y + R[2]*z + tr[0];
        pv[1] = R[3]*x + R[4]*y + R[5]*z + tr[1];
        pv[2] = R[6]*x + R[7]*y + R[8]*z + tr[2];
    }
}

// ---------------------------------------------------------------------------
// bias planes: att[h][i][j] = (p[i,j,:]·w_b[:,h] + b_b[h]) * sqrt(1/3)
// ---------------------------------------------------------------------------
__global__ void bias_kernel(const float* __restrict__ p,
                            const float* __restrict__ w_b,
                            const float* __restrict__ b_b,
                            float* __restrict__ att)
{
    __shared__ float wbt[HDS][CP];
    __shared__ float bbs[HDS];
    const int tid = threadIdx.x;
    #pragma unroll
    for (int k = 0; k < 6; k++) {
        int e = tid + k * 256;
        int h = e / CP, c = e % CP;
        wbt[h][c] = w_b[c * HDS + h];
    }
    if (tid < HDS) bbs[tid] = b_b[tid];
    __syncthreads();

    const int gw = blockIdx.x * 8 + (tid >> 5);
    const int lane = tid & 31;
    const int i = gw >> 4;
    const int j = ((gw & 15) << 5) + lane;

    float acc[HDS];
    #pragma unroll
    for (int h = 0; h < HDS; h++) acc[h] = 0.f;

    const float4* prow = (const float4*)(p + ((size_t)i * NN + j) * CP);
    #pragma unroll 4
    for (int c4 = 0; c4 < 32; c4++) {
        float4 pv = prow[c4];
        #pragma unroll
        for (int h = 0; h < HDS; h++) {
            float4 wv = ((const float4*)&wbt[h][0])[c4];
            acc[h] = fmaf(pv.x, wv.x,
                     fmaf(pv.y, wv.y,
                     fmaf(pv.z, wv.z,
                     fmaf(pv.w, wv.w, acc[h]))));
        }
    }
    #pragma unroll
    for (int h = 0; h < HDS; h++)
        att[((size_t)(h * NN) + i) * NN + j] = (acc[h] + bbs[h]) * SB;
}

// ---------------------------------------------------------------------------
// Fused logits + softmax.  Block = (i-tile of 8, head h).  256 threads.
// ---------------------------------------------------------------------------
__global__ void logits_softmax_kernel(const float* __restrict__ proj,
                                      const float* __restrict__ kpack,
                                      const float* __restrict__ kppack,
                                      const float* __restrict__ mask,
                                      const float* __restrict__ head_w,
                                      float* __restrict__ att)
{
    const int i0 = blockIdx.x * 8, h = blockIdx.y;
    const int tid = threadIdx.x;

    __shared__ float att_s[8][NN];
    __shared__ float kt[64][20];
    __shared__ float kpt[64][13];
    __shared__ float q_s[8][17];
    __shared__ float qp_s[8][13];
    __shared__ float m_i[8];
    __shared__ float sh_hw;

    if (tid < 128) {
        int il = tid >> 4, c = tid & 15;
        q_s[il][c] = proj[(size_t)(i0 + il) * LDP + OFF_Q + h * 16 + c];
    } else if (tid < 224) {
        int e = tid - 128;
        int il = e / 12, c = e % 12;
        qp_s[il][c] = proj[(size_t)(i0 + il) * LDP + OFF_QP + h * 12 + c];
    } else if (tid < 232) {
        m_i[tid - 224] = mask[i0 + (tid - 224)];
    } else if (tid == 232) {
        float w = head_w[h];
        float sp = fmaxf(w, 0.f) + log1pf(expf(-fabsf(w)));
        sh_hw = sp * SHW;
    }

    const float* kb  = kpack  + (size_t)(h * NN) * 16;
    const float* kpb = kppack + (size_t)(h * NN) * 12;

    const int jl = tid >> 2, ig = tid & 3;

    for (int j0 = 0; j0 < NN; j0 += 64) {
        #pragma unroll
        for (int k = 0; k < 4; k++) {
            int e = tid + k * 256;
            int r = e >> 4, c = e & 15;
            kt[r][c] = kb[(size_t)(j0 + r) * 16 + c];
        }
        #pragma unroll
        for (int k = 0; k < 3; k++) {
            int e = tid + k * 256;
            if (e < 768) {
                int r = e / 12, c = e % 12;
                kpt[r][c] = kpb[(size_t)(j0 + r) * 12 + c];
            }
        }
        __syncthreads();

        float mj = mask[j0 + jl];
        float hw = sh_hw;
        #pragma unroll
        for (int ii = 0; ii < 2; ii++) {
            int il = ig * 2 + ii;
            float qk = 0.f;
            #pragma unroll
            for (int c = 0; c < 16; c++) qk = fmaf(q_s[il][c], kt[jl][c], qk);
            float d2 = 0.f;
            #pragma unroll
            for (int d = 0; d < 12; d++) {
                float dd = qp_s[il][d] - kpt[jl][d];
                d2 = fmaf(dd, dd, d2);
            }
            float bias = att[((size_t)(h * NN) + i0 + il) * NN + j0 + jl];
            att_s[il][j0 + jl] = qk * SQK + bias - 0.5f * hw * d2
                               + (m_i[il] * mj - 1.0f) * 100000.0f;
        }
        __syncthreads();
    }

    const int w = tid >> 5, lane = tid & 31;
    float vals[16];
    float vmax = -1e30f;
    #pragma unroll
    for (int k = 0; k < 16; k++) {
        vals[k] = att_s[w][lane + 32 * k];
        vmax = fmaxf(vmax, vals[k]);
    }
    #pragma unroll
    for (int o = 16; o > 0; o >>= 1)
        vmax = fmaxf(vmax, __shfl_xor_sync(0xffffffffu, vmax, o));
    float sum = 0.f;
    #pragma unroll
    for (int k = 0; k < 16; k++) { vals[k] = expf(vals[k] - vmax); sum += vals[k]; }
    #pragma unroll
    for (int o = 16; o > 0; o >>= 1)
        sum += __shfl_xor_sync(0xffffffffu, sum, o);
    float inv = 1.0f / sum;
    float* arow = att + ((size_t)(h * NN) + i0 + w) * NN;
    #pragma unroll
    for (int k = 0; k < 16; k++)
        arow[lane + 32 * k] = vals[k] * inv;
}

// ---------------------------------------------------------------------------
// o_pair[i,h,c] = sum_j a[h,i,j]*p[i,j,c]  -> cat[i][576 + h*128 + c]
// ---------------------------------------------------------------------------
__global__ void opair_kernel(const float* __restrict__ att,
                             const float* __restrict__ p,
                             float* __restrict__ cat)
{
    const int i = blockIdx.x;
    __shared__ float as[HDS][NN];
    __shared__ float ps[32][128];
    const int tid = threadIdx.x;     // 192

    for (int idx = tid; idx < HDS * NN; idx += 192) {
        int h = idx >> 9, j = idx & 511;
        as[h][j] = att[((size_t)(h * NN + i)) * NN + j];
    }

    const int c4 = tid & 31;
    const int hh = tid >> 5;
    float acc0[4] = {0,0,0,0}, acc1[4] = {0,0,0,0};
    const float* pi = p + (size_t)i * NN * CP;

    for (int j0 = 0; j0 < NN; j0 += 32) {
        for (int idx = tid; idx < 32 * 32; idx += 192) {
            int jj = idx >> 5, cc = idx & 31;
            ((float4*)&ps[jj][0])[cc] =
                ((const float4*)(pi + (size_t)(j0 + jj) * CP))[cc];
        }
        __syncthreads();
        #pragma unroll 8
        for (int jj = 0; jj < 32; jj++) {
            float a0 = as[2 * hh][j0 + jj];
            float a1 = as[2 * hh + 1][j0 + jj];
            float4 pv = ((const float4*)&ps[jj][0])[c4];
            acc0[0] += a0 * pv.x; acc0[1] += a0 * pv.y;
            acc0[2] += a0 * pv.z; acc0[3] += a0 * pv.w;
            acc1[0] += a1 * pv.x; acc1[1] += a1 * pv.y;
            acc1[2] += a1 * pv.z; acc1[3] += a1 * pv.w;
        }
        __syncthreads();
    }
    float* dst = cat + (size_t)i * 2112 + 576;
    #pragma unroll
    for (int d = 0; d < 4; d++) {
        dst[(2 * hh) * 128 + c4 * 4 + d]     = acc0[d];
        dst[(2 * hh + 1) * 128 + c4 * 4 + d] = acc1[d];
    }
}

// ---------------------------------------------------------------------------
// Epilogue: copy o, rotate op back, norms.  (ov stride = 64)
// ---------------------------------------------------------------------------
__global__ void postproc_kernel(const float* __restrict__ ov,
                                const float* __restrict__ rot,
                                const float* __restrict__ trans,
                                float* __restrict__ cat)
{
    const int i = blockIdx.x;
    const int tid = threadIdx.x;   // 192
    float* ci = cat + (size_t)i * 2112;
    {
        int h = tid >> 4, c = tid & 15;
        ci[tid] = ov[((size_t)(h * NN) + i) * 64 + c];
    }
    if (tid < 96) {
        int h = tid >> 3, pp = tid & 7;
        const float* base = ov + ((size_t)(h * NN) + i) * 64 + 16 + pp * 3;
        float vx = base[0] - trans[i*3+0];
        float vy = base[1] - trans[i*3+1];
        float vz = base[2] - trans[i*3+2];
        const float* R = rot + i * 9;
        float ox = R[0]*vx + R[3]*vy + R[6]*vz;
        float oy = R[1]*vx + R[4]*vy + R[7]*vz;
        float oz = R[2]*vx + R[5]*vy + R[8]*vz;
        ci[192 + h*24 + pp*3 + 0] = ox;
        ci[192 + h*24 + pp*3 + 1] = oy;
        ci[192 + h*24 + pp*3 + 2] = oz;
        ci[480 + h*8 + pp] = sqrtf(ox*ox + oy*oy + oz*oz + 1e-8f);
    }
}

// ---------------------------------------------------------------------------
// 3-way split-K reduce + bias + optional relu (elementwise).
// ---------------------------------------------------------------------------
__global__ void reduce_act_kernel(const float* __restrict__ part,
                                  const float* __restrict__ bias,
                                  float* __restrict__ y, int relu)
{
    int idx = blockIdx.x * blockDim.x + threadIdx.x;
    const size_t SP = (size_t)NN * CS;
    int c = idx % CS;
    float v = part[idx] + part[SP + idx] + part[2*SP + idx] + bias[c];
    y[idx] = relu ? fmaxf(v, 0.f) : v;
}

// ---------------------------------------------------------------------------
// 3-way split-K reduce + bias + residual + LayerNorm.  Block/row, 128 thr.
// ---------------------------------------------------------------------------
__global__ void reduce_ln_kernel(const float* __restrict__ part,
                                 const float* __restrict__ bias,
                                 const float* __restrict__ res,
                                 const float* __restrict__ g,
                                 const float* __restrict__ b,
                                 float* __restrict__ y)
{
    __shared__ float rs[128], rs2[128];
    const int i = blockIdx.x, tid = threadIdx.x;
    const size_t SP = (size_t)NN * CS;
    float v[3];
    float sm = 0.f, sm2 = 0.f;
    #pragma unroll
    for (int k = 0; k < 3; k++) {
        int c = tid + k * 128;
        size_t o = (size_t)i * CS + c;
        float x = part[o] + part[SP + o] + part[2*SP + o] + bias[c] + res[o];
        v[k] = x;
        sm += x; sm2 += x * x;
    }
    rs[tid] = sm; rs2[tid] = sm2;
    __syncthreads();
    for (int st = 64; st > 0; st >>= 1) {
        if (tid < st) { rs[tid] += rs[tid + st]; rs2[tid] += rs2[tid + st]; }
        __syncthreads();
    }
    float mean = rs[0] * (1.0f / CS);
    float var  = rs2[0] * (1.0f / CS) - mean * mean;
    float inv  = rsqrtf(var + 1e-5f);
    #pragma unroll
    for (int k = 0; k < 3; k++) {
        int c = tid + k * 128;
        y[(size_t)i * CS + c] = (v[k] - mean) * inv * g[c] + b[c];
    }
}

// ---------------------------------------------------------------------------
// Fused backbone projection + quaternion frame update.
// ---------------------------------------------------------------------------
__global__ void bb_finalize_kernel(const float* __restrict__ s2,
                                   const float* __restrict__ bb_w,
                                   const float* __restrict__ bb_b,
                                   const float* __restrict__ rot,
                                   const float* __restrict__ trans,
                                   float* __restrict__ out)
{
    const int i = blockIdx.x;
    const int tid = threadIdx.x;
    const int w = tid >> 5, lane = tid & 31;
    __shared__ float u[6];
    const float* row = s2 + (size_t)i * CS;
    float sum = 0.f;
    for (int c = lane; c < CS; c += 32)
        sum = fmaf(row[c], bb_w[c * 6 + w], sum);
    #pragma unroll
    for (int o = 16; o > 0; o >>= 1)
        sum += __shfl_xor_sync(0xffffffffu, sum, o);
    if (lane == 0) u[w] = sum + bb_b[w];
    __syncthreads();
    if (tid == 0) {
        float bx = u[0], by = u[1], bz = u[2];
        float inv = rsqrtf(1.f + bx*bx + by*by + bz*bz);
        float qw = inv, x = bx * inv, y = by * inv, z = bz * inv;
        float Ru[9] = {
            1 - 2*(y*y + z*z), 2*(x*y - qw*z),    2*(x*z + qw*y),
            2*(x*y + qw*z),    1 - 2*(x*x + z*z), 2*(y*z - qw*x),
            2*(x*z - qw*y),    2*(y*z + qw*x),    1 - 2*(x*x + y*y)};
        const float* R = rot + i * 9;
        float* ro = out + NN * CS + i * 9;
        #pragma unroll
        for (int r = 0; r < 3; r++)
            #pragma unroll
            for (int c = 0; c < 3; c++)
                ro[r*3+c] = R[r*3+0]*Ru[0*3+c] + R[r*3+1]*Ru[1*3+c]
                          + R[r*3+2]*Ru[2*3+c];
        float tx = u[3], ty = u[4], tz = u[5];
        float* to = out + NN * CS + NN * 9 + i * 3;
        #pragma unroll
        for (int r = 0; r < 3; r++)
            to[r] = R[r*3+0]*tx + R[r*3+1]*ty + R[r*3+2]*tz + trans[i*3+r];
    }
}

// ---------------------------------------------------------------------------
static cudaStream_t g_s1 = nullptr;
static cudaEvent_t  g_ev0, g_ev1, g_ev2, g_ev3;

extern "C" void kernel_launch(void* const* d_in, const int* in_sizes, int n_in,
                              void* d_out, int out_size)
{
    if (!g_s1) {
        cudaStreamCreateWithFlags(&g_s1, cudaStreamNonBlocking);
        cudaEventCreateWithFlags(&g_ev0, cudaEventDisableTiming);
        cudaEventCreateWithFlags(&g_ev1, cudaEventDisableTiming);
        cudaEventCreateWithFlags(&g_ev2, cudaEventDisableTiming);
        cudaEventCreateWithFlags(&g_ev3, cudaEventDisableTiming);
    }

    const float* s      = (const float*)d_in[0];
    const float* p      = (const float*)d_in[1];
    const float* rot    = (const float*)d_in[2];
    const float* trans  = (const float*)d_in[3];
    const float* mask   = (const float*)d_in[4];
    const float* w_q    = (const float*)d_in[5];
    const float* b_q    = (const float*)d_in[6];
    const float* w_kv   = (const float*)d_in[7];
    const float* b_kv   = (const float*)d_in[8];
    const float* w_qp   = (const float*)d_in[9];
    const float* b_qp   = (const float*)d_in[10];
    const float* w_kvp  = (const float*)d_in[11];
    const float* b_kvp  = (const float*)d_in[12];
    const float* w_b    = (const float*)d_in[13];
    const float* b_b    = (const float*)d_in[14];
    const float* head_w = (const float*)d_in[15];
    const float* w_o    = (const float*)d_in[16];
    const float* b_o    = (const float*)d_in[17];
    const float* ln1_g  = (const float*)d_in[18];
    const float* ln1_b  = (const float*)d_in[19];
    const float* tw1    = (const float*)d_in[20];
    const float* tb1    = (const float*)d_in[21];
    const float* tw2    = (const float*)d_in[22];
    const float* tb2    = (const float*)d_in[23];
    const float* tw3    = (const float*)d_in[24];
    const float* tb3    = (const float*)d_in[25];
    const float* ln2_g  = (const float*)d_in[26];
    const float* ln2_b  = (const float*)d_in[27];
    const float* bb_w   = (const float*)d_in[28];
    const float* bb_b   = (const float*)d_in[29];
    float* out = (float*)d_out;

    float *wcat, *bcat, *proj, *kpk, *kppk, *vpk, *a_, *ov_, *cat_,
          *part, *x2, *x3, *x1;
    cudaGetSymbolAddress((void**)&wcat, g_wcat);
    cudaGetSymbolAddress((void**)&bcat, g_bcat);
    cudaGetSymbolAddress((void**)&proj, g_proj);
    cudaGetSymbolAddress((void**)&kpk,  g_kpack);
    cudaGetSymbolAddress((void**)&kppk, g_kppack);
    cudaGetSymbolAddress((void**)&vpk,  g_vpack);
    cudaGetSymbolAddress((void**)&a_,   g_att);
    cudaGetSymbolAddress((void**)&ov_,  g_ov);
    cudaGetSymbolAddress((void**)&cat_, g_cat);
    cudaGetSymbolAddress((void**)&part, g_part);
    cudaGetSymbolAddress((void**)&x2,   g_x2);
    cudaGetSymbolAddress((void**)&x3,   g_x3);
    cudaGetSymbolAddress((void**)&x1,   g_x1);

    // ---- fork: bias planes on side stream (independent of proj chain) -----
    cudaEventRecord(g_ev0, 0);
    cudaStreamWaitEvent(g_s1, g_ev0, 0);
    bias_kernel<<<1024, 256, 0, g_s1>>>(p, w_b, b_b, a_);
    cudaEventRecord(g_ev1, g_s1);

    // ---- main stream: projections ------------------------------------------
    pack_w_kernel<<<(CS * LDP / 4 + LDP / 4 + 255) / 256, 256>>>(
        w_q, b_q, w_kv, b_kv, w_qp, b_qp, w_kvp, b_kvp, wcat, bcat);
    gemm64_kernel<<<dim3(LDP / 64, 8, 1), 128>>>(s, CS, 0, wcat, LDP, 0,
                                                 bcat, proj, LDP, 0, CS);
    {
        const int TOT = HDS*NN*16 + HDS*NN*16 + HDS*NN*4 + HDS*NN*8 + NN*48;
        rotpack_kernel<<<(TOT + 255) / 256, 256>>>(proj, rot, trans,
                                                   kpk, kppk, vpk);
    }

    // join bias, then fused logits+softmax
    cudaStreamWaitEvent(0, g_ev1, 0);
    logits_softmax_kernel<<<dim3(64, HDS), 256>>>(proj, kpk, kppk, mask,
                                                  head_w, a_);

    // ---- fork: o_pair on side stream; ov gemm + postproc on main ----------
    cudaEventRecord(g_ev2, 0);
    cudaStreamWaitEvent(g_s1, g_ev2, 0);
    opair_kernel<<<NN, 192, 0, g_s1>>>(a_, p, cat_);
    cudaEventRecord(g_ev3, g_s1);

    // batched ov GEMM on the fast path (N padded to 64)
    gemm64_kernel<<<dim3(1, 8, HDS), 128>>>(a_, NN, (long long)NN * NN,
                                            vpk, 64, (long long)NN * 64,
                                            nullptr,
                                            ov_, 64, (long long)NN * 64,
                                            NN);
    postproc_kernel<<<NN, 192>>>(ov_, rot, trans, cat_);
    cudaStreamWaitEvent(0, g_ev3, 0);

    // ---- output projection (split-K 3) + fused reduce/residual/LN1 --------
    gemm64_kernel<<<dim3(6, 8, 3), 128>>>(cat_, 2112, 704,
                                          w_o, CS, (long long)704 * CS,
                                          nullptr, part, CS, (long long)NN * CS,
                                          704);
    reduce_ln_kernel<<<NN, 128>>>(part, b_o, s, ln1_g, ln1_b, x2);

    // ---- transition MLP (each GEMM split-K 3) ------------------------------
    gemm64_kernel<<<dim3(6, 8, 3), 128>>>(x2, CS, 128,
                                          tw1, CS, (long long)128 * CS,
                                          nullptr, part, CS, (long long)NN * CS,
                                          128);
    reduce_act_kernel<<<(NN * CS) / 256, 256>>>(part, tb1, x3, 1);
    gemm64_kernel<<<dim3(6, 8, 3), 128>>>(x3, CS, 128,
                                          tw2, CS, (long long)128 * CS,
                                          nullptr, part, CS, (long long)NN * CS,
                                          128);
    reduce_act_kernel<<<(NN * CS) / 256, 256>>>(part, tb2, x1, 1);
    gemm64_kernel<<<dim3(6, 8, 3), 128>>>(x1, CS, 128,
                                          tw3, CS, (long long)128 * CS,
                                          nullptr, part, CS, (long long)NN * CS,
                                          128);
    reduce_ln_kernel<<<NN, 128>>>(part, tb3, x2, ln2_g, ln2_b, out);

    // ---- backbone update ----------------------------------------------------
    bb_finalize_kernel<<<NN, 192>>>(out, bb_w, bb_b, rot, trans, out);
}

// round 7
// speedup vs baseline: 3.5907x; 1.0861x over previous
#include <cuda_runtime.h>
#include <math.h>

// ---------------------------------------------------------------------------
// StructureLayer (IPA) — B=1, N=512, H=12, C_S=384, C_P=128, C_H=16,
// P_QK=4, P_V=8.  Output: [ s2 (512*384) | rot_new (512*9) | trans_new (512*3) ]
// ---------------------------------------------------------------------------

#define NN 512
#define CS 384
#define CP 128
#define HDS 12

// proj row layout: [ q(192) | kv(384) | qp(144) | kvp(432) ]  = 1152
#define LDP 1152
#define OFF_Q   0
#define OFF_KV  192
#define OFF_QP  576
#define OFF_KVP 720

#define SQK 0.14433756729740643f    // sqrt(1/48)
#define SB  0.5773502691896258f     // sqrt(1/3)
#define SHW 0.13608276348795434f    // sqrt(1/54)

// ---- scratch (device globals) ----------------------------------------------
__device__ float g_wcat[CS * LDP];
__device__ float g_bcat[LDP];
__device__ float g_proj[NN * LDP];
__device__ float g_ppart[2 * NN * LDP];   // proj split-K partials
__device__ float g_kpack[HDS * NN * 16];
__device__ float g_kppack[HDS * NN * 12];
__device__ float g_vpack[HDS * NN * 64];  // [h][j][ v(16) | vp(24) | pad(24)=0 ]
__device__ float g_att[HDS * NN * NN];    // bias planes, then probs [h][i][j]
__device__ float g_ov[HDS * NN * 64];     // [h][i][ o(16) | op_raw(24) | pad ]
__device__ float g_cat[NN * 2112];
__device__ float g_part[3 * NN * CS];     // split-K partials
__device__ float g_x2[NN * CS];
__device__ float g_x3[NN * CS];
__device__ float g_x1[NN * CS];

// ---------------------------------------------------------------------------
// Pack projection weights/biases into one (384 x 1152) matrix. float4 copies.
// ---------------------------------------------------------------------------
__global__ void pack_w_kernel(const float* __restrict__ w_q,  const float* __restrict__ b_q,
                              const float* __restrict__ w_kv, const float* __restrict__ b_kv,
                              const float* __restrict__ w_qp, const float* __restrict__ b_qp,
                              const float* __restrict__ w_kvp,const float* __restrict__ b_kvp,
                              float* __restrict__ wcat, float* __restrict__ bcat)
{
    const int NW4 = CS * LDP / 4;
    int idx = blockIdx.x * blockDim.x + threadIdx.x;
    if (idx < NW4) {
        int r = idx / (LDP / 4), c = (idx % (LDP / 4)) * 4;
        float4 v;
        if      (c < 192) v = *(const float4*)(w_q  + r * 192 + c);
        else if (c < 576) v = *(const float4*)(w_kv + r * 384 + (c - 192));
        else if (c < 720) v = *(const float4*)(w_qp + r * 144 + (c - 576));
        else              v = *(const float4*)(w_kvp + r * 432 + (c - 720));
        *(float4*)(wcat + r * LDP + c) = v;
    } else if (idx < NW4 + LDP / 4) {
        int c = (idx - NW4) * 4;
        float4 v;
        if      (c < 192) v = *(const float4*)(b_q  + c);
        else if (c < 576) v = *(const float4*)(b_kv + (c - 192));
        else if (c < 720) v = *(const float4*)(b_qp + (c - 576));
        else              v = *(const float4*)(b_kvp + (c - 720));
        *(float4*)(bcat + c) = v;
    }
}

// ---------------------------------------------------------------------------
// Fast SGEMM: 64x64 tile, 128 threads, 8x4/thread, double-buffered smem.
// z = zb*KS + zk :  zb = batch index, zk = split-K index.
// Offsets: A += zb*sAz + zk*sAk ; B += zb*sBz + zk*sBk ; C += zb*sCz + zk*sCk.
// M,N multiples of 64; K multiple of 16; float4-aligned pointers.
// ---------------------------------------------------------------------------
__global__ void __launch_bounds__(128)
gemm64_kernel(const float* __restrict__ A, int lda, long long sAz, long long sAk,
              const float* __restrict__ B, int ldb, long long sBz, long long sBk,
              const float* __restrict__ bias,
              float* __restrict__ C, int ldc, long long sCz, long long sCk,
              int K, int KS)
{
    const int zb = blockIdx.z / KS, zk = blockIdx.z % KS;
    A += (size_t)zb * (size_t)sAz + (size_t)zk * (size_t)sAk;
    B += (size_t)zb * (size_t)sBz + (size_t)zk * (size_t)sBk;
    C += (size_t)zb * (size_t)sCz + (size_t)zk * (size_t)sCk;

    __shared__ __align__(16) float As[2][16][68];
    __shared__ __align__(16) float Bs[2][16][64];

    const int bm = blockIdx.y * 64, bn = blockIdx.x * 64;
    const int tid = threadIdx.x;
    const int tx = tid & 15, ty = tid >> 4;
    const int m0 = ty * 8, n0 = tx * 4;

    const int ar = tid >> 2, ak = (tid & 3) * 4;
    const int br = tid >> 4, bc = (tid & 15) * 4;

    const float* Ab = A + (size_t)bm * lda;

    float4 ra0, ra1, rb0, rb1;
    ra0 = *(const float4*)(Ab + (size_t)ar * lda + ak);
    ra1 = *(const float4*)(Ab + (size_t)(ar + 32) * lda + ak);
    rb0 = *(const float4*)(B + (size_t)br * ldb + bn + bc);
    rb1 = *(const float4*)(B + (size_t)(br + 8) * ldb + bn + bc);
    As[0][ak+0][ar] = ra0.x; As[0][ak+1][ar] = ra0.y;
    As[0][ak+2][ar] = ra0.z; As[0][ak+3][ar] = ra0.w;
    As[0][ak+0][ar+32] = ra1.x; As[0][ak+1][ar+32] = ra1.y;
    As[0][ak+2][ar+32] = ra1.z; As[0][ak+3][ar+32] = ra1.w;
    *(float4*)&Bs[0][br][bc]     = rb0;
    *(float4*)&Bs[0][br + 8][bc] = rb1;
    __syncthreads();

    float acc[8][4];
    #pragma unroll
    for (int i = 0; i < 8; i++)
        #pragma unroll
        for (int j = 0; j < 4; j++) acc[i][j] = 0.f;

    int buf = 0;
    for (int k0 = 0; k0 < K; k0 += 16) {
        const bool more = (k0 + 16) < K;
        if (more) {
            ra0 = *(const float4*)(Ab + (size_t)ar * lda + k0 + 16 + ak);
            ra1 = *(const float4*)(Ab + (size_t)(ar + 32) * lda + k0 + 16 + ak);
            rb0 = *(const float4*)(B + (size_t)(k0 + 16 + br) * ldb + bn + bc);
            rb1 = *(const float4*)(B + (size_t)(k0 + 16 + br + 8) * ldb + bn + bc);
        }
        #pragma unroll
        for (int kk = 0; kk < 16; kk++) {
            float4 a0 = *(const float4*)&As[buf][kk][m0];
            float4 a1 = *(const float4*)&As[buf][kk][m0 + 4];
            float4 b  = *(const float4*)&Bs[buf][kk][n0];
            float am[8] = {a0.x, a0.y, a0.z, a0.w, a1.x, a1.y, a1.z, a1.w};
            #pragma unroll
            for (int i = 0; i < 8; i++) {
                acc[i][0] = fmaf(am[i], b.x, acc[i][0]);
                acc[i][1] = fmaf(am[i], b.y, acc[i][1]);
                acc[i][2] = fmaf(am[i], b.z, acc[i][2]);
                acc[i][3] = fmaf(am[i], b.w, acc[i][3]);
            }
        }
        if (more) {
            buf ^= 1;
            __syncthreads();
            As[buf][ak+0][ar] = ra0.x; As[buf][ak+1][ar] = ra0.y;
            As[buf][ak+2][ar] = ra0.z; As[buf][ak+3][ar] = ra0.w;
            As[buf][ak+0][ar+32] = ra1.x; As[buf][ak+1][ar+32] = ra1.y;
            As[buf][ak+2][ar+32] = ra1.z; As[buf][ak+3][ar+32] = ra1.w;
            *(float4*)&Bs[buf][br][bc]     = rb0;
            *(float4*)&Bs[buf][br + 8][bc] = rb1;
            __syncthreads();
        }
    }

    #pragma unroll
    for (int i = 0; i < 8; i++) {
        float4 o = make_float4(acc[i][0], acc[i][1], acc[i][2], acc[i][3]);
        if (bias) {
            o.x += bias[bn + n0 + 0];
            o.y += bias[bn + n0 + 1];
            o.z += bias[bn + n0 + 2];
            o.w += bias[bn + n0 + 3];
        }
        *(float4*)(C + (size_t)(bm + m0 + i) * ldc + bn + n0) = o;
    }
}

// ---------------------------------------------------------------------------
// proj split-K reduce + bias.  proj[i] = p0[i] + p1[i] + bcat[i % LDP]
// ---------------------------------------------------------------------------
__global__ void reduce_proj_kernel(const float* __restrict__ ppart,
                                   const float* __restrict__ bcat,
                                   float* __restrict__ proj)
{
    int idx4 = blockIdx.x * blockDim.x + threadIdx.x;   // float4 index
    const size_t SP4 = (size_t)NN * LDP / 4;
    float4 a = ((const float4*)ppart)[idx4];
    float4 b = ((const float4*)ppart)[SP4 + idx4];
    int c = (idx4 % (LDP / 4)) * 4;
    float4 bb = *(const float4*)(bcat + c);
    float4 o = make_float4(a.x + b.x + bb.x, a.y + b.y + bb.y,
                           a.z + b.z + bb.z, a.w + b.w + bb.w);
    ((float4*)proj)[idx4] = o;
}

// ---------------------------------------------------------------------------
// Coalesced rotate + repack.
// ---------------------------------------------------------------------------
__global__ void rotpack_kernel(float* __restrict__ proj,
                               const float* __restrict__ rot,
                               const float* __restrict__ trans,
                               float* __restrict__ kpack,
                               float* __restrict__ kppack,
                               float* __restrict__ vpack)
{
    const int S1 = HDS * NN * 16;
    const int S2 = S1 + HDS * NN * 16;
    const int S3 = S2 + HDS * NN * 4;
    const int S4 = S3 + HDS * NN * 8;
    const int S5 = S4 + NN * 48;
    int idx = blockIdx.x * blockDim.x + threadIdx.x;

    if (idx < S1) {
        int c = idx & 15, j = (idx >> 4) & 511, h = idx >> 13;
        kpack[idx] = proj[(size_t)j * LDP + OFF_KV + h * 32 + c];
    } else if (idx < S2) {
        int t = idx - S1;
        int c = t & 15, j = (t >> 4) & 511, h = t >> 13;
        vpack[(((size_t)h * NN) + j) * 64 + c] =
            proj[(size_t)j * LDP + OFF_KV + h * 32 + 16 + c];
    } else if (idx < S3) {
        int t = idx - S2;
        int pp = t & 3, j = (t >> 2) & 511, h = t >> 11;
        const float* src = proj + (size_t)j * LDP + OFF_KVP + h * 36 + pp * 3;
        const float* R = rot + j * 9;
        const float* tr = trans + j * 3;
        float x = src[0], y = src[1], z = src[2];
        float* dst = kppack + (((size_t)h * NN) + j) * 12 + pp * 3;
        dst[0] = R[0]*x + R[1]*y + R[2]*z + tr[0];
        dst[1] = R[3]*x + R[4]*y + R[5]*z + tr[1];
        dst[2] = R[6]*x + R[7]*y + R[8]*z + tr[2];
    } else if (idx < S4) {
        int t = idx - S3;
        int pp = t & 7, j = (t >> 3) & 511, h = t >> 12;
        const float* src = proj + (size_t)j * LDP + OFF_KVP + h * 36 + (4 + pp) * 3;
        const float* R = rot + j * 9;
        const float* tr = trans + j * 3;
        float x = src[0], y = src[1], z = src[2];
        float* dst = vpack + (((size_t)h * NN) + j) * 64 + 16 + pp * 3;
        dst[0] = R[0]*x + R[1]*y + R[2]*z + tr[0];
        dst[1] = R[3]*x + R[4]*y + R[5]*z + tr[1];
        dst[2] = R[6]*x + R[7]*y + R[8]*z + tr[2];
    } else if (idx < S5) {
        int t = idx - S4;
        int pt = t % 48, j = t / 48;
        float* pv = proj + (size_t)j * LDP + OFF_QP + pt * 3;
        const float* R = rot + j * 9;
        const float* tr = trans + j * 3;
        float x = pv[0], y = pv[1], z = pv[2];
        pv[0] = R[0]*x + R[1]*y + R[2]*z + tr[0];
        pv[1] = R[3]*x + R[4]*y + R[5]*z + tr[1];
        pv[2] = R[6]*x + R[7]*y + R[8]*z + tr[2];
    }
}

// ---------------------------------------------------------------------------
// bias planes: att[h][i][j] = (p[i,j,:]·w_b[:,h] + b_b[h]) * sqrt(1/3)
// ---------------------------------------------------------------------------
__global__ void bias_kernel(const float* __restrict__ p,
                            const float* __restrict__ w_b,
                            const float* __restrict__ b_b,
                            float* __restrict__ att)
{
    __shared__ float wbt[HDS][CP];
    __shared__ float bbs[HDS];
    const int tid = threadIdx.x;
    #pragma unroll
    for (int k = 0; k < 6; k++) {
        int e = tid + k * 256;
        int h = e / CP, c = e % CP;
        wbt[h][c] = w_b[c * HDS + h];
    }
    if (tid < HDS) bbs[tid] = b_b[tid];
    __syncthreads();

    const int gw = blockIdx.x * 8 + (tid >> 5);
    const int lane = tid & 31;
    const int i = gw >> 4;
    const int j = ((gw & 15) << 5) + lane;

    float acc[HDS];
    #pragma unroll
    for (int h = 0; h < HDS; h++) acc[h] = 0.f;

    const float4* prow = (const float4*)(p + ((size_t)i * NN + j) * CP);
    #pragma unroll 4
    for (int c4 = 0; c4 < 32; c4++) {
        float4 pv = prow[c4];
        #pragma unroll
        for (int h = 0; h < HDS; h++) {
            float4 wv = ((const float4*)&wbt[h][0])[c4];
            acc[h] = fmaf(pv.x, wv.x,
                     fmaf(pv.y, wv.y,
                     fmaf(pv.z, wv.z,
                     fmaf(pv.w, wv.w, acc[h]))));
        }
    }
    #pragma unroll
    for (int h = 0; h < HDS; h++)
        att[((size_t)(h * NN) + i) * NN + j] = (acc[h] + bbs[h]) * SB;
}

// ---------------------------------------------------------------------------
// Fused logits + softmax.  Block = (i-tile of 8, head h).  256 threads.
// ---------------------------------------------------------------------------
__global__ void logits_softmax_kernel(const float* __restrict__ proj,
                                      const float* __restrict__ kpack,
                                      const float* __restrict__ kppack,
                                      const float* __restrict__ mask,
                                      const float* __restrict__ head_w,
                                      float* __restrict__ att)
{
    const int i0 = blockIdx.x * 8, h = blockIdx.y;
    const int tid = threadIdx.x;

    __shared__ float att_s[8][NN];
    __shared__ float kt[64][20];
    __shared__ float kpt[64][13];
    __shared__ float q_s[8][17];
    __shared__ float qp_s[8][13];
    __shared__ float m_i[8];
    __shared__ float sh_hw;

    if (tid < 128) {
        int il = tid >> 4, c = tid & 15;
        q_s[il][c] = proj[(size_t)(i0 + il) * LDP + OFF_Q + h * 16 + c];
    } else if (tid < 224) {
        int e = tid - 128;
        int il = e / 12, c = e % 12;
        qp_s[il][c] = proj[(size_t)(i0 + il) * LDP + OFF_QP + h * 12 + c];
    } else if (tid < 232) {
        m_i[tid - 224] = mask[i0 + (tid - 224)];
    } else if (tid == 232) {
        float w = head_w[h];
        float sp = fmaxf(w, 0.f) + log1pf(expf(-fabsf(w)));
        sh_hw = sp * SHW;
    }

    const float* kb  = kpack  + (size_t)(h * NN) * 16;
    const float* kpb = kppack + (size_t)(h * NN) * 12;

    const int jl = tid >> 2, ig = tid & 3;

    for (int j0 = 0; j0 < NN; j0 += 64) {
        #pragma unroll
        for (int k = 0; k < 4; k++) {
            int e = tid + k * 256;
            int r = e >> 4, c = e & 15;
            kt[r][c] = kb[(size_t)(j0 + r) * 16 + c];
        }
        #pragma unroll
        for (int k = 0; k < 3; k++) {
            int e = tid + k * 256;
            if (e < 768) {
                int r = e / 12, c = e % 12;
                kpt[r][c] = kpb[(size_t)(j0 + r) * 12 + c];
            }
        }
        __syncthreads();

        float mj = mask[j0 + jl];
        float hw = sh_hw;
        #pragma unroll
        for (int ii = 0; ii < 2; ii++) {
            int il = ig * 2 + ii;
            float qk = 0.f;
            #pragma unroll
            for (int c = 0; c < 16; c++) qk = fmaf(q_s[il][c], kt[jl][c], qk);
            float d2 = 0.f;
            #pragma unroll
            for (int d = 0; d < 12; d++) {
                float dd = qp_s[il][d] - kpt[jl][d];
                d2 = fmaf(dd, dd, d2);
            }
            float bias = att[((size_t)(h * NN) + i0 + il) * NN + j0 + jl];
            att_s[il][j0 + jl] = qk * SQK + bias - 0.5f * hw * d2
                               + (m_i[il] * mj - 1.0f) * 100000.0f;
        }
        __syncthreads();
    }

    const int w = tid >> 5, lane = tid & 31;
    float vals[16];
    float vmax = -1e30f;
    #pragma unroll
    for (int k = 0; k < 16; k++) {
        vals[k] = att_s[w][lane + 32 * k];
        vmax = fmaxf(vmax, vals[k]);
    }
    #pragma unroll
    for (int o = 16; o > 0; o >>= 1)
        vmax = fmaxf(vmax, __shfl_xor_sync(0xffffffffu, vmax, o));
    float sum = 0.f;
    #pragma unroll
    for (int k = 0; k < 16; k++) { vals[k] = expf(vals[k] - vmax); sum += vals[k]; }
    #pragma unroll
    for (int o = 16; o > 0; o >>= 1)
        sum += __shfl_xor_sync(0xffffffffu, sum, o);
    float inv = 1.0f / sum;
    float* arow = att + ((size_t)(h * NN) + i0 + w) * NN;
    #pragma unroll
    for (int k = 0; k < 16; k++)
        arow[lane + 32 * k] = vals[k] * inv;
}

// ---------------------------------------------------------------------------
// o_pair[i,h,c] = sum_j a[h,i,j]*p[i,j,c]  -> cat[i][576 + h*128 + c]
// ---------------------------------------------------------------------------
__global__ void opair_kernel(const float* __restrict__ att,
                             const float* __restrict__ p,
                             float* __restrict__ cat)
{
    const int i = blockIdx.x;
    __shared__ float as[HDS][NN];
    __shared__ float ps[32][128];
    const int tid = threadIdx.x;     // 192

    for (int idx = tid; idx < HDS * NN; idx += 192) {
        int h = idx >> 9, j = idx & 511;
        as[h][j] = att[((size_t)(h * NN + i)) * NN + j];
    }

    const int c4 = tid & 31;
    const int hh = tid >> 5;
    float acc0[4] = {0,0,0,0}, acc1[4] = {0,0,0,0};
    const float* pi = p + (size_t)i * NN * CP;

    for (int j0 = 0; j0 < NN; j0 += 32) {
        for (int idx = tid; idx < 32 * 32; idx += 192) {
            int jj = idx >> 5, cc = idx & 31;
            ((float4*)&ps[jj][0])[cc] =
                ((const float4*)(pi + (size_t)(j0 + jj) * CP))[cc];
        }
        __syncthreads();
        #pragma unroll 8
        for (int jj = 0; jj < 32; jj++) {
            float a0 = as[2 * hh][j0 + jj];
            float a1 = as[2 * hh + 1][j0 + jj];
            float4 pv = ((const float4*)&ps[jj][0])[c4];
            acc0[0] += a0 * pv.x; acc0[1] += a0 * pv.y;
            acc0[2] += a0 * pv.z; acc0[3] += a0 * pv.w;
            acc1[0] += a1 * pv.x; acc1[1] += a1 * pv.y;
            acc1[2] += a1 * pv.z; acc1[3] += a1 * pv.w;
        }
        __syncthreads();
    }
    float* dst = cat + (size_t)i * 2112 + 576;
    #pragma unroll
    for (int d = 0; d < 4; d++) {
        dst[(2 * hh) * 128 + c4 * 4 + d]     = acc0[d];
        dst[(2 * hh + 1) * 128 + c4 * 4 + d] = acc1[d];
    }
}

// ---------------------------------------------------------------------------
// Epilogue: copy o, rotate op back, norms.  (ov stride = 64)
// ---------------------------------------------------------------------------
__global__ void postproc_kernel(const float* __restrict__ ov,
                                const float* __restrict__ rot,
                                const float* __restrict__ trans,
                                float* __restrict__ cat)
{
    const int i = blockIdx.x;
    const int tid = threadIdx.x;   // 192
    float* ci = cat + (size_t)i * 2112;
    {
        int h = tid >> 4, c = tid & 15;
        ci[tid] = ov[((size_t)(h * NN) + i) * 64 + c];
    }
    if (tid < 96) {
        int h = tid >> 3, pp = tid & 7;
        const float* base = ov + ((size_t)(h * NN) + i) * 64 + 16 + pp * 3;
        float vx = base[0] - trans[i*3+0];
        float vy = base[1] - trans[i*3+1];
        float vz = base[2] - trans[i*3+2];
        const float* R = rot + i * 9;
        float ox = R[0]*vx + R[3]*vy + R[6]*vz;
        float oy = R[1]*vx + R[4]*vy + R[7]*vz;
        float oz = R[2]*vx + R[5]*vy + R[8]*vz;
        ci[192 + h*24 + pp*3 + 0] = ox;
        ci[192 + h*24 + pp*3 + 1] = oy;
        ci[192 + h*24 + pp*3 + 2] = oz;
        ci[480 + h*8 + pp] = sqrtf(ox*ox + oy*oy + oz*oz + 1e-8f);
    }
}

// ---------------------------------------------------------------------------
// 3-way split-K reduce + bias + optional relu (elementwise).
// ---------------------------------------------------------------------------
__global__ void reduce_act_kernel(const float* __restrict__ part,
                                  const float* __restrict__ bias,
                                  float* __restrict__ y, int relu)
{
    int idx = blockIdx.x * blockDim.x + threadIdx.x;
    const size_t SP = (size_t)NN * CS;
    int c = idx % CS;
    float v = part[idx] + part[SP + idx] + part[2*SP + idx] + bias[c];
    y[idx] = relu ? fmaxf(v, 0.f) : v;
}

// ---------------------------------------------------------------------------
// 3-way split-K reduce + bias + residual + LayerNorm.  Block/row, 128 thr.
// ---------------------------------------------------------------------------
__global__ void reduce_ln_kernel(const float* __restrict__ part,
                                 const float* __restrict__ bias,
                                 const float* __restrict__ res,
                                 const float* __restrict__ g,
                                 const float* __restrict__ b,
                                 float* __restrict__ y)
{
    __shared__ float rs[128], rs2[128];
    const int i = blockIdx.x, tid = threadIdx.x;
    const size_t SP = (size_t)NN * CS;
    float v[3];
    float sm = 0.f, sm2 = 0.f;
    #pragma unroll
    for (int k = 0; k < 3; k++) {
        int c = tid + k * 128;
        size_t o = (size_t)i * CS + c;
        float x = part[o] + part[SP + o] + part[2*SP + o] + bias[c] + res[o];
        v[k] = x;
        sm += x; sm2 += x * x;
    }
    rs[tid] = sm; rs2[tid] = sm2;
    __syncthreads();
    for (int st = 64; st > 0; st >>= 1) {
        if (tid < st) { rs[tid] += rs[tid + st]; rs2[tid] += rs2[tid + st]; }
        __syncthreads();
    }
    float mean = rs[0] * (1.0f / CS);
    float var  = rs2[0] * (1.0f / CS) - mean * mean;
    float inv  = rsqrtf(var + 1e-5f);
    #pragma unroll
    for (int k = 0; k < 3; k++) {
        int c = tid + k * 128;
        y[(size_t)i * CS + c] = (v[k] - mean) * inv * g[c] + b[c];
    }
}

// ---------------------------------------------------------------------------
// Fused backbone projection + quaternion frame update.
// ---------------------------------------------------------------------------
__global__ void bb_finalize_kernel(const float* __restrict__ s2,
                                   const float* __restrict__ bb_w,
                                   const float* __restrict__ bb_b,
                                   const float* __restrict__ rot,
                                   const float* __restrict__ trans,
                                   float* __restrict__ out)
{
    const int i = blockIdx.x;
    const int tid = threadIdx.x;
    const int w = tid >> 5, lane = tid & 31;
    __shared__ float u[6];
    const float* row = s2 + (size_t)i * CS;
    float sum = 0.f;
    for (int c = lane; c < CS; c += 32)
        sum = fmaf(row[c], bb_w[c * 6 + w], sum);
    #pragma unroll
    for (int o = 16; o > 0; o >>= 1)
        sum += __shfl_xor_sync(0xffffffffu, sum, o);
    if (lane == 0) u[w] = sum + bb_b[w];
    __syncthreads();
    if (tid == 0) {
        float bx = u[0], by = u[1], bz = u[2];
        float inv = rsqrtf(1.f + bx*bx + by*by + bz*bz);
        float qw = inv, x = bx * inv, y = by * inv, z = bz * inv;
        float Ru[9] = {
            1 - 2*(y*y + z*z), 2*(x*y - qw*z),    2*(x*z + qw*y),
            2*(x*y + qw*z),    1 - 2*(x*x + z*z), 2*(y*z - qw*x),
            2*(x*z - qw*y),    2*(y*z + qw*x),    1 - 2*(x*x + y*y)};
        const float* R = rot + i * 9;
        float* ro = out + NN * CS + i * 9;
        #pragma unroll
        for (int r = 0; r < 3; r++)
            #pragma unroll
            for (int c = 0; c < 3; c++)
                ro[r*3+c] = R[r*3+0]*Ru[0*3+c] + R[r*3+1]*Ru[1*3+c]
                          + R[r*3+2]*Ru[2*3+c];
        float tx = u[3], ty = u[4], tz = u[5];
        float* to = out + NN * CS + NN * 9 + i * 3;
        #pragma unroll
        for (int r = 0; r < 3; r++)
            to[r] = R[r*3+0]*tx + R[r*3+1]*ty + R[r*3+2]*tz + trans[i*3+r];
    }
}

// ---------------------------------------------------------------------------
static cudaStream_t g_s1 = nullptr;
static cudaEvent_t  g_ev0, g_ev1, g_ev2, g_ev3;

extern "C" void kernel_launch(void* const* d_in, const int* in_sizes, int n_in,
                              void* d_out, int out_size)
{
    if (!g_s1) {
        cudaStreamCreateWithFlags(&g_s1, cudaStreamNonBlocking);
        cudaEventCreateWithFlags(&g_ev0, cudaEventDisableTiming);
        cudaEventCreateWithFlags(&g_ev1, cudaEventDisableTiming);
        cudaEventCreateWithFlags(&g_ev2, cudaEventDisableTiming);
        cudaEventCreateWithFlags(&g_ev3, cudaEventDisableTiming);
    }

    const float* s      = (const float*)d_in[0];
    const float* p      = (const float*)d_in[1];
    const float* rot    = (const float*)d_in[2];
    const float* trans  = (const float*)d_in[3];
    const float* mask   = (const float*)d_in[4];
    const float* w_q    = (const float*)d_in[5];
    const float* b_q    = (const float*)d_in[6];
    const float* w_kv   = (const float*)d_in[7];
    const float* b_kv   = (const float*)d_in[8];
    const float* w_qp   = (const float*)d_in[9];
    const float* b_qp   = (const float*)d_in[10];
    const float* w_kvp  = (const float*)d_in[11];
    const float* b_kvp  = (const float*)d_in[12];
    const float* w_b    = (const float*)d_in[13];
    const float* b_b    = (const float*)d_in[14];
    const float* head_w = (const float*)d_in[15];
    const float* w_o    = (const float*)d_in[16];
    const float* b_o    = (const float*)d_in[17];
    const float* ln1_g  = (const float*)d_in[18];
    const float* ln1_b  = (const float*)d_in[19];
    const float* tw1    = (const float*)d_in[20];
    const float* tb1    = (const float*)d_in[21];
    const float* tw2    = (const float*)d_in[22];
    const float* tb2    = (const float*)d_in[23];
    const float* tw3    = (const float*)d_in[24];
    const float* tb3    = (const float*)d_in[25];
    const float* ln2_g  = (const float*)d_in[26];
    const float* ln2_b  = (const float*)d_in[27];
    const float* bb_w   = (const float*)d_in[28];
    const float* bb_b   = (const float*)d_in[29];
    float* out = (float*)d_out;

    float *wcat, *bcat, *proj, *ppart, *kpk, *kppk, *vpk, *a_, *ov_, *cat_,
          *part, *x2, *x3, *x1;
    cudaGetSymbolAddress((void**)&wcat, g_wcat);
    cudaGetSymbolAddress((void**)&bcat, g_bcat);
    cudaGetSymbolAddress((void**)&proj, g_proj);
    cudaGetSymbolAddress((void**)&ppart, g_ppart);
    cudaGetSymbolAddress((void**)&kpk,  g_kpack);
    cudaGetSymbolAddress((void**)&kppk, g_kppack);
    cudaGetSymbolAddress((void**)&vpk,  g_vpack);
    cudaGetSymbolAddress((void**)&a_,   g_att);
    cudaGetSymbolAddress((void**)&ov_,  g_ov);
    cudaGetSymbolAddress((void**)&cat_, g_cat);
    cudaGetSymbolAddress((void**)&part, g_part);
    cudaGetSymbolAddress((void**)&x2,   g_x2);
    cudaGetSymbolAddress((void**)&x3,   g_x3);
    cudaGetSymbolAddress((void**)&x1,   g_x1);

    // ---- fork: bias planes on side stream (independent of proj chain) -----
    cudaEventRecord(g_ev0, 0);
    cudaStreamWaitEvent(g_s1, g_ev0, 0);
    bias_kernel<<<1024, 256, 0, g_s1>>>(p, w_b, b_b, a_);
    cudaEventRecord(g_ev1, g_s1);

    // ---- main stream: projections (split-K 2 -> 288 blocks) ---------------
    pack_w_kernel<<<(CS * LDP / 4 + LDP / 4 + 255) / 256, 256>>>(
        w_q, b_q, w_kv, b_kv, w_qp, b_qp, w_kvp, b_kvp, wcat, bcat);
    gemm64_kernel<<<dim3(LDP / 64, 8, 2), 128>>>(
        s, CS, 0, 192,
        wcat, LDP, 0, (long long)192 * LDP,
        nullptr,
        ppart, LDP, 0, (long long)NN * LDP,
        192, 2);
    reduce_proj_kernel<<<(NN * LDP / 4) / 256, 256>>>(ppart, bcat, proj);
    {
        const int TOT = HDS*NN*16 + HDS*NN*16 + HDS*NN*4 + HDS*NN*8 + NN*48;
        rotpack_kernel<<<(TOT + 255) / 256, 256>>>(proj, rot, trans,
                                                   kpk, kppk, vpk);
    }

    // join bias, then fused logits+softmax
    cudaStreamWaitEvent(0, g_ev1, 0);
    logits_softmax_kernel<<<dim3(64, HDS), 256>>>(proj, kpk, kppk, mask,
                                                  head_w, a_);

    // ---- fork: o_pair on side stream; ov gemm + postproc on main ----------
    cudaEventRecord(g_ev2, 0);
    cudaStreamWaitEvent(g_s1, g_ev2, 0);
    opair_kernel<<<NN, 192, 0, g_s1>>>(a_, p, cat_);
    cudaEventRecord(g_ev3, g_s1);

    // batched ov GEMM (z = 12 batches, KS = 1)
    gemm64_kernel<<<dim3(1, 8, HDS), 128>>>(
        a_, NN, (long long)NN * NN, 0,
        vpk, 64, (long long)NN * 64, 0,
        nullptr,
        ov_, 64, (long long)NN * 64, 0,
        NN, 1);
    postproc_kernel<<<NN, 192>>>(ov_, rot, trans, cat_);
    cudaStreamWaitEvent(0, g_ev3, 0);

    // ---- output projection (split-K 3) + fused reduce/residual/LN1 --------
    gemm64_kernel<<<dim3(6, 8, 3), 128>>>(
        cat_, 2112, 0, 704,
        w_o, CS, 0, (long long)704 * CS,
        nullptr,
        part, CS, 0, (long long)NN * CS,
        704, 3);
    reduce_ln_kernel<<<NN, 128>>>(part, b_o, s, ln1_g, ln1_b, x2);

    // ---- transition MLP (each GEMM split-K 3) ------------------------------
    gemm64_kernel<<<dim3(6, 8, 3), 128>>>(
        x2, CS, 0, 128,
        tw1, CS, 0, (long long)128 * CS,
        nullptr,
        part, CS, 0, (long long)NN * CS,
        128, 3);
    reduce_act_kernel<<<(NN * CS) / 256, 256>>>(part, tb1, x3, 1);
    gemm64_kernel<<<dim3(6, 8, 3), 128>>>(
        x3, CS, 0, 128,
        tw2, CS, 0, (long long)128 * CS,
        nullptr,
        part, CS, 0, (long long)NN * CS,
        128, 3);
    reduce_act_kernel<<<(NN * CS) / 256, 256>>>(part, tb2, x1, 1);
    gemm64_kernel<<<dim3(6, 8, 3), 128>>>(
        x1, CS, 0, 128,
        tw3, CS, 0, (long long)128 * CS,
        nullptr,
        part, CS, 0, (long long)NN * CS,
        128, 3);
    reduce_ln_kernel<<<NN, 128>>>(part, tb3, x2, ln2_g, ln2_b, out);

    // ---- backbone update ----------------------------------------------------
    bb_finalize_kernel<<<NN, 192>>>(out, bb_w, bb_b, rot, trans, out);
}

// round 8
// speedup vs baseline: 3.6639x; 1.0204x over previous
#include <cuda_runtime.h>
#include <math.h>

// ---------------------------------------------------------------------------
// StructureLayer (IPA) — B=1, N=512, H=12, C_S=384, C_P=128, C_H=16,
// P_QK=4, P_V=8.  Output: [ s2 (512*384) | rot_new (512*9) | trans_new (512*3) ]
// ---------------------------------------------------------------------------

#define NN 512
#define CS 384
#define CP 128
#define HDS 12

// proj row layout: [ q(192) | kv(384) | qp(144) | kvp(432) ]  = 1152
#define LDP 1152
#define OFF_Q   0
#define OFF_KV  192
#define OFF_QP  576
#define OFF_KVP 720

#define SQK 0.14433756729740643f    // sqrt(1/48)
#define SB  0.5773502691896258f     // sqrt(1/3)
#define SHW 0.13608276348795434f    // sqrt(1/54)

// ---- scratch (device globals) ----------------------------------------------
__device__ float g_wcat[CS * LDP];
__device__ float g_bcat[LDP];
__device__ float g_proj[NN * LDP];
__device__ float g_ppart[2 * NN * LDP];   // proj split-K partials
__device__ float g_kpack[HDS * NN * 16];
__device__ float g_kppack[HDS * NN * 12];
__device__ float g_vpack[HDS * NN * 64];  // [h][j][ v(16) | vp(24) | pad(24)=0 ]
__device__ float g_att[HDS * NN * NN];    // bias planes, then probs [h][i][j]
__device__ float g_ov[HDS * NN * 64];     // [h][i][ o(16) | op_raw(24) | pad ]
__device__ float g_cat[NN * 2112];
__device__ float g_part[3 * NN * CS];     // split-K partials
__device__ float g_x2[NN * CS];
__device__ float g_x3[NN * CS];
__device__ float g_x1[NN * CS];

// ---------------------------------------------------------------------------
// tf32 helpers
// ---------------------------------------------------------------------------
__device__ __forceinline__ unsigned cvt_tf32(float x)
{
    unsigned r;
    asm("cvt.rna.tf32.f32 %0, %1;" : "=r"(r) : "f"(x));
    return r;
}

__device__ __forceinline__ void mma_tf32(float* d, const unsigned* a,
                                         const unsigned* b)
{
    asm volatile(
        "mma.sync.aligned.m16n8k8.row.col.f32.tf32.tf32.f32 "
        "{%0,%1,%2,%3}, {%4,%5,%6,%7}, {%8,%9}, {%0,%1,%2,%3};\n"
        : "+f"(d[0]), "+f"(d[1]), "+f"(d[2]), "+f"(d[3])
        : "r"(a[0]), "r"(a[1]), "r"(a[2]), "r"(a[3]),
          "r"(b[0]), "r"(b[1]));
}

// ---------------------------------------------------------------------------
// Pack projection weights/biases into one (384 x 1152) matrix. float4 copies.
// ---------------------------------------------------------------------------
__global__ void pack_w_kernel(const float* __restrict__ w_q,  const float* __restrict__ b_q,
                              const float* __restrict__ w_kv, const float* __restrict__ b_kv,
                              const float* __restrict__ w_qp, const float* __restrict__ b_qp,
                              const float* __restrict__ w_kvp,const float* __restrict__ b_kvp,
                              float* __restrict__ wcat, float* __restrict__ bcat)
{
    const int NW4 = CS * LDP / 4;
    int idx = blockIdx.x * blockDim.x + threadIdx.x;
    if (idx < NW4) {
        int r = idx / (LDP / 4), c = (idx % (LDP / 4)) * 4;
        float4 v;
        if      (c < 192) v = *(const float4*)(w_q  + r * 192 + c);
        else if (c < 576) v = *(const float4*)(w_kv + r * 384 + (c - 192));
        else if (c < 720) v = *(const float4*)(w_qp + r * 144 + (c - 576));
        else              v = *(const float4*)(w_kvp + r * 432 + (c - 720));
        *(float4*)(wcat + r * LDP + c) = v;
    } else if (idx < NW4 + LDP / 4) {
        int c = (idx - NW4) * 4;
        float4 v;
        if      (c < 192) v = *(const float4*)(b_q  + c);
        else if (c < 576) v = *(const float4*)(b_kv + (c - 192));
        else if (c < 720) v = *(const float4*)(b_qp + (c - 576));
        else              v = *(const float4*)(b_kvp + (c - 720));
        *(float4*)(bcat + c) = v;
    }
}

// ---------------------------------------------------------------------------
// tf32 tensor-core GEMM: 64x64 tile, 128 threads (4 warps, 2x2 layout,
// 32x32 warp tile = 2x4 m16n8k8 atoms).  Double-buffered smem, operands
// converted to tf32 on the smem store.  z = zb*KS + zk (batch x split-K).
// M,N multiples of 64; K multiple of 16; float4-aligned pointers.
// ---------------------------------------------------------------------------
__global__ void __launch_bounds__(128)
gemm64_kernel(const float* __restrict__ A, int lda, long long sAz, long long sAk,
              const float* __restrict__ B, int ldb, long long sBz, long long sBk,
              const float* __restrict__ bias,
              float* __restrict__ C, int ldc, long long sCz, long long sCk,
              int K, int KS)
{
    const int zb = blockIdx.z / KS, zk = blockIdx.z % KS;
    A += (size_t)zb * (size_t)sAz + (size_t)zk * (size_t)sAk;
    B += (size_t)zb * (size_t)sBz + (size_t)zk * (size_t)sBk;
    C += (size_t)zb * (size_t)sCz + (size_t)zk * (size_t)sCk;

    // [k][m] and [k][n], stride 72 (72 mod 32 = 8 -> conflict-free frags)
    __shared__ __align__(16) unsigned As[2][16][72];
    __shared__ __align__(16) unsigned Bs[2][16][72];

    const int bm = blockIdx.y * 64, bn = blockIdx.x * 64;
    const int tid = threadIdx.x;
    const int lane = tid & 31, warp = tid >> 5;
    const int g = lane >> 2, t4 = lane & 3;
    const int wm = (warp >> 1) * 32, wn = (warp & 1) * 32;

    const int ar = tid >> 2, ak = (tid & 3) * 4;   // A: rows ar, ar+32
    const int br = tid >> 4, bc = (tid & 15) * 4;  // B: rows br, br+8

    const float* Ab = A + (size_t)bm * lda;

    float4 ra0, ra1, rb0, rb1;
    ra0 = *(const float4*)(Ab + (size_t)ar * lda + ak);
    ra1 = *(const float4*)(Ab + (size_t)(ar + 32) * lda + ak);
    rb0 = *(const float4*)(B + (size_t)br * ldb + bn + bc);
    rb1 = *(const float4*)(B + (size_t)(br + 8) * ldb + bn + bc);

    As[0][ak+0][ar] = cvt_tf32(ra0.x); As[0][ak+1][ar] = cvt_tf32(ra0.y);
    As[0][ak+2][ar] = cvt_tf32(ra0.z); As[0][ak+3][ar] = cvt_tf32(ra0.w);
    As[0][ak+0][ar+32] = cvt_tf32(ra1.x); As[0][ak+1][ar+32] = cvt_tf32(ra1.y);
    As[0][ak+2][ar+32] = cvt_tf32(ra1.z); As[0][ak+3][ar+32] = cvt_tf32(ra1.w);
    {
        uint4 u0 = make_uint4(cvt_tf32(rb0.x), cvt_tf32(rb0.y),
                              cvt_tf32(rb0.z), cvt_tf32(rb0.w));
        uint4 u1 = make_uint4(cvt_tf32(rb1.x), cvt_tf32(rb1.y),
                              cvt_tf32(rb1.z), cvt_tf32(rb1.w));
        *(uint4*)&Bs[0][br][bc]     = u0;
        *(uint4*)&Bs[0][br + 8][bc] = u1;
    }
    __syncthreads();

    float acc[2][4][4];
    #pragma unroll
    for (int mt = 0; mt < 2; mt++)
        #pragma unroll
        for (int nt = 0; nt < 4; nt++)
            #pragma unroll
            for (int r = 0; r < 4; r++) acc[mt][nt][r] = 0.f;

    int buf = 0;
    for (int k0 = 0; k0 < K; k0 += 16) {
        const bool more = (k0 + 16) < K;
        if (more) {
            ra0 = *(const float4*)(Ab + (size_t)ar * lda + k0 + 16 + ak);
            ra1 = *(const float4*)(Ab + (size_t)(ar + 32) * lda + k0 + 16 + ak);
            rb0 = *(const float4*)(B + (size_t)(k0 + 16 + br) * ldb + bn + bc);
            rb1 = *(const float4*)(B + (size_t)(k0 + 16 + br + 8) * ldb + bn + bc);
        }
        #pragma unroll
        for (int kk = 0; kk < 16; kk += 8) {
            unsigned af[2][4], bf[4][2];
            #pragma unroll
            for (int mt = 0; mt < 2; mt++) {
                int m0 = wm + mt * 16 + g;
                af[mt][0] = As[buf][kk + t4][m0];
                af[mt][1] = As[buf][kk + t4][m0 + 8];
                af[mt][2] = As[buf][kk + 4 + t4][m0];
                af[mt][3] = As[buf][kk + 4 + t4][m0 + 8];
            }
            #pragma unroll
            for (int nt = 0; nt < 4; nt++) {
                int n0 = wn + nt * 8 + g;
                bf[nt][0] = Bs[buf][kk + t4][n0];
                bf[nt][1] = Bs[buf][kk + 4 + t4][n0];
            }
            #pragma unroll
            for (int mt = 0; mt < 2; mt++)
                #pragma unroll
                for (int nt = 0; nt < 4; nt++)
                    mma_tf32(acc[mt][nt], af[mt], bf[nt]);
        }
        if (more) {
            buf ^= 1;
            __syncthreads();
            As[buf][ak+0][ar] = cvt_tf32(ra0.x); As[buf][ak+1][ar] = cvt_tf32(ra0.y);
            As[buf][ak+2][ar] = cvt_tf32(ra0.z); As[buf][ak+3][ar] = cvt_tf32(ra0.w);
            As[buf][ak+0][ar+32] = cvt_tf32(ra1.x); As[buf][ak+1][ar+32] = cvt_tf32(ra1.y);
            As[buf][ak+2][ar+32] = cvt_tf32(ra1.z); As[buf][ak+3][ar+32] = cvt_tf32(ra1.w);
            uint4 u0 = make_uint4(cvt_tf32(rb0.x), cvt_tf32(rb0.y),
                                  cvt_tf32(rb0.z), cvt_tf32(rb0.w));
            uint4 u1 = make_uint4(cvt_tf32(rb1.x), cvt_tf32(rb1.y),
                                  cvt_tf32(rb1.z), cvt_tf32(rb1.w));
            *(uint4*)&Bs[buf][br][bc]     = u0;
            *(uint4*)&Bs[buf][br + 8][bc] = u1;
            __syncthreads();
        }
    }

    #pragma unroll
    for (int mt = 0; mt < 2; mt++) {
        int row0 = bm + wm + mt * 16 + g;
        #pragma unroll
        for (int nt = 0; nt < 4; nt++) {
            int col = bn + wn + nt * 8 + t4 * 2;
            float b0 = 0.f, b1 = 0.f;
            if (bias) { b0 = bias[col]; b1 = bias[col + 1]; }
            float2 v0 = make_float2(acc[mt][nt][0] + b0, acc[mt][nt][1] + b1);
            float2 v1 = make_float2(acc[mt][nt][2] + b0, acc[mt][nt][3] + b1);
            *(float2*)(C + (size_t)row0 * ldc + col)       = v0;
            *(float2*)(C + (size_t)(row0 + 8) * ldc + col) = v1;
        }
    }
}

// ---------------------------------------------------------------------------
// proj split-K reduce + bias.  proj[i] = p0[i] + p1[i] + bcat[i % LDP]
// ---------------------------------------------------------------------------
__global__ void reduce_proj_kernel(const float* __restrict__ ppart,
                                   const float* __restrict__ bcat,
                                   float* __restrict__ proj)
{
    int idx4 = blockIdx.x * blockDim.x + threadIdx.x;   // float4 index
    const size_t SP4 = (size_t)NN * LDP / 4;
    float4 a = ((const float4*)ppart)[idx4];
    float4 b = ((const float4*)ppart)[SP4 + idx4];
    int c = (idx4 % (LDP / 4)) * 4;
    float4 bb = *(const float4*)(bcat + c);
    float4 o = make_float4(a.x + b.x + bb.x, a.y + b.y + bb.y,
                           a.z + b.z + bb.z, a.w + b.w + bb.w);
    ((float4*)proj)[idx4] = o;
}

// ---------------------------------------------------------------------------
// Coalesced rotate + repack.
// ---------------------------------------------------------------------------
__global__ void rotpack_kernel(float* __restrict__ proj,
                               const float* __restrict__ rot,
                               const float* __restrict__ trans,
                               float* __restrict__ kpack,
                               float* __restrict__ kppack,
                               float* __restrict__ vpack)
{
    const int S1 = HDS * NN * 16;
    const int S2 = S1 + HDS * NN * 16;
    const int S3 = S2 + HDS * NN * 4;
    const int S4 = S3 + HDS * NN * 8;
    const int S5 = S4 + NN * 48;
    int idx = blockIdx.x * blockDim.x + threadIdx.x;

    if (idx < S1) {
        int c = idx & 15, j = (idx >> 4) & 511, h = idx >> 13;
        kpack[idx] = proj[(size_t)j * LDP + OFF_KV + h * 32 + c];
    } else if (idx < S2) {
        int t = idx - S1;
        int c = t & 15, j = (t >> 4) & 511, h = t >> 13;
        vpack[(((size_t)h * NN) + j) * 64 + c] =
            proj[(size_t)j * LDP + OFF_KV + h * 32 + 16 + c];
    } else if (idx < S3) {
        int t = idx - S2;
        int pp = t & 3, j = (t >> 2) & 511, h = t >> 11;
        const float* src = proj + (size_t)j * LDP + OFF_KVP + h * 36 + pp * 3;
        const float* R = rot + j * 9;
        const float* tr = trans + j * 3;
        float x = src[0], y = src[1], z = src[2];
        float* dst = kppack + (((size_t)h * NN) + j) * 12 + pp * 3;
        dst[0] = R[0]*x + R[1]*y + R[2]*z + tr[0];
        dst[1] = R[3]*x + R[4]*y + R[5]*z + tr[1];
        dst[2] = R[6]*x + R[7]*y + R[8]*z + tr[2];
    } else if (idx < S4) {
        int t = idx - S3;
        int pp = t & 7, j = (t >> 3) & 511, h = t >> 12;
        const float* src = proj + (size_t)j * LDP + OFF_KVP + h * 36 + (4 + pp) * 3;
        const float* R = rot + j * 9;
        const float* tr = trans + j * 3;
        float x = src[0], y = src[1], z = src[2];
        float* dst = vpack + (((size_t)h * NN) + j) * 64 + 16 + pp * 3;
        dst[0] = R[0]*x + R[1]*y + R[2]*z + tr[0];
        dst[1] = R[3]*x + R[4]*y + R[5]*z + tr[1];
        dst[2] = R[6]*x + R[7]*y + R[8]*z + tr[2];
    } else if (idx < S5) {
        int t = idx - S4;
        int pt = t % 48, j = t / 48;
        float* pv = proj + (size_t)j * LDP + OFF_QP + pt * 3;
        const float* R = rot + j * 9;
        const float* tr = trans + j * 3;
        float x = pv[0], y = pv[1], z = pv[2];
        pv[0] = R[0]*x + R[1]*y + R[2]*z + tr[0];
        pv[1] = R[3]*x + R[4]*y + R[5]*z + tr[1];
        pv[2] = R[6]*x + R[7]*y + R[8]*z + tr[2];
    }
}

// ---------------------------------------------------------------------------
// bias planes: att[h][i][j] = (p[i,j,:]·w_b[:,h] + b_b[h]) * sqrt(1/3)
// ---------------------------------------------------------------------------
__global__ void bias_kernel(const float* __restrict__ p,
                            const float* __restrict__ w_b,
                            const float* __restrict__ b_b,
                            float* __restrict__ att)
{
    __shared__ float wbt[HDS][CP];
    __shared__ float bbs[HDS];
    const int tid = threadIdx.x;
    #pragma unroll
    for (int k = 0; k < 6; k++) {
        int e = tid + k * 256;
        int h = e / CP, c = e % CP;
        wbt[h][c] = w_b[c * HDS + h];
    }
    if (tid < HDS) bbs[tid] = b_b[tid];
    __syncthreads();

    const int gw = blockIdx.x * 8 + (tid >> 5);
    const int lane = tid & 31;
    const int i = gw >> 4;
    const int j = ((gw & 15) << 5) + lane;

    float acc[HDS];
    #pragma unroll
    for (int h = 0; h < HDS; h++) acc[h] = 0.f;

    const float4* prow = (const float4*)(p + ((size_t)i * NN + j) * CP);
    #pragma unroll 4
    for (int c4 = 0; c4 < 32; c4++) {
        float4 pv = prow[c4];
        #pragma unroll
        for (int h = 0; h < HDS; h++) {
            float4 wv = ((const float4*)&wbt[h][0])[c4];
            acc[h] = fmaf(pv.x, wv.x,
                     fmaf(pv.y, wv.y,
                     fmaf(pv.z, wv.z,
                     fmaf(pv.w, wv.w, acc[h]))));
        }
    }
    #pragma unroll
    for (int h = 0; h < HDS; h++)
        att[((size_t)(h * NN) + i) * NN + j] = (acc[h] + bbs[h]) * SB;
}

// ---------------------------------------------------------------------------
// Fused logits + softmax.  Block = (i-tile of 8, head h).  256 threads.
// ---------------------------------------------------------------------------
__global__ void logits_softmax_kernel(const float* __restrict__ proj,
                                      const float* __restrict__ kpack,
                                      const float* __restrict__ kppack,
                                      const float* __restrict__ mask,
                                      const float* __restrict__ head_w,
                                      float* __restrict__ att)
{
    const int i0 = blockIdx.x * 8, h = blockIdx.y;
    const int tid = threadIdx.x;

    __shared__ float att_s[8][NN];
    __shared__ float kt[64][20];
    __shared__ float kpt[64][13];
    __shared__ float q_s[8][17];
    __shared__ float qp_s[8][13];
    __shared__ float m_i[8];
    __shared__ float sh_hw;

    if (tid < 128) {
        int il = tid >> 4, c = tid & 15;
        q_s[il][c] = proj[(size_t)(i0 + il) * LDP + OFF_Q + h * 16 + c];
    } else if (tid < 224) {
        int e = tid - 128;
        int il = e / 12, c = e % 12;
        qp_s[il][c] = proj[(size_t)(i0 + il) * LDP + OFF_QP + h * 12 + c];
    } else if (tid < 232) {
        m_i[tid - 224] = mask[i0 + (tid - 224)];
    } else if (tid == 232) {
        float w = head_w[h];
        float sp = fmaxf(w, 0.f) + log1pf(expf(-fabsf(w)));
        sh_hw = sp * SHW;
    }

    const float* kb  = kpack  + (size_t)(h * NN) * 16;
    const float* kpb = kppack + (size_t)(h * NN) * 12;

    const int jl = tid >> 2, ig = tid & 3;

    for (int j0 = 0; j0 < NN; j0 += 64) {
        #pragma unroll
        for (int k = 0; k < 4; k++) {
            int e = tid + k * 256;
            int r = e >> 4, c = e & 15;
            kt[r][c] = kb[(size_t)(j0 + r) * 16 + c];
        }
        #pragma unroll
        for (int k = 0; k < 3; k++) {
            int e = tid + k * 256;
            if (e < 768) {
                int r = e / 12, c = e % 12;
                kpt[r][c] = kpb[(size_t)(j0 + r) * 12 + c];
            }
        }
        __syncthreads();

        float mj = mask[j0 + jl];
        float hw = sh_hw;
        #pragma unroll
        for (int ii = 0; ii < 2; ii++) {
            int il = ig * 2 + ii;
            float qk = 0.f;
            #pragma unroll
            for (int c = 0; c < 16; c++) qk = fmaf(q_s[il][c], kt[jl][c], qk);
            float d2 = 0.f;
            #pragma unroll
            for (int d = 0; d < 12; d++) {
                float dd = qp_s[il][d] - kpt[jl][d];
                d2 = fmaf(dd, dd, d2);
            }
            float bias = att[((size_t)(h * NN) + i0 + il) * NN + j0 + jl];
            att_s[il][j0 + jl] = qk * SQK + bias - 0.5f * hw * d2
                               + (m_i[il] * mj - 1.0f) * 100000.0f;
        }
        __syncthreads();
    }

    const int w = tid >> 5, lane = tid & 31;
    float vals[16];
    float vmax = -1e30f;
    #pragma unroll
    for (int k = 0; k < 16; k++) {
        vals[k] = att_s[w][lane + 32 * k];
        vmax = fmaxf(vmax, vals[k]);
    }
    #pragma unroll
    for (int o = 16; o > 0; o >>= 1)
        vmax = fmaxf(vmax, __shfl_xor_sync(0xffffffffu, vmax, o));
    float sum = 0.f;
    #pragma unroll
    for (int k = 0; k < 16; k++) { vals[k] = expf(vals[k] - vmax); sum += vals[k]; }
    #pragma unroll
    for (int o = 16; o > 0; o >>= 1)
        sum += __shfl_xor_sync(0xffffffffu, sum, o);
    float inv = 1.0f / sum;
    float* arow = att + ((size_t)(h * NN) + i0 + w) * NN;
    #pragma unroll
    for (int k = 0; k < 16; k++)
        arow[lane + 32 * k] = vals[k] * inv;
}

// ---------------------------------------------------------------------------
// o_pair[i,h,c] = sum_j a[h,i,j]*p[i,j,c]  -> cat[i][576 + h*128 + c]
// ---------------------------------------------------------------------------
__global__ void opair_kernel(const float* __restrict__ att,
                             const float* __restrict__ p,
                             float* __restrict__ cat)
{
    const int i = blockIdx.x;
    __shared__ float as[HDS][NN];
    __shared__ float ps[32][128];
    const int tid = threadIdx.x;     // 192

    for (int idx = tid; idx < HDS * NN; idx += 192) {
        int h = idx >> 9, j = idx & 511;
        as[h][j] = att[((size_t)(h * NN + i)) * NN + j];
    }

    const int c4 = tid & 31;
    const int hh = tid >> 5;
    float acc0[4] = {0,0,0,0}, acc1[4] = {0,0,0,0};
    const float* pi = p + (size_t)i * NN * CP;

    for (int j0 = 0; j0 < NN; j0 += 32) {
        for (int idx = tid; idx < 32 * 32; idx += 192) {
            int jj = idx >> 5, cc = idx & 31;
            ((float4*)&ps[jj][0])[cc] =
                ((const float4*)(pi + (size_t)(j0 + jj) * CP))[cc];
        }
        __syncthreads();
        #pragma unroll 8
        for (int jj = 0; jj < 32; jj++) {
            float a0 = as[2 * hh][j0 + jj];
            float a1 = as[2 * hh + 1][j0 + jj];
            float4 pv = ((const float4*)&ps[jj][0])[c4];
            acc0[0] += a0 * pv.x; acc0[1] += a0 * pv.y;
            acc0[2] += a0 * pv.z; acc0[3] += a0 * pv.w;
            acc1[0] += a1 * pv.x; acc1[1] += a1 * pv.y;
            acc1[2] += a1 * pv.z; acc1[3] += a1 * pv.w;
        }
        __syncthreads();
    }
    float* dst = cat + (size_t)i * 2112 + 576;
    #pragma unroll
    for (int d = 0; d < 4; d++) {
        dst[(2 * hh) * 128 + c4 * 4 + d]     = acc0[d];
        dst[(2 * hh + 1) * 128 + c4 * 4 + d] = acc1[d];
    }
}

// ---------------------------------------------------------------------------
// Epilogue: copy o, rotate op back, norms.  (ov stride = 64)
// ---------------------------------------------------------------------------
__global__ void postproc_kernel(const float* __restrict__ ov,
                                const float* __restrict__ rot,
                                const float* __restrict__ trans,
                                float* __restrict__ cat)
{
    const int i = blockIdx.x;
    const int tid = threadIdx.x;   // 192
    float* ci = cat + (size_t)i * 2112;
    {
        int h = tid >> 4, c = tid & 15;
        ci[tid] = ov[((size_t)(h * NN) + i) * 64 + c];
    }
    if (tid < 96) {
        int h = tid >> 3, pp = tid & 7;
        const float* base = ov + ((size_t)(h * NN) + i) * 64 + 16 + pp * 3;
        float vx = base[0] - trans[i*3+0];
        float vy = base[1] - trans[i*3+1];
        float vz = base[2] - trans[i*3+2];
        const float* R = rot + i * 9;
        float ox = R[0]*vx + R[3]*vy + R[6]*vz;
        float oy = R[1]*vx + R[4]*vy + R[7]*vz;
        float oz = R[2]*vx + R[5]*vy + R[8]*vz;
        ci[192 + h*24 + pp*3 + 0] = ox;
        ci[192 + h*24 + pp*3 + 1] = oy;
        ci[192 + h*24 + pp*3 + 2] = oz;
        ci[480 + h*8 + pp] = sqrtf(ox*ox + oy*oy + oz*oz + 1e-8f);
    }
}

// ---------------------------------------------------------------------------
// 3-way split-K reduce + bias + optional relu (elementwise).
// ---------------------------------------------------------------------------
__global__ void reduce_act_kernel(const float* __restrict__ part,
                                  const float* __restrict__ bias,
                                  float* __restrict__ y, int relu)
{
    int idx = blockIdx.x * blockDim.x + threadIdx.x;
    const size_t SP = (size_t)NN * CS;
    int c = idx % CS;
    float v = part[idx] + part[SP + idx] + part[2*SP + idx] + bias[c];
    y[idx] = relu ? fmaxf(v, 0.f) : v;
}

// ---------------------------------------------------------------------------
// 3-way split-K reduce + bias + residual + LayerNorm.  Block/row, 128 thr.
// ---------------------------------------------------------------------------
__global__ void reduce_ln_kernel(const float* __restrict__ part,
                                 const float* __restrict__ bias,
                                 const float* __restrict__ res,
                                 const float* __restrict__ g,
                                 const float* __restrict__ b,
                                 float* __restrict__ y)
{
    __shared__ float rs[128], rs2[128];
    const int i = blockIdx.x, tid = threadIdx.x;
    const size_t SP = (size_t)NN * CS;
    float v[3];
    float sm = 0.f, sm2 = 0.f;
    #pragma unroll
    for (int k = 0; k < 3; k++) {
        int c = tid + k * 128;
        size_t o = (size_t)i * CS + c;
        float x = part[o] + part[SP + o] + part[2*SP + o] + bias[c] + res[o];
        v[k] = x;
        sm += x; sm2 += x * x;
    }
    rs[tid] = sm; rs2[tid] = sm2;
    __syncthreads();
    for (int st = 64; st > 0; st >>= 1) {
        if (tid < st) { rs[tid] += rs[tid + st]; rs2[tid] += rs2[tid + st]; }
        __syncthreads();
    }
    float mean = rs[0] * (1.0f / CS);
    float var  = rs2[0] * (1.0f / CS) - mean * mean;
    float inv  = rsqrtf(var + 1e-5f);
    #pragma unroll
    for (int k = 0; k < 3; k++) {
        int c = tid + k * 128;
        y[(size_t)i * CS + c] = (v[k] - mean) * inv * g[c] + b[c];
    }
}

// ---------------------------------------------------------------------------
// Fused backbone projection + quaternion frame update.
// ---------------------------------------------------------------------------
__global__ void bb_finalize_kernel(const float* __restrict__ s2,
                                   const float* __restrict__ bb_w,
                                   const float* __restrict__ bb_b,
                                   const float* __restrict__ rot,
                                   const float* __restrict__ trans,
                                   float* __restrict__ out)
{
    const int i = blockIdx.x;
    const int tid = threadIdx.x;
    const int w = tid >> 5, lane = tid & 31;
    __shared__ float u[6];
    const float* row = s2 + (size_t)i * CS;
    float sum = 0.f;
    for (int c = lane; c < CS; c += 32)
        sum = fmaf(row[c], bb_w[c * 6 + w], sum);
    #pragma unroll
    for (int o = 16; o > 0; o >>= 1)
        sum += __shfl_xor_sync(0xffffffffu, sum, o);
    if (lane == 0) u[w] = sum + bb_b[w];
    __syncthreads();
    if (tid == 0) {
        float bx = u[0], by = u[1], bz = u[2];
        float inv = rsqrtf(1.f + bx*bx + by*by + bz*bz);
        float qw = inv, x = bx * inv, y = by * inv, z = bz * inv;
        float Ru[9] = {
            1 - 2*(y*y + z*z), 2*(x*y - qw*z),    2*(x*z + qw*y),
            2*(x*y + qw*z),    1 - 2*(x*x + z*z), 2*(y*z - qw*x),
            2*(x*z - qw*y),    2*(y*z + qw*x),    1 - 2*(x*x + y*y)};
        const float* R = rot + i * 9;
        float* ro = out + NN * CS + i * 9;
        #pragma unroll
        for (int r = 0; r < 3; r++)
            #pragma unroll
            for (int c = 0; c < 3; c++)
                ro[r*3+c] = R[r*3+0]*Ru[0*3+c] + R[r*3+1]*Ru[1*3+c]
                          + R[r*3+2]*Ru[2*3+c];
        float tx = u[3], ty = u[4], tz = u[5];
        float* to = out + NN * CS + NN * 9 + i * 3;
        #pragma unroll
        for (int r = 0; r < 3; r++)
            to[r] = R[r*3+0]*tx + R[r*3+1]*ty + R[r*3+2]*tz + trans[i*3+r];
    }
}

// ---------------------------------------------------------------------------
static cudaStream_t g_s1 = nullptr;
static cudaEvent_t  g_ev0, g_ev1, g_ev2, g_ev3;

extern "C" void kernel_launch(void* const* d_in, const int* in_sizes, int n_in,
                              void* d_out, int out_size)
{
    if (!g_s1) {
        cudaStreamCreateWithFlags(&g_s1, cudaStreamNonBlocking);
        cudaEventCreateWithFlags(&g_ev0, cudaEventDisableTiming);
        cudaEventCreateWithFlags(&g_ev1, cudaEventDisableTiming);
        cudaEventCreateWithFlags(&g_ev2, cudaEventDisableTiming);
        cudaEventCreateWithFlags(&g_ev3, cudaEventDisableTiming);
    }

    const float* s      = (const float*)d_in[0];
    const float* p      = (const float*)d_in[1];
    const float* rot    = (const float*)d_in[2];
    const float* trans  = (const float*)d_in[3];
    const float* mask   = (const float*)d_in[4];
    const float* w_q    = (const float*)d_in[5];
    const float* b_q    = (const float*)d_in[6];
    const float* w_kv   = (const float*)d_in[7];
    const float* b_kv   = (const float*)d_in[8];
    const float* w_qp   = (const float*)d_in[9];
    const float* b_qp   = (const float*)d_in[10];
    const float* w_kvp  = (const float*)d_in[11];
    const float* b_kvp  = (const float*)d_in[12];
    const float* w_b    = (const float*)d_in[13];
    const float* b_b    = (const float*)d_in[14];
    const float* head_w = (const float*)d_in[15];
    const float* w_o    = (const float*)d_in[16];
    const float* b_o    = (const float*)d_in[17];
    const float* ln1_g  = (const float*)d_in[18];
    const float* ln1_b  = (const float*)d_in[19];
    const float* tw1    = (const float*)d_in[20];
    const float* tb1    = (const float*)d_in[21];
    const float* tw2    = (const float*)d_in[22];
    const float* tb2    = (const float*)d_in[23];
    const float* tw3    = (const float*)d_in[24];
    const float* tb3    = (const float*)d_in[25];
    const float* ln2_g  = (const float*)d_in[26];
    const float* ln2_b  = (const float*)d_in[27];
    const float* bb_w   = (const float*)d_in[28];
    const float* bb_b   = (const float*)d_in[29];
    float* out = (float*)d_out;

    float *wcat, *bcat, *proj, *ppart, *kpk, *kppk, *vpk, *a_, *ov_, *cat_,
          *part, *x2, *x3, *x1;
    cudaGetSymbolAddress((void**)&wcat, g_wcat);
    cudaGetSymbolAddress((void**)&bcat, g_bcat);
    cudaGetSymbolAddress((void**)&proj, g_proj);
    cudaGetSymbolAddress((void**)&ppart, g_ppart);
    cudaGetSymbolAddress((void**)&kpk,  g_kpack);
    cudaGetSymbolAddress((void**)&kppk, g_kppack);
    cudaGetSymbolAddress((void**)&vpk,  g_vpack);
    cudaGetSymbolAddress((void**)&a_,   g_att);
    cudaGetSymbolAddress((void**)&ov_,  g_ov);
    cudaGetSymbolAddress((void**)&cat_, g_cat);
    cudaGetSymbolAddress((void**)&part, g_part);
    cudaGetSymbolAddress((void**)&x2,   g_x2);
    cudaGetSymbolAddress((void**)&x3,   g_x3);
    cudaGetSymbolAddress((void**)&x1,   g_x1);

    // ---- fork: bias planes on side stream (independent of proj chain) -----
    cudaEventRecord(g_ev0, 0);
    cudaStreamWaitEvent(g_s1, g_ev0, 0);
    bias_kernel<<<1024, 256, 0, g_s1>>>(p, w_b, b_b, a_);
    cudaEventRecord(g_ev1, g_s1);

    // ---- main stream: projections (split-K 2 -> 288 blocks) ---------------
    pack_w_kernel<<<(CS * LDP / 4 + LDP / 4 + 255) / 256, 256>>>(
        w_q, b_q, w_kv, b_kv, w_qp, b_qp, w_kvp, b_kvp, wcat, bcat);
    gemm64_kernel<<<dim3(LDP / 64, 8, 2), 128>>>(
        s, CS, 0, 192,
        wcat, LDP, 0, (long long)192 * LDP,
        nullptr,
        ppart, LDP, 0, (long long)NN * LDP,
        192, 2);
    reduce_proj_kernel<<<(NN * LDP / 4) / 256, 256>>>(ppart, bcat, proj);
    {
        const int TOT = HDS*NN*16 + HDS*NN*16 + HDS*NN*4 + HDS*NN*8 + NN*48;
        rotpack_kernel<<<(TOT + 255) / 256, 256>>>(proj, rot, trans,
                                                   kpk, kppk, vpk);
    }

    // join bias, then fused logits+softmax
    cudaStreamWaitEvent(0, g_ev1, 0);
    logits_softmax_kernel<<<dim3(64, HDS), 256>>>(proj, kpk, kppk, mask,
                                                  head_w, a_);

    // ---- fork: o_pair on side stream; ov gemm + postproc on main ----------
    cudaEventRecord(g_ev2, 0);
    cudaStreamWaitEvent(g_s1, g_ev2, 0);
    opair_kernel<<<NN, 192, 0, g_s1>>>(a_, p, cat_);
    cudaEventRecord(g_ev3, g_s1);

    // batched ov GEMM (z = 12 batches, KS = 1)
    gemm64_kernel<<<dim3(1, 8, HDS), 128>>>(
        a_, NN, (long long)NN * NN, 0,
        vpk, 64, (long long)NN * 64, 0,
        nullptr,
        ov_, 64, (long long)NN * 64, 0,
        NN, 1);
    postproc_kernel<<<NN, 192>>>(ov_, rot, trans, cat_);
    cudaStreamWaitEvent(0, g_ev3, 0);

    // ---- output projection (split-K 3) + fused reduce/residual/LN1 --------
    gemm64_kernel<<<dim3(6, 8, 3), 128>>>(
        cat_, 2112, 0, 704,
        w_o, CS, 0, (long long)704 * CS,
        nullptr,
        part, CS, 0, (long long)NN * CS,
        704, 3);
    reduce_ln_kernel<<<NN, 128>>>(part, b_o, s, ln1_g, ln1_b, x2);

    // ---- transition MLP (each GEMM split-K 3) ------------------------------
    gemm64_kernel<<<dim3(6, 8, 3), 128>>>(
        x2, CS, 0, 128,
        tw1, CS, 0, (long long)128 * CS,
        nullptr,
        part, CS, 0, (long long)NN * CS,
        128, 3);
    reduce_act_kernel<<<(NN * CS) / 256, 256>>>(part, tb1, x3, 1);
    gemm64_kernel<<<dim3(6, 8, 3), 128>>>(
        x3, CS, 0, 128,
        tw2, CS, 0, (long long)128 * CS,
        nullptr,
        part, CS, 0, (long long)NN * CS,
        128, 3);
    reduce_act_kernel<<<(NN * CS) / 256, 256>>>(part, tb2, x1, 1);
    gemm64_kernel<<<dim3(6, 8, 3), 128>>>(
        x1, CS, 0, 128,
        tw3, CS, 0, (long long)128 * CS,
        nullptr,
        part, CS, 0, (long long)NN * CS,
        128, 3);
    reduce_ln_kernel<<<NN, 128>>>(part, tb3, x2, ln2_g, ln2_b, out);

    // ---- backbone update ----------------------------------------------------
    bb_finalize_kernel<<<NN, 192>>>(out, bb_w, bb_b, rot, trans, out);
}

// round 9
// speedup vs baseline: 3.7393x; 1.0206x over previous
#include <cuda_runtime.h>
#include <math.h>

// ---------------------------------------------------------------------------
// StructureLayer (IPA) — B=1, N=512, H=12, C_S=384, C_P=128, C_H=16,
// P_QK=4, P_V=8.  Output: [ s2 (512*384) | rot_new (512*9) | trans_new (512*3) ]
// ---------------------------------------------------------------------------

#define NN 512
#define CS 384
#define CP 128
#define HDS 12

// proj row layout: [ q(192) | kv(384) | qp(144) | kvp(432) ]  = 1152
#define LDP 1152
#define OFF_Q   0
#define OFF_KV  192
#define OFF_QP  576
#define OFF_KVP 720

#define SQK 0.14433756729740643f    // sqrt(1/48)
#define SB  0.5773502691896258f     // sqrt(1/3)
#define SHW 0.13608276348795434f    // sqrt(1/54)

// ---- scratch (device globals) ----------------------------------------------
__device__ float g_wcat[CS * LDP];
__device__ float g_bcat[LDP];
__device__ float g_proj[NN * LDP];       // only q / qp sections used
__device__ float g_ppart[2 * NN * LDP];  // proj split-K partials
__device__ float g_kpack[HDS * NN * 16];
__device__ float g_kppack[HDS * NN * 12];
__device__ float g_vpack[HDS * NN * 64]; // [h][j][ v(16) | vp(24) | pad=0 ]
__device__ float g_att[HDS * NN * NN];   // bias planes, then probs [h][i][j]
__device__ float g_ov[HDS * NN * 64];    // [h][i][ o(16) | op_raw(24) | pad ]
__device__ float g_cat[NN * 2112];
__device__ float g_part[3 * NN * CS];    // split-K partials (A)
__device__ float g_partB[3 * NN * CS];   // split-K partials (B)
__device__ float g_x2[NN * CS];

// ---------------------------------------------------------------------------
// tf32 helpers
// ---------------------------------------------------------------------------
__device__ __forceinline__ unsigned cvt_tf32(float x)
{
    unsigned r;
    asm("cvt.rna.tf32.f32 %0, %1;" : "=r"(r) : "f"(x));
    return r;
}

__device__ __forceinline__ void mma_tf32(float* d, const unsigned* a,
                                         const unsigned* b)
{
    asm volatile(
        "mma.sync.aligned.m16n8k8.row.col.f32.tf32.tf32.f32 "
        "{%0,%1,%2,%3}, {%4,%5,%6,%7}, {%8,%9}, {%0,%1,%2,%3};\n"
        : "+f"(d[0]), "+f"(d[1]), "+f"(d[2]), "+f"(d[3])
        : "r"(a[0]), "r"(a[1]), "r"(a[2]), "r"(a[3]),
          "r"(b[0]), "r"(b[1]));
}

// A-load: optionally reduce 3 split-K partials + bias + relu on the fly.
__device__ __forceinline__ float4 ldA4(const float* p,
                                       const float* abias, int bcol,
                                       long long SP, int arelu)
{
    float4 v = *(const float4*)p;
    if (abias) {
        float4 v1 = *(const float4*)(p + SP);
        float4 v2 = *(const float4*)(p + 2 * SP);
        float4 bb = *(const float4*)(abias + bcol);
        v.x += v1.x + v2.x + bb.x;
        v.y += v1.y + v2.y + bb.y;
        v.z += v1.z + v2.z + bb.z;
        v.w += v1.w + v2.w + bb.w;
        if (arelu) {
            v.x = fmaxf(v.x, 0.f); v.y = fmaxf(v.y, 0.f);
            v.z = fmaxf(v.z, 0.f); v.w = fmaxf(v.w, 0.f);
        }
    }
    return v;
}

// ---------------------------------------------------------------------------
// Pack projection weights/biases into one (384 x 1152) matrix. float4 copies.
// ---------------------------------------------------------------------------
__global__ void pack_w_kernel(const float* __restrict__ w_q,  const float* __restrict__ b_q,
                              const float* __restrict__ w_kv, const float* __restrict__ b_kv,
                              const float* __restrict__ w_qp, const float* __restrict__ b_qp,
                              const float* __restrict__ w_kvp,const float* __restrict__ b_kvp,
                              float* __restrict__ wcat, float* __restrict__ bcat)
{
    const int NW4 = CS * LDP / 4;
    int idx = blockIdx.x * blockDim.x + threadIdx.x;
    if (idx < NW4) {
        int r = idx / (LDP / 4), c = (idx % (LDP / 4)) * 4;
        float4 v;
        if      (c < 192) v = *(const float4*)(w_q  + r * 192 + c);
        else if (c < 576) v = *(const float4*)(w_kv + r * 384 + (c - 192));
        else if (c < 720) v = *(const float4*)(w_qp + r * 144 + (c - 576));
        else              v = *(const float4*)(w_kvp + r * 432 + (c - 720));
        *(float4*)(wcat + r * LDP + c) = v;
    } else if (idx < NW4 + LDP / 4) {
        int c = (idx - NW4) * 4;
        float4 v;
        if      (c < 192) v = *(const float4*)(b_q  + c);
        else if (c < 576) v = *(const float4*)(b_kv + (c - 192));
        else if (c < 720) v = *(const float4*)(b_qp + (c - 576));
        else              v = *(const float4*)(b_kvp + (c - 720));
        *(float4*)(bcat + c) = v;
    }
}

// ---------------------------------------------------------------------------
// tf32 tensor-core GEMM: 64x64 tile, 128 threads, double-buffered smem.
// z = zb*KS + zk (batch x split-K).  Optional fused A-side 3-partial
// reduce + bias + relu (abias != nullptr).
// ---------------------------------------------------------------------------
__global__ void __launch_bounds__(128)
gemm64_kernel(const float* __restrict__ A, int lda, long long sAz, long long sAk,
              const float* __restrict__ B, int ldb, long long sBz, long long sBk,
              const float* __restrict__ bias,
              float* __restrict__ C, int ldc, long long sCz, long long sCk,
              int K, int KS,
              const float* __restrict__ abias, long long aSP, int aKoff, int arelu)
{
    const int zb = blockIdx.z / KS, zk = blockIdx.z % KS;
    A += (size_t)zb * (size_t)sAz + (size_t)zk * (size_t)sAk;
    B += (size_t)zb * (size_t)sBz + (size_t)zk * (size_t)sBk;
    C += (size_t)zb * (size_t)sCz + (size_t)zk * (size_t)sCk;
    const int azoff = zk * aKoff;

    __shared__ __align__(16) unsigned As[2][16][72];
    __shared__ __align__(16) unsigned Bs[2][16][72];

    const int bm = blockIdx.y * 64, bn = blockIdx.x * 64;
    const int tid = threadIdx.x;
    const int lane = tid & 31, warp = tid >> 5;
    const int g = lane >> 2, t4 = lane & 3;
    const int wm = (warp >> 1) * 32, wn = (warp & 1) * 32;

    const int ar = tid >> 2, ak = (tid & 3) * 4;
    const int br = tid >> 4, bc = (tid & 15) * 4;

    const float* Ab = A + (size_t)bm * lda;

    float4 ra0, ra1, rb0, rb1;
    ra0 = ldA4(Ab + (size_t)ar * lda + ak, abias, azoff + ak, aSP, arelu);
    ra1 = ldA4(Ab + (size_t)(ar + 32) * lda + ak, abias, azoff + ak, aSP, arelu);
    rb0 = *(const float4*)(B + (size_t)br * ldb + bn + bc);
    rb1 = *(const float4*)(B + (size_t)(br + 8) * ldb + bn + bc);

    As[0][ak+0][ar] = cvt_tf32(ra0.x); As[0][ak+1][ar] = cvt_tf32(ra0.y);
    As[0][ak+2][ar] = cvt_tf32(ra0.z); As[0][ak+3][ar] = cvt_tf32(ra0.w);
    As[0][ak+0][ar+32] = cvt_tf32(ra1.x); As[0][ak+1][ar+32] = cvt_tf32(ra1.y);
    As[0][ak+2][ar+32] = cvt_tf32(ra1.z); As[0][ak+3][ar+32] = cvt_tf32(ra1.w);
    {
        uint4 u0 = make_uint4(cvt_tf32(rb0.x), cvt_tf32(rb0.y),
                              cvt_tf32(rb0.z), cvt_tf32(rb0.w));
        uint4 u1 = make_uint4(cvt_tf32(rb1.x), cvt_tf32(rb1.y),
                              cvt_tf32(rb1.z), cvt_tf32(rb1.w));
        *(uint4*)&Bs[0][br][bc]     = u0;
        *(uint4*)&Bs[0][br + 8][bc] = u1;
    }
    __syncthreads();

    float acc[2][4][4];
    #pragma unroll
    for (int mt = 0; mt < 2; mt++)
        #pragma unroll
        for (int nt = 0; nt < 4; nt++)
            #pragma unroll
            for (int r = 0; r < 4; r++) acc[mt][nt][r] = 0.f;

    int buf = 0;
    for (int k0 = 0; k0 < K; k0 += 16) {
        const bool more = (k0 + 16) < K;
        if (more) {
            int kc = k0 + 16 + ak;
            ra0 = ldA4(Ab + (size_t)ar * lda + kc, abias, azoff + kc, aSP, arelu);
            ra1 = ldA4(Ab + (size_t)(ar + 32) * lda + kc, abias, azoff + kc, aSP, arelu);
            rb0 = *(const float4*)(B + (size_t)(k0 + 16 + br) * ldb + bn + bc);
            rb1 = *(const float4*)(B + (size_t)(k0 + 16 + br + 8) * ldb + bn + bc);
        }
        #pragma unroll
        for (int kk = 0; kk < 16; kk += 8) {
            unsigned af[2][4], bf[4][2];
            #pragma unroll
            for (int mt = 0; mt < 2; mt++) {
                int m0 = wm + mt * 16 + g;
                af[mt][0] = As[buf][kk + t4][m0];
                af[mt][1] = As[buf][kk + t4][m0 + 8];
                af[mt][2] = As[buf][kk + 4 + t4][m0];
                af[mt][3] = As[buf][kk + 4 + t4][m0 + 8];
            }
            #pragma unroll
            for (int nt = 0; nt < 4; nt++) {
                int n0 = wn + nt * 8 + g;
                bf[nt][0] = Bs[buf][kk + t4][n0];
                bf[nt][1] = Bs[buf][kk + 4 + t4][n0];
            }
            #pragma unroll
            for (int mt = 0; mt < 2; mt++)
                #pragma unroll
                for (int nt = 0; nt < 4; nt++)
                    mma_tf32(acc[mt][nt], af[mt], bf[nt]);
        }
        if (more) {
            buf ^= 1;
            __syncthreads();
            As[buf][ak+0][ar] = cvt_tf32(ra0.x); As[buf][ak+1][ar] = cvt_tf32(ra0.y);
            As[buf][ak+2][ar] = cvt_tf32(ra0.z); As[buf][ak+3][ar] = cvt_tf32(ra0.w);
            As[buf][ak+0][ar+32] = cvt_tf32(ra1.x); As[buf][ak+1][ar+32] = cvt_tf32(ra1.y);
            As[buf][ak+2][ar+32] = cvt_tf32(ra1.z); As[buf][ak+3][ar+32] = cvt_tf32(ra1.w);
            uint4 u0 = make_uint4(cvt_tf32(rb0.x), cvt_tf32(rb0.y),
                                  cvt_tf32(rb0.z), cvt_tf32(rb0.w));
            uint4 u1 = make_uint4(cvt_tf32(rb1.x), cvt_tf32(rb1.y),
                                  cvt_tf32(rb1.z), cvt_tf32(rb1.w));
            *(uint4*)&Bs[buf][br][bc]     = u0;
            *(uint4*)&Bs[buf][br + 8][bc] = u1;
            __syncthreads();
        }
    }

    #pragma unroll
    for (int mt = 0; mt < 2; mt++) {
        int row0 = bm + wm + mt * 16 + g;
        #pragma unroll
        for (int nt = 0; nt < 4; nt++) {
            int col = bn + wn + nt * 8 + t4 * 2;
            float b0 = 0.f, b1 = 0.f;
            if (bias) { b0 = bias[col]; b1 = bias[col + 1]; }
            float2 v0 = make_float2(acc[mt][nt][0] + b0, acc[mt][nt][1] + b1);
            float2 v1 = make_float2(acc[mt][nt][2] + b0, acc[mt][nt][3] + b1);
            *(float2*)(C + (size_t)row0 * ldc + col)       = v0;
            *(float2*)(C + (size_t)(row0 + 8) * ldc + col) = v1;
        }
    }
}

// ---------------------------------------------------------------------------
// Fused proj split-K reduce + bias + rotate + repack.
// Reads ppart (2 partials) + bcat directly; writes q/qp into proj (for the
// logits kernel) and kpack / kppack / vpack head-major.
// ---------------------------------------------------------------------------
__global__ void rotpack_kernel(const float* __restrict__ ppart,
                               const float* __restrict__ bcat,
                               const float* __restrict__ rot,
                               const float* __restrict__ trans,
                               float* __restrict__ proj,
                               float* __restrict__ kpack,
                               float* __restrict__ kppack,
                               float* __restrict__ vpack)
{
    const long long SP = (long long)NN * LDP;
    const int S0 = NN * 48;                 // q, float4 units
    const int S1 = S0 + HDS * NN * 4;       // kpack, float4 units
    const int S2 = S1 + HDS * NN * 4;       // vpack v, float4 units
    const int S3 = S2 + HDS * NN * 4;       // kpp triples
    const int S4 = S3 + HDS * NN * 8;       // vp triples
    const int S5 = S4 + NN * 48;            // qp triples
    int idx = blockIdx.x * blockDim.x + threadIdx.x;

    if (idx < S0) {
        int j = idx / 48, c = (idx % 48) * 4;
        const float* p0 = ppart + (size_t)j * LDP + c;
        float4 a = *(const float4*)p0;
        float4 b = *(const float4*)(p0 + SP);
        float4 bb = *(const float4*)(bcat + c);
        *(float4*)(proj + (size_t)j * LDP + c) =
            make_float4(a.x+b.x+bb.x, a.y+b.y+bb.y, a.z+b.z+bb.z, a.w+b.w+bb.w);
    } else if (idx < S1) {
        int t = idx - S0;
        int c = (t & 3) * 4, j = (t >> 2) & 511, h = t >> 11;
        int col = OFF_KV + h * 32 + c;
        const float* p0 = ppart + (size_t)j * LDP + col;
        float4 a = *(const float4*)p0;
        float4 b = *(const float4*)(p0 + SP);
        float4 bb = *(const float4*)(bcat + col);
        *(float4*)(kpack + (((size_t)h * NN) + j) * 16 + c) =
            make_float4(a.x+b.x+bb.x, a.y+b.y+bb.y, a.z+b.z+bb.z, a.w+b.w+bb.w);
    } else if (idx < S2) {
        int t = idx - S1;
        int c = (t & 3) * 4, j = (t >> 2) & 511, h = t >> 11;
        int col = OFF_KV + h * 32 + 16 + c;
        const float* p0 = ppart + (size_t)j * LDP + col;
        float4 a = *(const float4*)p0;
        float4 b = *(const float4*)(p0 + SP);
        float4 bb = *(const float4*)(bcat + col);
        *(float4*)(vpack + (((size_t)h * NN) + j) * 64 + c) =
            make_float4(a.x+b.x+bb.x, a.y+b.y+bb.y, a.z+b.z+bb.z, a.w+b.w+bb.w);
    } else if (idx < S4) {
        // triples needing rotation (kpp / vp)
        int t = idx - S2;
        int pp, j, h;
        float* dst;
        if (t < HDS * NN * 4) {
            pp = t & 3; j = (t >> 2) & 511; h = t >> 11;
            dst = kppack + (((size_t)h * NN) + j) * 12 + pp * 3;
        } else {
            t -= HDS * NN * 4;
            int vp = t & 7; j = (t >> 3) & 511; h = t >> 12;
            pp = 4 + vp;
            dst = vpack + (((size_t)h * NN) + j) * 64 + 16 + vp * 3;
        }
        int col = OFF_KVP + h * 36 + pp * 3;
        const float* p0 = ppart + (size_t)j * LDP + col;
        float x = p0[0] + p0[SP + 0] + bcat[col + 0];
        float y = p0[1] + p0[SP + 1] + bcat[col + 1];
        float z = p0[2] + p0[SP + 2] + bcat[col + 2];
        const float* R = rot + j * 9;
        const float* tr = trans + j * 3;
        dst[0] = R[0]*x + R[1]*y + R[2]*z + tr[0];
        dst[1] = R[3]*x + R[4]*y + R[5]*z + tr[1];
        dst[2] = R[6]*x + R[7]*y + R[8]*z + tr[2];
    } else if (idx < S5) {
        int t = idx - S4;
        int pt = t % 48, j = t / 48;
        int col = OFF_QP + pt * 3;
        const float* p0 = ppart + (size_t)j * LDP + col;
        float x = p0[0] + p0[SP + 0] + bcat[col + 0];
        float y = p0[1] + p0[SP + 1] + bcat[col + 1];
        float z = p0[2] + p0[SP + 2] + bcat[col + 2];
        const float* R = rot + j * 9;
        const float* tr = trans + j * 3;
        float* pv = proj + (size_t)j * LDP + col;
        pv[0] = R[0]*x + R[1]*y + R[2]*z + tr[0];
        pv[1] = R[3]*x + R[4]*y + R[5]*z + tr[1];
        pv[2] = R[6]*x + R[7]*y + R[8]*z + tr[2];
    }
}

// ---------------------------------------------------------------------------
// bias planes: att[h][i][j] = (p[i,j,:]·w_b[:,h] + b_b[h]) * sqrt(1/3)
// ---------------------------------------------------------------------------
__global__ void bias_kernel(const float* __restrict__ p,
                            const float* __restrict__ w_b,
                            const float* __restrict__ b_b,
                            float* __restrict__ att)
{
    __shared__ float wbt[HDS][CP];
    __shared__ float bbs[HDS];
    const int tid = threadIdx.x;
    #pragma unroll
    for (int k = 0; k < 6; k++) {
        int e = tid + k * 256;
        int h = e / CP, c = e % CP;
        wbt[h][c] = w_b[c * HDS + h];
    }
    if (tid < HDS) bbs[tid] = b_b[tid];
    __syncthreads();

    const int gw = blockIdx.x * 8 + (tid >> 5);
    const int lane = tid & 31;
    const int i = gw >> 4;
    const int j = ((gw & 15) << 5) + lane;

    float acc[HDS];
    #pragma unroll
    for (int h = 0; h < HDS; h++) acc[h] = 0.f;

    const float4* prow = (const float4*)(p + ((size_t)i * NN + j) * CP);
    #pragma unroll 4
    for (int c4 = 0; c4 < 32; c4++) {
        float4 pv = prow[c4];
        #pragma unroll
        for (int h = 0; h < HDS; h++) {
            float4 wv = ((const float4*)&wbt[h][0])[c4];
            acc[h] = fmaf(pv.x, wv.x,
                     fmaf(pv.y, wv.y,
                     fmaf(pv.z, wv.z,
                     fmaf(pv.w, wv.w, acc[h]))));
        }
    }
    #pragma unroll
    for (int h = 0; h < HDS; h++)
        att[((size_t)(h * NN) + i) * NN + j] = (acc[h] + bbs[h]) * SB;
}

// ---------------------------------------------------------------------------
// Fused logits + softmax.  Block = (i-tile of 8, head h).  256 threads.
// Thread map: jl = tid & 63 (coalesced bias reads), ig = tid >> 6.
// ---------------------------------------------------------------------------
__global__ void logits_softmax_kernel(const float* __restrict__ proj,
                                      const float* __restrict__ kpack,
                                      const float* __restrict__ kppack,
                                      const float* __restrict__ mask,
                                      const float* __restrict__ head_w,
                                      float* __restrict__ att)
{
    const int i0 = blockIdx.x * 8, h = blockIdx.y;
    const int tid = threadIdx.x;

    __shared__ float att_s[8][NN];
    __shared__ float kt[64][17];
    __shared__ float kpt[64][13];
    __shared__ float q_s[8][17];
    __shared__ float qp_s[8][13];
    __shared__ float m_i[8];
    __shared__ float sh_hw;

    if (tid < 128) {
        int il = tid >> 4, c = tid & 15;
        q_s[il][c] = proj[(size_t)(i0 + il) * LDP + OFF_Q + h * 16 + c];
    } else if (tid < 224) {
        int e = tid - 128;
        int il = e / 12, c = e % 12;
        qp_s[il][c] = proj[(size_t)(i0 + il) * LDP + OFF_QP + h * 12 + c];
    } else if (tid < 232) {
        m_i[tid - 224] = mask[i0 + (tid - 224)];
    } else if (tid == 232) {
        float w = head_w[h];
        float sp = fmaxf(w, 0.f) + log1pf(expf(-fabsf(w)));
        sh_hw = sp * SHW;
    }

    const float* kb  = kpack  + (size_t)(h * NN) * 16;
    const float* kpb = kppack + (size_t)(h * NN) * 12;

    const int jl = tid & 63, ig = tid >> 6;

    for (int j0 = 0; j0 < NN; j0 += 64) {
        #pragma unroll
        for (int k = 0; k < 4; k++) {
            int e = tid + k * 256;
            int r = e >> 4, c = e & 15;
            kt[r][c] = kb[(size_t)(j0 + r) * 16 + c];
        }
        #pragma unroll
        for (int k = 0; k < 3; k++) {
            int e = tid + k * 256;
            if (e < 768) {
                int r = e / 12, c = e % 12;
                kpt[r][c] = kpb[(size_t)(j0 + r) * 12 + c];
            }
        }
        __syncthreads();

        float mj = mask[j0 + jl];
        float hw = sh_hw;
        #pragma unroll
        for (int ii = 0; ii < 2; ii++) {
            int il = ig * 2 + ii;
            float qk = 0.f;
            #pragma unroll
            for (int c = 0; c < 16; c++) qk = fmaf(q_s[il][c], kt[jl][c], qk);
            float d2 = 0.f;
            #pragma unroll
            for (int d = 0; d < 12; d++) {
                float dd = qp_s[il][d] - kpt[jl][d];
                d2 = fmaf(dd, dd, d2);
            }
            float bias = att[((size_t)(h * NN) + i0 + il) * NN + j0 + jl];
            att_s[il][j0 + jl] = qk * SQK + bias - 0.5f * hw * d2
                               + (m_i[il] * mj - 1.0f) * 100000.0f;
        }
        __syncthreads();
    }

    const int w = tid >> 5, lane = tid & 31;
    float vals[16];
    float vmax = -1e30f;
    #pragma unroll
    for (int k = 0; k < 16; k++) {
        vals[k] = att_s[w][lane + 32 * k];
        vmax = fmaxf(vmax, vals[k]);
    }
    #pragma unroll
    for (int o = 16; o > 0; o >>= 1)
        vmax = fmaxf(vmax, __shfl_xor_sync(0xffffffffu, vmax, o));
    float sum = 0.f;
    #pragma unroll
    for (int k = 0; k < 16; k++) { vals[k] = expf(vals[k] - vmax); sum += vals[k]; }
    #pragma unroll
    for (int o = 16; o > 0; o >>= 1)
        sum += __shfl_xor_sync(0xffffffffu, sum, o);
    float inv = 1.0f / sum;
    float* arow = att + ((size_t)(h * NN) + i0 + w) * NN;
    #pragma unroll
    for (int k = 0; k < 16; k++)
        arow[lane + 32 * k] = vals[k] * inv;
}

// ---------------------------------------------------------------------------
// o_pair[i,h,c] = sum_j a[h,i,j]*p[i,j,c]  -> cat[i][576 + h*128 + c]
// ---------------------------------------------------------------------------
__global__ void opair_kernel(const float* __restrict__ att,
                             const float* __restrict__ p,
                             float* __restrict__ cat)
{
    const int i = blockIdx.x;
    __shared__ float as[HDS][NN];
    __shared__ float ps[32][128];
    const int tid = threadIdx.x;     // 192

    for (int idx = tid; idx < HDS * NN; idx += 192) {
        int h = idx >> 9, j = idx & 511;
        as[h][j] = att[((size_t)(h * NN + i)) * NN + j];
    }

    const int c4 = tid & 31;
    const int hh = tid >> 5;
    float acc0[4] = {0,0,0,0}, acc1[4] = {0,0,0,0};
    const float* pi = p + (size_t)i * NN * CP;

    for (int j0 = 0; j0 < NN; j0 += 32) {
        for (int idx = tid; idx < 32 * 32; idx += 192) {
            int jj = idx >> 5, cc = idx & 31;
            ((float4*)&ps[jj][0])[cc] =
                ((const float4*)(pi + (size_t)(j0 + jj) * CP))[cc];
        }
        __syncthreads();
        #pragma unroll 8
        for (int jj = 0; jj < 32; jj++) {
            float a0 = as[2 * hh][j0 + jj];
            float a1 = as[2 * hh + 1][j0 + jj];
            float4 pv = ((const float4*)&ps[jj][0])[c4];
            acc0[0] += a0 * pv.x; acc0[1] += a0 * pv.y;
            acc0[2] += a0 * pv.z; acc0[3] += a0 * pv.w;
            acc1[0] += a1 * pv.x; acc1[1] += a1 * pv.y;
            acc1[2] += a1 * pv.z; acc1[3] += a1 * pv.w;
        }
        __syncthreads();
    }
    float* dst = cat + (size_t)i * 2112 + 576;
    #pragma unroll
    for (int d = 0; d < 4; d++) {
        dst[(2 * hh) * 128 + c4 * 4 + d]     = acc0[d];
        dst[(2 * hh + 1) * 128 + c4 * 4 + d] = acc1[d];
    }
}

// ---------------------------------------------------------------------------
// Epilogue: copy o, rotate op back, norms.  (ov stride = 64)
// ---------------------------------------------------------------------------
__global__ void postproc_kernel(const float* __restrict__ ov,
                                const float* __restrict__ rot,
                                const float* __restrict__ trans,
                                float* __restrict__ cat)
{
    const int i = blockIdx.x;
    const int tid = threadIdx.x;   // 192
    float* ci = cat + (size_t)i * 2112;
    {
        int h = tid >> 4, c = tid & 15;
        ci[tid] = ov[((size_t)(h * NN) + i) * 64 + c];
    }
    if (tid < 96) {
        int h = tid >> 3, pp = tid & 7;
        const float* base = ov + ((size_t)(h * NN) + i) * 64 + 16 + pp * 3;
        float vx = base[0] - trans[i*3+0];
        float vy = base[1] - trans[i*3+1];
        float vz = base[2] - trans[i*3+2];
        const float* R = rot + i * 9;
        float ox = R[0]*vx + R[3]*vy + R[6]*vz;
        float oy = R[1]*vx + R[4]*vy + R[7]*vz;
        float oz = R[2]*vx + R[5]*vy + R[8]*vz;
        ci[192 + h*24 + pp*3 + 0] = ox;
        ci[192 + h*24 + pp*3 + 1] = oy;
        ci[192 + h*24 + pp*3 + 2] = oz;
        ci[480 + h*8 + pp] = sqrtf(ox*ox + oy*oy + oz*oz + 1e-8f);
    }
}

// ---------------------------------------------------------------------------
// 3-way split-K reduce + bias + residual + LayerNorm.  Block/row, 128 thr.
// ---------------------------------------------------------------------------
__global__ void reduce_ln_kernel(const float* __restrict__ part,
                                 const float* __restrict__ bias,
                                 const float* __restrict__ res,
                                 const float* __restrict__ g,
                                 const float* __restrict__ b,
                                 float* __restrict__ y)
{
    __shared__ float rs[128], rs2[128];
    const int i = blockIdx.x, tid = threadIdx.x;
    const size_t SP = (size_t)NN * CS;
    float v[3];
    float sm = 0.f, sm2 = 0.f;
    #pragma unroll
    for (int k = 0; k < 3; k++) {
        int c = tid + k * 128;
        size_t o = (size_t)i * CS + c;
        float x = part[o] + part[SP + o] + part[2*SP + o] + bias[c] + res[o];
        v[k] = x;
        sm += x; sm2 += x * x;
    }
    rs[tid] = sm; rs2[tid] = sm2;
    __syncthreads();
    for (int st = 64; st > 0; st >>= 1) {
        if (tid < st) { rs[tid] += rs[tid + st]; rs2[tid] += rs2[tid + st]; }
        __syncthreads();
    }
    float mean = rs[0] * (1.0f / CS);
    float var  = rs2[0] * (1.0f / CS) - mean * mean;
    float inv  = rsqrtf(var + 1e-5f);
    #pragma unroll
    for (int k = 0; k < 3; k++) {
        int c = tid + k * 128;
        y[(size_t)i * CS + c] = (v[k] - mean) * inv * g[c] + b[c];
    }
}

// ---------------------------------------------------------------------------
// Fused: 3-way reduce + bias + residual + LayerNorm2 + backbone projection
// + quaternion frame update.  Block per row, 128 threads.
// ---------------------------------------------------------------------------
__global__ void lnbb_kernel(const float* __restrict__ part,
                            const float* __restrict__ bias,
                            const float* __restrict__ res,
                            const float* __restrict__ g,
                            const float* __restrict__ b,
                            const float* __restrict__ bb_w,
                            const float* __restrict__ bb_b,
                            const float* __restrict__ rot,
                            const float* __restrict__ trans,
                            float* __restrict__ out)
{
    __shared__ float rs[128], rs2[128], ys[CS], wsm[CS * 6], u[6];
    const int i = blockIdx.x, tid = threadIdx.x;
    const size_t SP = (size_t)NN * CS;

    // stage bb_w coalesced
    #pragma unroll
    for (int k = 0; k < 18; k++) wsm[tid + k * 128] = bb_w[tid + k * 128];

    float v[3];
    float sm = 0.f, sm2 = 0.f;
    #pragma unroll
    for (int k = 0; k < 3; k++) {
        int c = tid + k * 128;
        size_t o = (size_t)i * CS + c;
        float x = part[o] + part[SP + o] + part[2*SP + o] + bias[c] + res[o];
        v[k] = x;
        sm += x; sm2 += x * x;
    }
    rs[tid] = sm; rs2[tid] = sm2;
    __syncthreads();
    for (int st = 64; st > 0; st >>= 1) {
        if (tid < st) { rs[tid] += rs[tid + st]; rs2[tid] += rs2[tid + st]; }
        __syncthreads();
    }
    float mean = rs[0] * (1.0f / CS);
    float var  = rs2[0] * (1.0f / CS) - mean * mean;
    float inv  = rsqrtf(var + 1e-5f);
    #pragma unroll
    for (int k = 0; k < 3; k++) {
        int c = tid + k * 128;
        float yv = (v[k] - mean) * inv * g[c] + b[c];
        ys[c] = yv;
        out[(size_t)i * CS + c] = yv;
    }
    __syncthreads();

    if (tid < 32) {
        #pragma unroll
        for (int o = 0; o < 6; o++) {
            float sum = 0.f;
            for (int c = tid; c < CS; c += 32)
                sum = fmaf(ys[c], wsm[c * 6 + o], sum);
            #pragma unroll
            for (int off = 16; off > 0; off >>= 1)
                sum += __shfl_xor_sync(0xffffffffu, sum, off);
            if (tid == 0) u[o] = sum + bb_b[o];
        }
        if (tid == 0) {
            float bx = u[0], by = u[1], bz = u[2];
            float qinv = rsqrtf(1.f + bx*bx + by*by + bz*bz);
            float qw = qinv, x = bx * qinv, y = by * qinv, z = bz * qinv;
            float Ru[9] = {
                1 - 2*(y*y + z*z), 2*(x*y - qw*z),    2*(x*z + qw*y),
                2*(x*y + qw*z),    1 - 2*(x*x + z*z), 2*(y*z - qw*x),
                2*(x*z - qw*y),    2*(y*z + qw*x),    1 - 2*(x*x + y*y)};
            const float* R = rot + i * 9;
            float* ro = out + NN * CS + i * 9;
            #pragma unroll
            for (int r = 0; r < 3; r++)
                #pragma unroll
                for (int c = 0; c < 3; c++)
                    ro[r*3+c] = R[r*3+0]*Ru[0*3+c] + R[r*3+1]*Ru[1*3+c]
                              + R[r*3+2]*Ru[2*3+c];
            float tx = u[3], ty = u[4], tz = u[5];
            float* to = out + NN * CS + NN * 9 + i * 3;
            #pragma unroll
            for (int r = 0; r < 3; r++)
                to[r] = R[r*3+0]*tx + R[r*3+1]*ty + R[r*3+2]*tz + trans[i*3+r];
        }
    }
}

// ---------------------------------------------------------------------------
static cudaStream_t g_s1 = nullptr;
static cudaEvent_t  g_ev0, g_ev1, g_ev2, g_ev3;

extern "C" void kernel_launch(void* const* d_in, const int* in_sizes, int n_in,
                              void* d_out, int out_size)
{
    if (!g_s1) {
        cudaStreamCreateWithFlags(&g_s1, cudaStreamNonBlocking);
        cudaEventCreateWithFlags(&g_ev0, cudaEventDisableTiming);
        cudaEventCreateWithFlags(&g_ev1, cudaEventDisableTiming);
        cudaEventCreateWithFlags(&g_ev2, cudaEventDisableTiming);
        cudaEventCreateWithFlags(&g_ev3, cudaEventDisableTiming);
    }

    const float* s      = (const float*)d_in[0];
    const float* p      = (const float*)d_in[1];
    const float* rot    = (const float*)d_in[2];
    const float* trans  = (const float*)d_in[3];
    const float* mask   = (const float*)d_in[4];
    const float* w_q    = (const float*)d_in[5];
    const float* b_q    = (const float*)d_in[6];
    const float* w_kv   = (const float*)d_in[7];
    const float* b_kv   = (const float*)d_in[8];
    const float* w_qp   = (const float*)d_in[9];
    const float* b_qp   = (const float*)d_in[10];
    const float* w_kvp  = (const float*)d_in[11];
    const float* b_kvp  = (const float*)d_in[12];
    const float* w_b    = (const float*)d_in[13];
    const float* b_b    = (const float*)d_in[14];
    const float* head_w = (const float*)d_in[15];
    const float* w_o    = (const float*)d_in[16];
    const float* b_o    = (const float*)d_in[17];
    const float* ln1_g  = (const float*)d_in[18];
    const float* ln1_b  = (const float*)d_in[19];
    const float* tw1    = (const float*)d_in[20];
    const float* tb1    = (const float*)d_in[21];
    const float* tw2    = (const float*)d_in[22];
    const float* tb2    = (const float*)d_in[23];
    const float* tw3    = (const float*)d_in[24];
    const float* tb3    = (const float*)d_in[25];
    const float* ln2_g  = (const float*)d_in[26];
    const float* ln2_b  = (const float*)d_in[27];
    const float* bb_w   = (const float*)d_in[28];
    const float* bb_b   = (const float*)d_in[29];
    float* out = (float*)d_out;

    float *wcat, *bcat, *proj, *ppart, *kpk, *kppk, *vpk, *a_, *ov_, *cat_,
          *part, *partB, *x2;
    cudaGetSymbolAddress((void**)&wcat, g_wcat);
    cudaGetSymbolAddress((void**)&bcat, g_bcat);
    cudaGetSymbolAddress((void**)&proj, g_proj);
    cudaGetSymbolAddress((void**)&ppart, g_ppart);
    cudaGetSymbolAddress((void**)&kpk,  g_kpack);
    cudaGetSymbolAddress((void**)&kppk, g_kppack);
    cudaGetSymbolAddress((void**)&vpk,  g_vpack);
    cudaGetSymbolAddress((void**)&a_,   g_att);
    cudaGetSymbolAddress((void**)&ov_,  g_ov);
    cudaGetSymbolAddress((void**)&cat_, g_cat);
    cudaGetSymbolAddress((void**)&part, g_part);
    cudaGetSymbolAddress((void**)&partB, g_partB);
    cudaGetSymbolAddress((void**)&x2,   g_x2);

    const long long SPC = (long long)NN * CS;

    // ---- fork: bias planes on side stream ---------------------------------
    cudaEventRecord(g_ev0, 0);
    cudaStreamWaitEvent(g_s1, g_ev0, 0);
    bias_kernel<<<1024, 256, 0, g_s1>>>(p, w_b, b_b, a_);
    cudaEventRecord(g_ev1, g_s1);

    // ---- main: projections (split-K 2), fused reduce+rotate+pack ----------
    pack_w_kernel<<<(CS * LDP / 4 + LDP / 4 + 255) / 256, 256>>>(
        w_q, b_q, w_kv, b_kv, w_qp, b_qp, w_kvp, b_kvp, wcat, bcat);
    gemm64_kernel<<<dim3(LDP / 64, 8, 2), 128>>>(
        s, CS, 0, 192,
        wcat, LDP, 0, (long long)192 * LDP,
        nullptr,
        ppart, LDP, 0, (long long)NN * LDP,
        192, 2, nullptr, 0, 0, 0);
    {
        const int TOT = NN*48 + HDS*NN*4*3 + HDS*NN*8 + NN*48;
        rotpack_kernel<<<(TOT + 255) / 256, 256>>>(ppart, bcat, rot, trans,
                                                   proj, kpk, kppk, vpk);
    }

    // join bias, then fused logits+softmax
    cudaStreamWaitEvent(0, g_ev1, 0);
    logits_softmax_kernel<<<dim3(64, HDS), 256>>>(proj, kpk, kppk, mask,
                                                  head_w, a_);

    // ---- fork: opair + w_o-high-K on side stream --------------------------
    cudaEventRecord(g_ev2, 0);
    cudaStreamWaitEvent(g_s1, g_ev2, 0);
    opair_kernel<<<NN, 192, 0, g_s1>>>(a_, p, cat_);
    // w_o cols 576..2111 (opair region), split-K 2 -> part slots 1,2
    gemm64_kernel<<<dim3(6, 8, 2), 128, 0, g_s1>>>(
        cat_ + 576, 2112, 0, 768,
        w_o + 576 * CS, CS, 0, (long long)768 * CS,
        nullptr,
        part + SPC, CS, 0, SPC,
        768, 2, nullptr, 0, 0, 0);
    cudaEventRecord(g_ev3, g_s1);

    // main: ov GEMM + postproc + w_o low-K
    gemm64_kernel<<<dim3(1, 8, HDS), 128>>>(
        a_, NN, (long long)NN * NN, 0,
        vpk, 64, (long long)NN * 64, 0,
        nullptr,
        ov_, 64, (long long)NN * 64, 0,
        NN, 1, nullptr, 0, 0, 0);
    postproc_kernel<<<NN, 192>>>(ov_, rot, trans, cat_);
    // w_o cols 0..575 -> part slot 0
    gemm64_kernel<<<dim3(6, 8, 1), 128>>>(
        cat_, 2112, 0, 0,
        w_o, CS, 0, 0,
        nullptr,
        part, CS, 0, 0,
        576, 1, nullptr, 0, 0, 0);
    cudaStreamWaitEvent(0, g_ev3, 0);

    // ---- reduce + residual + LN1 -------------------------------------------
    reduce_ln_kernel<<<NN, 128>>>(part, b_o, s, ln1_g, ln1_b, x2);

    // ---- transition MLP: reduces fused into next GEMM's A-staging ----------
    gemm64_kernel<<<dim3(6, 8, 3), 128>>>(
        x2, CS, 0, 128,
        tw1, CS, 0, (long long)128 * CS,
        nullptr,
        partB, CS, 0, SPC,
        128, 3, nullptr, 0, 0, 0);
    gemm64_kernel<<<dim3(6, 8, 3), 128>>>(
        partB, CS, 0, 128,
        tw2, CS, 0, (long long)128 * CS,
        nullptr,
        part, CS, 0, SPC,
        128, 3, tb1, SPC, 128, 1);
    gemm64_kernel<<<dim3(6, 8, 3), 128>>>(
        part, CS, 0, 128,
        tw3, CS, 0, (long long)128 * CS,
        nullptr,
        partB, CS, 0, SPC,
        128, 3, tb2, SPC, 128, 1);

    // ---- reduce + residual + LN2 + backbone update --------------------------
    lnbb_kernel<<<NN, 128>>>(partB, tb3, x2, ln2_g, ln2_b,
                             bb_w, bb_b, rot, trans, out);
}

// round 10
// speedup vs baseline: 3.7584x; 1.0051x over previous
#include <cuda_runtime.h>
#include <math.h>

// ---------------------------------------------------------------------------
// StructureLayer (IPA) — B=1, N=512, H=12, C_S=384, C_P=128, C_H=16,
// P_QK=4, P_V=8.  Output: [ s2 (512*384) | rot_new (512*9) | trans_new (512*3) ]
// ---------------------------------------------------------------------------

#define NN 512
#define CS 384
#define CP 128
#define HDS 12

// proj row layout: [ q(192) | kv(384) | qp(144) | kvp(432) ]  = 1152
#define LDP 1152
#define OFF_Q   0
#define OFF_KV  192
#define OFF_QP  576
#define OFF_KVP 720

#define SQK 0.14433756729740643f    // sqrt(1/48)
#define SB  0.5773502691896258f     // sqrt(1/3)
#define SHW 0.13608276348795434f    // sqrt(1/54)

// opair_tc dynamic smem: As 512*17 u32 + Bs 64*132 u32
#define OPAIR_SMEM ((512 * 17 + 64 * 132) * 4)

// ---- scratch (device globals) ----------------------------------------------
__device__ float g_wcat[CS * LDP];
__device__ float g_bcat[LDP];
__device__ float g_proj[NN * LDP];       // only q / qp sections used
__device__ float g_ppart[2 * NN * LDP];  // proj split-K partials
__device__ float g_kpack[HDS * NN * 16];
__device__ float g_kppack[HDS * NN * 12];
__device__ float g_vpack[HDS * NN * 64]; // [h][j][ v(16) | vp(24) | pad=0 ]
__device__ float g_att[HDS * NN * NN];   // bias planes, then probs [h][i][j]
__device__ float g_cat[NN * 2112];
__device__ float g_part[3 * NN * CS];    // split-K partials (A)
__device__ float g_partB[3 * NN * CS];   // split-K partials (B)
__device__ float g_x2[NN * CS];

// ---------------------------------------------------------------------------
// tf32 helpers
// ---------------------------------------------------------------------------
__device__ __forceinline__ unsigned cvt_tf32(float x)
{
    unsigned r;
    asm("cvt.rna.tf32.f32 %0, %1;" : "=r"(r) : "f"(x));
    return r;
}

__device__ __forceinline__ void mma_tf32(float* d, const unsigned* a,
                                         const unsigned* b)
{
    asm volatile(
        "mma.sync.aligned.m16n8k8.row.col.f32.tf32.tf32.f32 "
        "{%0,%1,%2,%3}, {%4,%5,%6,%7}, {%8,%9}, {%0,%1,%2,%3};\n"
        : "+f"(d[0]), "+f"(d[1]), "+f"(d[2]), "+f"(d[3])
        : "r"(a[0]), "r"(a[1]), "r"(a[2]), "r"(a[3]),
          "r"(b[0]), "r"(b[1]));
}

// A-load: optionally reduce 3 split-K partials + bias + relu on the fly.
__device__ __forceinline__ float4 ldA4(const float* p,
                                       const float* abias, int bcol,
                                       long long SP, int arelu)
{
    float4 v = *(const float4*)p;
    if (abias) {
        float4 v1 = *(const float4*)(p + SP);
        float4 v2 = *(const float4*)(p + 2 * SP);
        float4 bb = *(const float4*)(abias + bcol);
        v.x += v1.x + v2.x + bb.x;
        v.y += v1.y + v2.y + bb.y;
        v.z += v1.z + v2.z + bb.z;
        v.w += v1.w + v2.w + bb.w;
        if (arelu) {
            v.x = fmaxf(v.x, 0.f); v.y = fmaxf(v.y, 0.f);
            v.z = fmaxf(v.z, 0.f); v.w = fmaxf(v.w, 0.f);
        }
    }
    return v;
}

// ---------------------------------------------------------------------------
// Pack projection weights/biases into one (384 x 1152) matrix. float4 copies.
// ---------------------------------------------------------------------------
__global__ void pack_w_kernel(const float* __restrict__ w_q,  const float* __restrict__ b_q,
                              const float* __restrict__ w_kv, const float* __restrict__ b_kv,
                              const float* __restrict__ w_qp, const float* __restrict__ b_qp,
                              const float* __restrict__ w_kvp,const float* __restrict__ b_kvp,
                              float* __restrict__ wcat, float* __restrict__ bcat)
{
    const int NW4 = CS * LDP / 4;
    int idx = blockIdx.x * blockDim.x + threadIdx.x;
    if (idx < NW4) {
        int r = idx / (LDP / 4), c = (idx % (LDP / 4)) * 4;
        float4 v;
        if      (c < 192) v = *(const float4*)(w_q  + r * 192 + c);
        else if (c < 576) v = *(const float4*)(w_kv + r * 384 + (c - 192));
        else if (c < 720) v = *(const float4*)(w_qp + r * 144 + (c - 576));
        else              v = *(const float4*)(w_kvp + r * 432 + (c - 720));
        *(float4*)(wcat + r * LDP + c) = v;
    } else if (idx < NW4 + LDP / 4) {
        int c = (idx - NW4) * 4;
        float4 v;
        if      (c < 192) v = *(const float4*)(b_q  + c);
        else if (c < 576) v = *(const float4*)(b_kv + (c - 192));
        else if (c < 720) v = *(const float4*)(b_qp + (c - 576));
        else              v = *(const float4*)(b_kvp + (c - 720));
        *(float4*)(bcat + c) = v;
    }
}

// ---------------------------------------------------------------------------
// tf32 tensor-core GEMM: 64x64 tile, 128 threads, double-buffered smem.
// z = zb*KS + zk (batch x split-K).  Optional fused A-side 3-partial
// reduce + bias + relu (abias != nullptr).
// ---------------------------------------------------------------------------
__global__ void __launch_bounds__(128)
gemm64_kernel(const float* __restrict__ A, int lda, long long sAz, long long sAk,
              const float* __restrict__ B, int ldb, long long sBz, long long sBk,
              const float* __restrict__ bias,
              float* __restrict__ C, int ldc, long long sCz, long long sCk,
              int K, int KS,
              const float* __restrict__ abias, long long aSP, int aKoff, int arelu)
{
    const int zb = blockIdx.z / KS, zk = blockIdx.z % KS;
    A += (size_t)zb * (size_t)sAz + (size_t)zk * (size_t)sAk;
    B += (size_t)zb * (size_t)sBz + (size_t)zk * (size_t)sBk;
    C += (size_t)zb * (size_t)sCz + (size_t)zk * (size_t)sCk;
    const int azoff = zk * aKoff;

    __shared__ __align__(16) unsigned As[2][16][72];
    __shared__ __align__(16) unsigned Bs[2][16][72];

    const int bm = blockIdx.y * 64, bn = blockIdx.x * 64;
    const int tid = threadIdx.x;
    const int lane = tid & 31, warp = tid >> 5;
    const int g = lane >> 2, t4 = lane & 3;
    const int wm = (warp >> 1) * 32, wn = (warp & 1) * 32;

    const int ar = tid >> 2, ak = (tid & 3) * 4;
    const int br = tid >> 4, bc = (tid & 15) * 4;

    const float* Ab = A + (size_t)bm * lda;

    float4 ra0, ra1, rb0, rb1;
    ra0 = ldA4(Ab + (size_t)ar * lda + ak, abias, azoff + ak, aSP, arelu);
    ra1 = ldA4(Ab + (size_t)(ar + 32) * lda + ak, abias, azoff + ak, aSP, arelu);
    rb0 = *(const float4*)(B + (size_t)br * ldb + bn + bc);
    rb1 = *(const float4*)(B + (size_t)(br + 8) * ldb + bn + bc);

    As[0][ak+0][ar] = cvt_tf32(ra0.x); As[0][ak+1][ar] = cvt_tf32(ra0.y);
    As[0][ak+2][ar] = cvt_tf32(ra0.z); As[0][ak+3][ar] = cvt_tf32(ra0.w);
    As[0][ak+0][ar+32] = cvt_tf32(ra1.x); As[0][ak+1][ar+32] = cvt_tf32(ra1.y);
    As[0][ak+2][ar+32] = cvt_tf32(ra1.z); As[0][ak+3][ar+32] = cvt_tf32(ra1.w);
    {
        uint4 u0 = make_uint4(cvt_tf32(rb0.x), cvt_tf32(rb0.y),
                              cvt_tf32(rb0.z), cvt_tf32(rb0.w));
        uint4 u1 = make_uint4(cvt_tf32(rb1.x), cvt_tf32(rb1.y),
                              cvt_tf32(rb1.z), cvt_tf32(rb1.w));
        *(uint4*)&Bs[0][br][bc]     = u0;
        *(uint4*)&Bs[0][br + 8][bc] = u1;
    }
    __syncthreads();

    float acc[2][4][4];
    #pragma unroll
    for (int mt = 0; mt < 2; mt++)
        #pragma unroll
        for (int nt = 0; nt < 4; nt++)
            #pragma unroll
            for (int r = 0; r < 4; r++) acc[mt][nt][r] = 0.f;

    int buf = 0;
    for (int k0 = 0; k0 < K; k0 += 16) {
        const bool more = (k0 + 16) < K;
        if (more) {
            int kc = k0 + 16 + ak;
            ra0 = ldA4(Ab + (size_t)ar * lda + kc, abias, azoff + kc, aSP, arelu);
            ra1 = ldA4(Ab + (size_t)(ar + 32) * lda + kc, abias, azoff + kc, aSP, arelu);
            rb0 = *(const float4*)(B + (size_t)(k0 + 16 + br) * ldb + bn + bc);
            rb1 = *(const float4*)(B + (size_t)(k0 + 16 + br + 8) * ldb + bn + bc);
        }
        #pragma unroll
        for (int kk = 0; kk < 16; kk += 8) {
            unsigned af[2][4], bf[4][2];
            #pragma unroll
            for (int mt = 0; mt < 2; mt++) {
                int m0 = wm + mt * 16 + g;
                af[mt][0] = As[buf][kk + t4][m0];
                af[mt][1] = As[buf][kk + t4][m0 + 8];
                af[mt][2] = As[buf][kk + 4 + t4][m0];
                af[mt][3] = As[buf][kk + 4 + t4][m0 + 8];
            }
            #pragma unroll
            for (int nt = 0; nt < 4; nt++) {
                int n0 = wn + nt * 8 + g;
                bf[nt][0] = Bs[buf][kk + t4][n0];
                bf[nt][1] = Bs[buf][kk + 4 + t4][n0];
            }
            #pragma unroll
            for (int mt = 0; mt < 2; mt++)
                #pragma unroll
                for (int nt = 0; nt < 4; nt++)
                    mma_tf32(acc[mt][nt], af[mt], bf[nt]);
        }
        if (more) {
            buf ^= 1;
            __syncthreads();
            As[buf][ak+0][ar] = cvt_tf32(ra0.x); As[buf][ak+1][ar] = cvt_tf32(ra0.y);
            As[buf][ak+2][ar] = cvt_tf32(ra0.z); As[buf][ak+3][ar] = cvt_tf32(ra0.w);
            As[buf][ak+0][ar+32] = cvt_tf32(ra1.x); As[buf][ak+1][ar+32] = cvt_tf32(ra1.y);
            As[buf][ak+2][ar+32] = cvt_tf32(ra1.z); As[buf][ak+3][ar+32] = cvt_tf32(ra1.w);
            uint4 u0 = make_uint4(cvt_tf32(rb0.x), cvt_tf32(rb0.y),
                                  cvt_tf32(rb0.z), cvt_tf32(rb0.w));
            uint4 u1 = make_uint4(cvt_tf32(rb1.x), cvt_tf32(rb1.y),
                                  cvt_tf32(rb1.z), cvt_tf32(rb1.w));
            *(uint4*)&Bs[buf][br][bc]     = u0;
            *(uint4*)&Bs[buf][br + 8][bc] = u1;
            __syncthreads();
        }
    }

    #pragma unroll
    for (int mt = 0; mt < 2; mt++) {
        int row0 = bm + wm + mt * 16 + g;
        #pragma unroll
        for (int nt = 0; nt < 4; nt++) {
            int col = bn + wn + nt * 8 + t4 * 2;
            float b0 = 0.f, b1 = 0.f;
            if (bias) { b0 = bias[col]; b1 = bias[col + 1]; }
            float2 v0 = make_float2(acc[mt][nt][0] + b0, acc[mt][nt][1] + b1);
            float2 v1 = make_float2(acc[mt][nt][2] + b0, acc[mt][nt][3] + b1);
            *(float2*)(C + (size_t)row0 * ldc + col)       = v0;
            *(float2*)(C + (size_t)(row0 + 8) * ldc + col) = v1;
        }
    }
}

// ---------------------------------------------------------------------------
// ov GEMM (att @ [v|vp], per-head) with fused postproc epilogue:
// writes o / rotated-op / norms directly into cat.  grid (1, 8, HDS).
// ---------------------------------------------------------------------------
__global__ void __launch_bounds__(128)
ovgemm_kernel(const float* __restrict__ att,
              const float* __restrict__ vpk,
              const float* __restrict__ rot,
              const float* __restrict__ trans,
              float* __restrict__ cat)
{
    const int h = blockIdx.z;
    const float* A = att + (size_t)h * NN * NN;
    const float* B = vpk + (size_t)h * NN * 64;

    __shared__ __align__(16) unsigned As[2][16][72];
    __shared__ __align__(16) unsigned Bs[2][16][72];
    __shared__ float sm[64][41];

    const int bm = blockIdx.y * 64;
    const int tid = threadIdx.x;
    const int lane = tid & 31, warp = tid >> 5;
    const int g = lane >> 2, t4 = lane & 3;
    const int wm = (warp >> 1) * 32, wn = (warp & 1) * 32;

    const int ar = tid >> 2, ak = (tid & 3) * 4;
    const int br = tid >> 4, bc = (tid & 15) * 4;

    const float* Ab = A + (size_t)bm * NN;

    float4 ra0, ra1, rb0, rb1;
    ra0 = *(const float4*)(Ab + (size_t)ar * NN + ak);
    ra1 = *(const float4*)(Ab + (size_t)(ar + 32) * NN + ak);
    rb0 = *(const float4*)(B + (size_t)br * 64 + bc);
    rb1 = *(const float4*)(B + (size_t)(br + 8) * 64 + bc);

    As[0][ak+0][ar] = cvt_tf32(ra0.x); As[0][ak+1][ar] = cvt_tf32(ra0.y);
    As[0][ak+2][ar] = cvt_tf32(ra0.z); As[0][ak+3][ar] = cvt_tf32(ra0.w);
    As[0][ak+0][ar+32] = cvt_tf32(ra1.x); As[0][ak+1][ar+32] = cvt_tf32(ra1.y);
    As[0][ak+2][ar+32] = cvt_tf32(ra1.z); As[0][ak+3][ar+32] = cvt_tf32(ra1.w);
    {
        uint4 u0 = make_uint4(cvt_tf32(rb0.x), cvt_tf32(rb0.y),
                              cvt_tf32(rb0.z), cvt_tf32(rb0.w));
        uint4 u1 = make_uint4(cvt_tf32(rb1.x), cvt_tf32(rb1.y),
                              cvt_tf32(rb1.z), cvt_tf32(rb1.w));
        *(uint4*)&Bs[0][br][bc]     = u0;
        *(uint4*)&Bs[0][br + 8][bc] = u1;
    }
    __syncthreads();

    float acc[2][4][4];
    #pragma unroll
    for (int mt = 0; mt < 2; mt++)
        #pragma unroll
        for (int nt = 0; nt < 4; nt++)
            #pragma unroll
            for (int r = 0; r < 4; r++) acc[mt][nt][r] = 0.f;

    int buf = 0;
    for (int k0 = 0; k0 < NN; k0 += 16) {
        const bool more = (k0 + 16) < NN;
        if (more) {
            ra0 = *(const float4*)(Ab + (size_t)ar * NN + k0 + 16 + ak);
            ra1 = *(const float4*)(Ab + (size_t)(ar + 32) * NN + k0 + 16 + ak);
            rb0 = *(const float4*)(B + (size_t)(k0 + 16 + br) * 64 + bc);
            rb1 = *(const float4*)(B + (size_t)(k0 + 16 + br + 8) * 64 + bc);
        }
        #pragma unroll
        for (int kk = 0; kk < 16; kk += 8) {
            unsigned af[2][4], bf[4][2];
            #pragma unroll
            for (int mt = 0; mt < 2; mt++) {
                int m0 = wm + mt * 16 + g;
                af[mt][0] = As[buf][kk + t4][m0];
                af[mt][1] = As[buf][kk + t4][m0 + 8];
                af[mt][2] = As[buf][kk + 4 + t4][m0];
                af[mt][3] = As[buf][kk + 4 + t4][m0 + 8];
            }
            #pragma unroll
            for (int nt = 0; nt < 4; nt++) {
                int n0 = wn + nt * 8 + g;
                bf[nt][0] = Bs[buf][kk + t4][n0];
                bf[nt][1] = Bs[buf][kk + 4 + t4][n0];
            }
            #pragma unroll
            for (int mt = 0; mt < 2; mt++)
                #pragma unroll
                for (int nt = 0; nt < 4; nt++)
                    mma_tf32(acc[mt][nt], af[mt], bf[nt]);
        }
        if (more) {
            buf ^= 1;
            __syncthreads();
            As[buf][ak+0][ar] = cvt_tf32(ra0.x); As[buf][ak+1][ar] = cvt_tf32(ra0.y);
            As[buf][ak+2][ar] = cvt_tf32(ra0.z); As[buf][ak+3][ar] = cvt_tf32(ra0.w);
            As[buf][ak+0][ar+32] = cvt_tf32(ra1.x); As[buf][ak+1][ar+32] = cvt_tf32(ra1.y);
            As[buf][ak+2][ar+32] = cvt_tf32(ra1.z); As[buf][ak+3][ar+32] = cvt_tf32(ra1.w);
            uint4 u0 = make_uint4(cvt_tf32(rb0.x), cvt_tf32(rb0.y),
                                  cvt_tf32(rb0.z), cvt_tf32(rb0.w));
            uint4 u1 = make_uint4(cvt_tf32(rb1.x), cvt_tf32(rb1.y),
                                  cvt_tf32(rb1.z), cvt_tf32(rb1.w));
            *(uint4*)&Bs[buf][br][bc]     = u0;
            *(uint4*)&Bs[buf][br + 8][bc] = u1;
            __syncthreads();
        }
    }

    // stash useful cols (0..39) to smem
    #pragma unroll
    for (int mt = 0; mt < 2; mt++) {
        int r0 = wm + mt * 16 + g;
        #pragma unroll
        for (int nt = 0; nt < 4; nt++) {
            int col = wn + nt * 8 + t4 * 2;
            if (col < 40) {
                sm[r0][col]       = acc[mt][nt][0];
                sm[r0][col + 1]   = acc[mt][nt][1];
                sm[r0 + 8][col]     = acc[mt][nt][2];
                sm[r0 + 8][col + 1] = acc[mt][nt][3];
            }
        }
    }
    __syncthreads();

    // postproc epilogue
    #pragma unroll
    for (int l = 0; l < 8; l++) {
        int e = tid + l * 128;
        int r = e >> 4, c = e & 15;
        cat[(size_t)(bm + r) * 2112 + h * 16 + c] = sm[r][c];
    }
    #pragma unroll
    for (int l = 0; l < 4; l++) {
        int e = tid + l * 128;
        int r = e >> 3, pp = e & 7;
        int i = bm + r;
        float vx = sm[r][16 + pp*3 + 0] - trans[i*3 + 0];
        float vy = sm[r][16 + pp*3 + 1] - trans[i*3 + 1];
        float vz = sm[r][16 + pp*3 + 2] - trans[i*3 + 2];
        const float* R = rot + i * 9;
        float ox = R[0]*vx + R[3]*vy + R[6]*vz;
        float oy = R[1]*vx + R[4]*vy + R[7]*vz;
        float oz = R[2]*vx + R[5]*vy + R[8]*vz;
        float* ci = cat + (size_t)i * 2112;
        ci[192 + h*24 + pp*3 + 0] = ox;
        ci[192 + h*24 + pp*3 + 1] = oy;
        ci[192 + h*24 + pp*3 + 2] = oz;
        ci[480 + h*8 + pp] = sqrtf(ox*ox + oy*oy + oz*oz + 1e-8f);
    }
}

// ---------------------------------------------------------------------------
// o_pair via tensor cores: per-i block computes (16x512)@(512x128)
// with att rows (12 heads padded to 16) as A, p[i] as B.  128 threads.
// Dynamic smem: As [512][17] u32, Bs [64][132] u32.
// ---------------------------------------------------------------------------
extern __shared__ unsigned opair_smem[];
__global__ void __launch_bounds__(128)
opair_tc_kernel(const float* __restrict__ att,
                const float* __restrict__ p,
                float* __restrict__ cat)
{
    const int i = blockIdx.x;
    unsigned* As = opair_smem;                 // [j][h] stride 17
    unsigned* Bs = opair_smem + 512 * 17;      // [jj][c] stride 132
    const int tid = threadIdx.x;

    for (int idx = tid; idx < HDS * NN; idx += 128) {
        int j = idx & 511, h = idx >> 9;
        As[j * 17 + h] = cvt_tf32(att[((size_t)(h * NN) + i) * NN + j]);
    }
    for (int idx = tid; idx < 4 * NN; idx += 128) {
        int j = idx & 511, h = 12 + (idx >> 9);
        As[j * 17 + h] = 0u;
    }

    const int lane = tid & 31, warp = tid >> 5;
    const int g = lane >> 2, t4 = lane & 3;
    const int wn = warp * 32;

    float acc[4][4];
    #pragma unroll
    for (int nt = 0; nt < 4; nt++)
        #pragma unroll
        for (int r = 0; r < 4; r++) acc[nt][r] = 0.f;

    const float4* pi4 = (const float4*)(p + (size_t)i * NN * CP);

    for (int j0 = 0; j0 < NN; j0 += 64) {
        __syncthreads();
        #pragma unroll
        for (int l = 0; l < 16; l++) {
            int e = tid + l * 128;
            int jj = e >> 5, c4 = e & 31;
            float4 v = pi4[(size_t)(j0 + jj) * 32 + c4];
            uint4 u = make_uint4(cvt_tf32(v.x), cvt_tf32(v.y),
                                 cvt_tf32(v.z), cvt_tf32(v.w));
            *(uint4*)&Bs[jj * 132 + c4 * 4] = u;
        }
        __syncthreads();
        #pragma unroll
        for (int ks = 0; ks < 8; ks++) {
            unsigned af[4];
            int kg = (j0 + ks * 8 + t4) * 17;
            int kg4 = (j0 + ks * 8 + 4 + t4) * 17;
            af[0] = As[kg + g];
            af[1] = As[kg + g + 8];
            af[2] = As[kg4 + g];
            af[3] = As[kg4 + g + 8];
            #pragma unroll
            for (int nt = 0; nt < 4; nt++) {
                unsigned bf[2];
                int n0 = wn + nt * 8 + g;
                bf[0] = Bs[(ks * 8 + t4) * 132 + n0];
                bf[1] = Bs[(ks * 8 + 4 + t4) * 132 + n0];
                mma_tf32(acc[nt], af, bf);
            }
        }
    }

    float* dst = cat + (size_t)i * 2112 + 576;
    #pragma unroll
    for (int nt = 0; nt < 4; nt++) {
        int col = wn + nt * 8 + t4 * 2;
        dst[g * 128 + col]     = acc[nt][0];
        dst[g * 128 + col + 1] = acc[nt][1];
        if (g + 8 < HDS) {
            dst[(g + 8) * 128 + col]     = acc[nt][2];
            dst[(g + 8) * 128 + col + 1] = acc[nt][3];
        }
    }
}

// ---------------------------------------------------------------------------
// Fused proj split-K reduce + bias + rotate + repack.
// ---------------------------------------------------------------------------
__global__ void rotpack_kernel(const float* __restrict__ ppart,
                               const float* __restrict__ bcat,
                               const float* __restrict__ rot,
                               const float* __restrict__ trans,
                               float* __restrict__ proj,
                               float* __restrict__ kpack,
                               float* __restrict__ kppack,
                               float* __restrict__ vpack)
{
    const long long SP = (long long)NN * LDP;
    const int S0 = NN * 48;
    const int S1 = S0 + HDS * NN * 4;
    const int S2 = S1 + HDS * NN * 4;
    const int S3 = S2 + HDS * NN * 4;
    const int S4 = S3 + HDS * NN * 8;
    const int S5 = S4 + NN * 48;
    int idx = blockIdx.x * blockDim.x + threadIdx.x;

    if (idx < S0) {
        int j = idx / 48, c = (idx % 48) * 4;
        const float* p0 = ppart + (size_t)j * LDP + c;
        float4 a = *(const float4*)p0;
        float4 b = *(const float4*)(p0 + SP);
        float4 bb = *(const float4*)(bcat + c);
        *(float4*)(proj + (size_t)j * LDP + c) =
            make_float4(a.x+b.x+bb.x, a.y+b.y+bb.y, a.z+b.z+bb.z, a.w+b.w+bb.w);
    } else if (idx < S1) {
        int t = idx - S0;
        int c = (t & 3) * 4, j = (t >> 2) & 511, h = t >> 11;
        int col = OFF_KV + h * 32 + c;
        const float* p0 = ppart + (size_t)j * LDP + col;
        float4 a = *(const float4*)p0;
        float4 b = *(const float4*)(p0 + SP);
        float4 bb = *(const float4*)(bcat + col);
        *(float4*)(kpack + (((size_t)h * NN) + j) * 16 + c) =
            make_float4(a.x+b.x+bb.x, a.y+b.y+bb.y, a.z+b.z+bb.z, a.w+b.w+bb.w);
    } else if (idx < S2) {
        int t = idx - S1;
        int c = (t & 3) * 4, j = (t >> 2) & 511, h = t >> 11;
        int col = OFF_KV + h * 32 + 16 + c;
        const float* p0 = ppart + (size_t)j * LDP + col;
        float4 a = *(const float4*)p0;
        float4 b = *(const float4*)(p0 + SP);
        float4 bb = *(const float4*)(bcat + col);
        *(float4*)(vpack + (((size_t)h * NN) + j) * 64 + c) =
            make_float4(a.x+b.x+bb.x, a.y+b.y+bb.y, a.z+b.z+bb.z, a.w+b.w+bb.w);
    } else if (idx < S4) {
        int t = idx - S2;
        int pp, j, h;
        float* dst;
        if (t < HDS * NN * 4) {
            pp = t & 3; j = (t >> 2) & 511; h = t >> 11;
            dst = kppack + (((size_t)h * NN) + j) * 12 + pp * 3;
        } else {
            t -= HDS * NN * 4;
            int vp = t & 7; j = (t >> 3) & 511; h = t >> 12;
            pp = 4 + vp;
            dst = vpack + (((size_t)h * NN) + j) * 64 + 16 + vp * 3;
        }
        int col = OFF_KVP + h * 36 + pp * 3;
        const float* p0 = ppart + (size_t)j * LDP + col;
        float x = p0[0] + p0[SP + 0] + bcat[col + 0];
        float y = p0[1] + p0[SP + 1] + bcat[col + 1];
        float z = p0[2] + p0[SP + 2] + bcat[col + 2];
        const float* R = rot + j * 9;
        const float* tr = trans + j * 3;
        dst[0] = R[0]*x + R[1]*y + R[2]*z + tr[0];
        dst[1] = R[3]*x + R[4]*y + R[5]*z + tr[1];
        dst[2] = R[6]*x + R[7]*y + R[8]*z + tr[2];
    } else if (idx < S5) {
        int t = idx - S4;
        int pt = t % 48, j = t / 48;
        int col = OFF_QP + pt * 3;
        const float* p0 = ppart + (size_t)j * LDP + col;
        float x = p0[0] + p0[SP + 0] + bcat[col + 0];
        float y = p0[1] + p0[SP + 1] + bcat[col + 1];
        float z = p0[2] + p0[SP + 2] + bcat[col + 2];
        const float* R = rot + j * 9;
        const float* tr = trans + j * 3;
        float* pv = proj + (size_t)j * LDP + col;
        pv[0] = R[0]*x + R[1]*y + R[2]*z + tr[0];
        pv[1] = R[3]*x + R[4]*y + R[5]*z + tr[1];
        pv[2] = R[6]*x + R[7]*y + R[8]*z + tr[2];
    }
}

// ---------------------------------------------------------------------------
// bias planes: att[h][i][j] = (p[i,j,:]·w_b[:,h] + b_b[h]) * sqrt(1/3)
// ---------------------------------------------------------------------------
__global__ void bias_kernel(const float* __restrict__ p,
                            const float* __restrict__ w_b,
                            const float* __restrict__ b_b,
                            float* __restrict__ att)
{
    __shared__ float wbt[HDS][CP];
    __shared__ float bbs[HDS];
    const int tid = threadIdx.x;
    #pragma unroll
    for (int k = 0; k < 6; k++) {
        int e = tid + k * 256;
        int h = e / CP, c = e % CP;
        wbt[h][c] = w_b[c * HDS + h];
    }
    if (tid < HDS) bbs[tid] = b_b[tid];
    __syncthreads();

    const int gw = blockIdx.x * 8 + (tid >> 5);
    const int lane = tid & 31;
    const int i = gw >> 4;
    const int j = ((gw & 15) << 5) + lane;

    float acc[HDS];
    #pragma unroll
    for (int h = 0; h < HDS; h++) acc[h] = 0.f;

    const float4* prow = (const float4*)(p + ((size_t)i * NN + j) * CP);
    #pragma unroll 4
    for (int c4 = 0; c4 < 32; c4++) {
        float4 pv = prow[c4];
        #pragma unroll
        for (int h = 0; h < HDS; h++) {
            float4 wv = ((const float4*)&wbt[h][0])[c4];
            acc[h] = fmaf(pv.x, wv.x,
                     fmaf(pv.y, wv.y,
                     fmaf(pv.z, wv.z,
                     fmaf(pv.w, wv.w, acc[h]))));
        }
    }
    #pragma unroll
    for (int h = 0; h < HDS; h++)
        att[((size_t)(h * NN) + i) * NN + j] = (acc[h] + bbs[h]) * SB;
}

// ---------------------------------------------------------------------------
// Fused logits + softmax.  Block = (i-tile of 8, head h).  256 threads.
// ---------------------------------------------------------------------------
__global__ void logits_softmax_kernel(const float* __restrict__ proj,
                                      const float* __restrict__ kpack,
                                      const float* __restrict__ kppack,
                                      const float* __restrict__ mask,
                                      const float* __restrict__ head_w,
                                      float* __restrict__ att)
{
    const int i0 = blockIdx.x * 8, h = blockIdx.y;
    const int tid = threadIdx.x;

    __shared__ float att_s[8][NN];
    __shared__ float kt[64][17];
    __shared__ float kpt[64][13];
    __shared__ float q_s[8][17];
    __shared__ float qp_s[8][13];
    __shared__ float m_i[8];
    __shared__ float sh_hw;

    if (tid < 128) {
        int il = tid >> 4, c = tid & 15;
        q_s[il][c] = proj[(size_t)(i0 + il) * LDP + OFF_Q + h * 16 + c];
    } else if (tid < 224) {
        int e = tid - 128;
        int il = e / 12, c = e % 12;
        qp_s[il][c] = proj[(size_t)(i0 + il) * LDP + OFF_QP + h * 12 + c];
    } else if (tid < 232) {
        m_i[tid - 224] = mask[i0 + (tid - 224)];
    } else if (tid == 232) {
        float w = head_w[h];
        float sp = fmaxf(w, 0.f) + log1pf(expf(-fabsf(w)));
        sh_hw = sp * SHW;
    }

    const float* kb  = kpack  + (size_t)(h * NN) * 16;
    const float* kpb = kppack + (size_t)(h * NN) * 12;

    const int jl = tid & 63, ig = tid >> 6;

    for (int j0 = 0; j0 < NN; j0 += 64) {
        #pragma unroll
        for (int k = 0; k < 4; k++) {
            int e = tid + k * 256;
            int r = e >> 4, c = e & 15;
            kt[r][c] = kb[(size_t)(j0 + r) * 16 + c];
        }
        #pragma unroll
        for (int k = 0; k < 3; k++) {
            int e = tid + k * 256;
            if (e < 768) {
                int r = e / 12, c = e % 12;
                kpt[r][c] = kpb[(size_t)(j0 + r) * 12 + c];
            }
        }
        __syncthreads();

        float mj = mask[j0 + jl];
        float hw = sh_hw;
        #pragma unroll
        for (int ii = 0; ii < 2; ii++) {
            int il = ig * 2 + ii;
            float qk = 0.f;
            #pragma unroll
            for (int c = 0; c < 16; c++) qk = fmaf(q_s[il][c], kt[jl][c], qk);
            float d2 = 0.f;
            #pragma unroll
            for (int d = 0; d < 12; d++) {
                float dd = qp_s[il][d] - kpt[jl][d];
                d2 = fmaf(dd, dd, d2);
            }
            float bias = att[((size_t)(h * NN) + i0 + il) * NN + j0 + jl];
            att_s[il][j0 + jl] = qk * SQK + bias - 0.5f * hw * d2
                               + (m_i[il] * mj - 1.0f) * 100000.0f;
        }
        __syncthreads();
    }

    const int w = tid >> 5, lane = tid & 31;
    float vals[16];
    float vmax = -1e30f;
    #pragma unroll
    for (int k = 0; k < 16; k++) {
        vals[k] = att_s[w][lane + 32 * k];
        vmax = fmaxf(vmax, vals[k]);
    }
    #pragma unroll
    for (int o = 16; o > 0; o >>= 1)
        vmax = fmaxf(vmax, __shfl_xor_sync(0xffffffffu, vmax, o));
    float sum = 0.f;
    #pragma unroll
    for (int k = 0; k < 16; k++) { vals[k] = expf(vals[k] - vmax); sum += vals[k]; }
    #pragma unroll
    for (int o = 16; o > 0; o >>= 1)
        sum += __shfl_xor_sync(0xffffffffu, sum, o);
    float inv = 1.0f / sum;
    float* arow = att + ((size_t)(h * NN) + i0 + w) * NN;
    #pragma unroll
    for (int k = 0; k < 16; k++)
        arow[lane + 32 * k] = vals[k] * inv;
}

// ---------------------------------------------------------------------------
// 3-way split-K reduce + bias + residual + LayerNorm.  Block/row, 128 thr.
// ---------------------------------------------------------------------------
__global__ void reduce_ln_kernel(const float* __restrict__ part,
                                 const float* __restrict__ bias,
                                 const float* __restrict__ res,
                                 const float* __restrict__ g,
                                 const float* __restrict__ b,
                                 float* __restrict__ y)
{
    __shared__ float rs[128], rs2[128];
    const int i = blockIdx.x, tid = threadIdx.x;
    const size_t SP = (size_t)NN * CS;
    float v[3];
    float sm = 0.f, sm2 = 0.f;
    #pragma unroll
    for (int k = 0; k < 3; k++) {
        int c = tid + k * 128;
        size_t o = (size_t)i * CS + c;
        float x = part[o] + part[SP + o] + part[2*SP + o] + bias[c] + res[o];
        v[k] = x;
        sm += x; sm2 += x * x;
    }
    rs[tid] = sm; rs2[tid] = sm2;
    __syncthreads();
    for (int st = 64; st > 0; st >>= 1) {
        if (tid < st) { rs[tid] += rs[tid + st]; rs2[tid] += rs2[tid + st]; }
        __syncthreads();
    }
    float mean = rs[0] * (1.0f / CS);
    float var  = rs2[0] * (1.0f / CS) - mean * mean;
    float inv  = rsqrtf(var + 1e-5f);
    #pragma unroll
    for (int k = 0; k < 3; k++) {
        int c = tid + k * 128;
        y[(size_t)i * CS + c] = (v[k] - mean) * inv * g[c] + b[c];
    }
}

// ---------------------------------------------------------------------------
// Fused: 3-way reduce + bias + residual + LayerNorm2 + backbone projection
// + quaternion frame update.  Block per row, 128 threads.
// ---------------------------------------------------------------------------
__global__ void lnbb_kernel(const float* __restrict__ part,
                            const float* __restrict__ bias,
                            const float* __restrict__ res,
                            const float* __restrict__ g,
                            const float* __restrict__ b,
                            const float* __restrict__ bb_w,
                            const float* __restrict__ bb_b,
                            const float* __restrict__ rot,
                            const float* __restrict__ trans,
                            float* __restrict__ out)
{
    __shared__ float rs[128], rs2[128], ys[CS], wsm[CS * 6], u[6];
    const int i = blockIdx.x, tid = threadIdx.x;
    const size_t SP = (size_t)NN * CS;

    #pragma unroll
    for (int k = 0; k < 18; k++) wsm[tid + k * 128] = bb_w[tid + k * 128];

    float v[3];
    float sm = 0.f, sm2 = 0.f;
    #pragma unroll
    for (int k = 0; k < 3; k++) {
        int c = tid + k * 128;
        size_t o = (size_t)i * CS + c;
        float x = part[o] + part[SP + o] + part[2*SP + o] + bias[c] + res[o];
        v[k] = x;
        sm += x; sm2 += x * x;
    }
    rs[tid] = sm; rs2[tid] = sm2;
    __syncthreads();
    for (int st = 64; st > 0; st >>= 1) {
        if (tid < st) { rs[tid] += rs[tid + st]; rs2[tid] += rs2[tid + st]; }
        __syncthreads();
    }
    float mean = rs[0] * (1.0f / CS);
    float var  = rs2[0] * (1.0f / CS) - mean * mean;
    float inv  = rsqrtf(var + 1e-5f);
    #pragma unroll
    for (int k = 0; k < 3; k++) {
        int c = tid + k * 128;
        float yv = (v[k] - mean) * inv * g[c] + b[c];
        ys[c] = yv;
        out[(size_t)i * CS + c] = yv;
    }
    __syncthreads();

    if (tid < 32) {
        #pragma unroll
        for (int o = 0; o < 6; o++) {
            float sum = 0.f;
            for (int c = tid; c < CS; c += 32)
                sum = fmaf(ys[c], wsm[c * 6 + o], sum);
            #pragma unroll
            for (int off = 16; off > 0; off >>= 1)
                sum += __shfl_xor_sync(0xffffffffu, sum, off);
            if (tid == 0) u[o] = sum + bb_b[o];
        }
        if (tid == 0) {
            float bx = u[0], by = u[1], bz = u[2];
            float qinv = rsqrtf(1.f + bx*bx + by*by + bz*bz);
            float qw = qinv, x = bx * qinv, y = by * qinv, z = bz * qinv;
            float Ru[9] = {
                1 - 2*(y*y + z*z), 2*(x*y - qw*z),    2*(x*z + qw*y),
                2*(x*y + qw*z),    1 - 2*(x*x + z*z), 2*(y*z - qw*x),
                2*(x*z - qw*y),    2*(y*z + qw*x),    1 - 2*(x*x + y*y)};
            const float* R = rot + i * 9;
            float* ro = out + NN * CS + i * 9;
            #pragma unroll
            for (int r = 0; r < 3; r++)
                #pragma unroll
                for (int c = 0; c < 3; c++)
                    ro[r*3+c] = R[r*3+0]*Ru[0*3+c] + R[r*3+1]*Ru[1*3+c]
                              + R[r*3+2]*Ru[2*3+c];
            float tx = u[3], ty = u[4], tz = u[5];
            float* to = out + NN * CS + NN * 9 + i * 3;
            #pragma unroll
            for (int r = 0; r < 3; r++)
                to[r] = R[r*3+0]*tx + R[r*3+1]*ty + R[r*3+2]*tz + trans[i*3+r];
        }
    }
}

// ---------------------------------------------------------------------------
static cudaStream_t g_s1 = nullptr;
static cudaEvent_t  g_ev0, g_ev1, g_ev2, g_ev3;

extern "C" void kernel_launch(void* const* d_in, const int* in_sizes, int n_in,
                              void* d_out, int out_size)
{
    if (!g_s1) {
        cudaStreamCreateWithFlags(&g_s1, cudaStreamNonBlocking);
        cudaEventCreateWithFlags(&g_ev0, cudaEventDisableTiming);
        cudaEventCreateWithFlags(&g_ev1, cudaEventDisableTiming);
        cudaEventCreateWithFlags(&g_ev2, cudaEventDisableTiming);
        cudaEventCreateWithFlags(&g_ev3, cudaEventDisableTiming);
        cudaFuncSetAttribute(opair_tc_kernel,
                             cudaFuncAttributeMaxDynamicSharedMemorySize,
                             OPAIR_SMEM);
    }

    const float* s      = (const float*)d_in[0];
    const float* p      = (const float*)d_in[1];
    const float* rot    = (const float*)d_in[2];
    const float* trans  = (const float*)d_in[3];
    const float* mask   = (const float*)d_in[4];
    const float* w_q    = (const float*)d_in[5];
    const float* b_q    = (const float*)d_in[6];
    const float* w_kv   = (const float*)d_in[7];
    const float* b_kv   = (const float*)d_in[8];
    const float* w_qp   = (const float*)d_in[9];
    const float* b_qp   = (const float*)d_in[10];
    const float* w_kvp  = (const float*)d_in[11];
    const float* b_kvp  = (const float*)d_in[12];
    const float* w_b    = (const float*)d_in[13];
    const float* b_b    = (const float*)d_in[14];
    const float* head_w = (const float*)d_in[15];
    const float* w_o    = (const float*)d_in[16];
    const float* b_o    = (const float*)d_in[17];
    const float* ln1_g  = (const float*)d_in[18];
    const float* ln1_b  = (const float*)d_in[19];
    const float* tw1    = (const float*)d_in[20];
    const float* tb1    = (const float*)d_in[21];
    const float* tw2    = (const float*)d_in[22];
    const float* tb2    = (const float*)d_in[23];
    const float* tw3    = (const float*)d_in[24];
    const float* tb3    = (const float*)d_in[25];
    const float* ln2_g  = (const float*)d_in[26];
    const float* ln2_b  = (const float*)d_in[27];
    const float* bb_w   = (const float*)d_in[28];
    const float* bb_b   = (const float*)d_in[29];
    float* out = (float*)d_out;

    float *wcat, *bcat, *proj, *ppart, *kpk, *kppk, *vpk, *a_, *cat_,
          *part, *partB, *x2;
    cudaGetSymbolAddress((void**)&wcat, g_wcat);
    cudaGetSymbolAddress((void**)&bcat, g_bcat);
    cudaGetSymbolAddress((void**)&proj, g_proj);
    cudaGetSymbolAddress((void**)&ppart, g_ppart);
    cudaGetSymbolAddress((void**)&kpk,  g_kpack);
    cudaGetSymbolAddress((void**)&kppk, g_kppack);
    cudaGetSymbolAddress((void**)&vpk,  g_vpack);
    cudaGetSymbolAddress((void**)&a_,   g_att);
    cudaGetSymbolAddress((void**)&cat_, g_cat);
    cudaGetSymbolAddress((void**)&part, g_part);
    cudaGetSymbolAddress((void**)&partB, g_partB);
    cudaGetSymbolAddress((void**)&x2,   g_x2);

    const long long SPC = (long long)NN * CS;

    // ---- fork: bias planes on side stream ---------------------------------
    cudaEventRecord(g_ev0, 0);
    cudaStreamWaitEvent(g_s1, g_ev0, 0);
    bias_kernel<<<1024, 256, 0, g_s1>>>(p, w_b, b_b, a_);
    cudaEventRecord(g_ev1, g_s1);

    // ---- main: projections (split-K 2), fused reduce+rotate+pack ----------
    pack_w_kernel<<<(CS * LDP / 4 + LDP / 4 + 255) / 256, 256>>>(
        w_q, b_q, w_kv, b_kv, w_qp, b_qp, w_kvp, b_kvp, wcat, bcat);
    gemm64_kernel<<<dim3(LDP / 64, 8, 2), 128>>>(
        s, CS, 0, 192,
        wcat, LDP, 0, (long long)192 * LDP,
        nullptr,
        ppart, LDP, 0, (long long)NN * LDP,
        192, 2, nullptr, 0, 0, 0);
    {
        const int TOT = NN*48 + HDS*NN*4*3 + HDS*NN*8 + NN*48;
        rotpack_kernel<<<(TOT + 255) / 256, 256>>>(ppart, bcat, rot, trans,
                                                   proj, kpk, kppk, vpk);
    }

    // join bias, then fused logits+softmax
    cudaStreamWaitEvent(0, g_ev1, 0);
    logits_softmax_kernel<<<dim3(64, HDS), 256>>>(proj, kpk, kppk, mask,
                                                  head_w, a_);

    // ---- fork: opair + w_o-high-K on side stream ---------------------------
    cudaEventRecord(g_ev2, 0);
    cudaStreamWaitEvent(g_s1, g_ev2, 0);
    opair_tc_kernel<<<NN, 128, OPAIR_SMEM, g_s1>>>(a_, p, cat_);
    // w_o cols 576..2111 (opair region), split-K 2 -> part slots 1,2
    gemm64_kernel<<<dim3(6, 8, 2), 128, 0, g_s1>>>(
        cat_ + 576, 2112, 0, 768,
        w_o + 576 * CS, CS, 0, (long long)768 * CS,
        nullptr,
        part + SPC, CS, 0, SPC,
        768, 2, nullptr, 0, 0, 0);
    cudaEventRecord(g_ev3, g_s1);

    // main: fused ov GEMM + postproc, then w_o low-K
    ovgemm_kernel<<<dim3(1, 8, HDS), 128>>>(a_, vpk, rot, trans, cat_);
    gemm64_kernel<<<dim3(6, 8, 1), 128>>>(
        cat_, 2112, 0, 0,
        w_o, CS, 0, 0,
        nullptr,
        part, CS, 0, 0,
        576, 1, nullptr, 0, 0, 0);
    cudaStreamWaitEvent(0, g_ev3, 0);

    // ---- reduce + residual + LN1 -------------------------------------------
    reduce_ln_kernel<<<NN, 128>>>(part, b_o, s, ln1_g, ln1_b, x2);

    // ---- transition MLP: reduces fused into next GEMM's A-staging ----------
    gemm64_kernel<<<dim3(6, 8, 3), 128>>>(
        x2, CS, 0, 128,
        tw1, CS, 0, (long long)128 * CS,
        nullptr,
        partB, CS, 0, SPC,
        128, 3, nullptr, 0, 0, 0);
    gemm64_kernel<<<dim3(6, 8, 3), 128>>>(
        partB, CS, 0, 128,
        tw2, CS, 0, (long long)128 * CS,
        nullptr,
        part, CS, 0, SPC,
        128, 3, tb1, SPC, 128, 1);
    gemm64_kernel<<<dim3(6, 8, 3), 128>>>(
        part, CS, 0, 128,
        tw3, CS, 0, (long long)128 * CS,
        nullptr,
        partB, CS, 0, SPC,
        128, 3, tb2, SPC, 128, 1);

    // ---- reduce + residual + LN2 + backbone update --------------------------
    lnbb_kernel<<<NN, 128>>>(partB, tb3, x2, ln2_g, ln2_b,
                             bb_w, bb_b, rot, trans, out);
}